// round 8
// baseline (speedup 1.0000x reference)
#include <cuda_runtime.h>
#include <cuda_fp16.h>
#include <cstdint>

#define BB  2
#define LL  1024
#define DD  768
#define HH  12
#define DHD 64
#define BHN (BB*HH)

// ---- scratch ----
__device__ __half g_q [BHN*LL*DHD];            // [bh][l][dh] fp16
__device__ __half g_k [BHN*LL*DHD];            // [bh][l][dh] fp16
__device__ __half g_vT[BHN*DHD*LL];            // [bh][dh][l] fp16 (transposed)
__device__ __half g_qw[5*BHN*LL*DHD];          // [i][bh][l][dh] fp16
__device__ __half g_st[(size_t)5*BB*LL*LL];    // struct fp16
__device__ float  g_s [(size_t)BHN*LL*LL];     // scores fp32
__device__ float  g_pm[BHN*8*LL];              // partial row max  [bh][kt][l]
__device__ float  g_ps[BHN*8*LL];              // partial row sumexp

// ============================================================
// fp16 mma helpers (m16n8k16, f32 accum)
// ============================================================
__device__ __forceinline__ void mma16(float* c, const uint4 a, const uint2 b) {
    asm volatile(
        "mma.sync.aligned.m16n8k16.row.col.f32.f16.f16.f32 "
        "{%0,%1,%2,%3}, {%4,%5,%6,%7}, {%8,%9}, {%0,%1,%2,%3};"
        : "+f"(c[0]), "+f"(c[1]), "+f"(c[2]), "+f"(c[3])
        : "r"(a.x), "r"(a.y), "r"(a.z), "r"(a.w), "r"(b.x), "r"(b.y));
}

// ---- f32 register-tile loaders (row-major, row stride ld) ----
template<int ITERS, int TPB>
__device__ __forceinline__ void ldgT4(float4* v, const float* __restrict__ src,
                                      int ld, int tid, int nvalid) {
    #pragma unroll
    for (int it = 0; it < ITERS; it++) {
        int idx = tid + it*TPB;
        int m = idx >> 4, k4 = idx & 15;
        v[it] = (m < nvalid) ? *(const float4*)(src + (size_t)m*ld + k4*4)
                             : make_float4(0.f, 0.f, 0.f, 0.f);
    }
}

// ---- fp16 register-tile loader: each item = 8 halfs (m, k0..k0+7) ----
template<int ITERS, int TPB>
__device__ __forceinline__ void ldgH(uint4* v, const __half* __restrict__ src,
                                     int ld, int tid) {
    #pragma unroll
    for (int it = 0; it < ITERS; it++) {
        int idx = tid + it*TPB;
        int m = idx >> 3, k8 = idx & 7;
        v[it] = *(const uint4*)(src + (size_t)m*ld + k8*8);
    }
}

// ---- STS to A-fragment fp16 layout from f32 regs (16KB dst) ----
template<int ITERS, int TPB>
__device__ __forceinline__ void stsAh(__half2* dst, const float4* v, int tid) {
    #pragma unroll
    for (int it = 0; it < ITERS; it++) {
        int idx = tid + it*TPB;
        int m = idx >> 4, k4 = idx & 15;
        int mt = m >> 4, r = m & 15;
        int rbit = r >> 3, rlow = r & 7;
        {
            int k = k4*4;
            int ku = k & 15, ks = k >> 4, khigh = ku >> 3, kpair = (ku >> 1) & 3;
            dst[((ks*8 + mt)*32 + rlow*4 + kpair)*4 + rbit + 2*khigh] =
                __floats2half2_rn(v[it].x, v[it].y);
        }
        {
            int k = k4*4 + 2;
            int ku = k & 15, ks = k >> 4, khigh = ku >> 3, kpair = (ku >> 1) & 3;
            dst[((ks*8 + mt)*32 + rlow*4 + kpair)*4 + rbit + 2*khigh] =
                __floats2half2_rn(v[it].z, v[it].w);
        }
    }
}

// ---- STS to A-fragment from fp16 regs (no cvt) ----
template<int ITERS, int TPB>
__device__ __forceinline__ void stsAhH(__half2* dst, const uint4* v, int tid) {
    #pragma unroll
    for (int it = 0; it < ITERS; it++) {
        int idx = tid + it*TPB;
        int m = idx >> 3, k0 = (idx & 7)*8;
        int mt = m >> 4, r = m & 15;
        int rbit = r >> 3, rlow = r & 7;
        int ks = k0 >> 4, khigh = (k0 >> 3) & 1;
        int base = ((ks*8 + mt)*32 + rlow*4)*4 + rbit + 2*khigh;
        const __half2* p = (const __half2*)&v[it];
        dst[base + 0]  = p[0];
        dst[base + 4]  = p[1];
        dst[base + 8]  = p[2];
        dst[base + 12] = p[3];
    }
}

// ---- STS to B-fragment (NT = N/8) from fp16 regs, n-major source ----
template<int ITERS, int TPB, int NT>
__device__ __forceinline__ void stsBhH(__half2* dst, const uint4* v, int tid) {
    #pragma unroll
    for (int it = 0; it < ITERS; it++) {
        int idx = tid + it*TPB;
        int n = idx >> 3, k0 = (idx & 7)*8;
        int nt = n >> 3, nlow = n & 7;
        int ks = k0 >> 4, reg = (k0 >> 3) & 1;
        int base = ((ks*NT + nt)*32 + nlow*4)*2 + reg;
        const __half2* p = (const __half2*)&v[it];
        dst[base + 0] = p[0];
        dst[base + 2] = p[1];
        dst[base + 4] = p[2];
        dst[base + 6] = p[3];
    }
}

// ---- STS to B-fragment (NT=16) from f32 n-major regs (for dist E bands) ----
template<int ITERS, int TPB>
__device__ __forceinline__ void stsBh(__half2* dst, const float4* v, int tid) {
    #pragma unroll
    for (int it = 0; it < ITERS; it++) {
        int idx = tid + it*TPB;
        int n = idx >> 4, k4 = idx & 15;
        int nt = n >> 3, nlow = n & 7;
        {
            int k = k4*4;
            int ku = k & 15, ks = k >> 4;
            dst[((ks*16 + nt)*32 + nlow*4 + ((ku & 7) >> 1))*2 + (ku >> 3)] =
                __floats2half2_rn(v[it].x, v[it].y);
        }
        {
            int k = k4*4 + 2;
            int ku = k & 15, ks = k >> 4;
            dst[((ks*16 + nt)*32 + nlow*4 + ((ku & 7) >> 1))*2 + (ku >> 3)] =
                __floats2half2_rn(v[it].z, v[it].w);
        }
    }
}

// ---- fused stage: f32 row-major 128x64 -> A-frag (256 threads) ----
__device__ __forceinline__ void stageAh(__half2* dst, const float* __restrict__ src,
                                        int ld, int tid) {
    float4 v[8];
    ldgT4<8,256>(v, src, ld, tid, 128);
    stsAh<8,256>(dst, v, tid);
}

// A-frag staging with fused exp(x - rowmax): for pv probs (f32 source)
__device__ __forceinline__ void stageAhExp(__half2* dst, const float* __restrict__ src,
                                           int ld, int tid, const float* __restrict__ rm) {
    float4 v[8];
    ldgT4<8,256>(v, src, ld, tid, 128);
    #pragma unroll
    for (int it = 0; it < 8; it++) {
        int m = (tid + it*256) >> 4;
        float mm = rm[m];
        v[it].x = __expf(v[it].x - mm);
        v[it].y = __expf(v[it].y - mm);
        v[it].z = __expf(v[it].z - mm);
        v[it].w = __expf(v[it].w - mm);
    }
    stsAh<8,256>(dst, v, tid);
}

// ---- fused stage: f32 k-major 64xN (stride ldn) -> B-frag (256 thr) ----
template<int N>
__device__ __forceinline__ void stageBTh(__half2* dst, const float* __restrict__ src,
                                         int ldn, int tid) {
    constexpr int NT = N / 8;
    constexpr int F4 = N / 4;
    constexpr int ITEMS = 32 * F4;
    #pragma unroll
    for (int it = 0; it < ITEMS/256; it++) {
        int idx = tid + it*256;
        int k2 = idx / F4, nq = idx % F4;
        int k = k2*2;
        float4 u = *(const float4*)(src + (size_t)k*ldn + nq*4);
        float4 w = *(const float4*)(src + (size_t)(k+1)*ldn + nq*4);
        int ku = k & 15, ks = k >> 4, reg = ku >> 3;
        int kl = (ku & 7) >> 1;
        float uu[4] = {u.x,u.y,u.z,u.w};
        float ww[4] = {w.x,w.y,w.z,w.w};
        #pragma unroll
        for (int c2 = 0; c2 < 4; c2++) {
            int n = nq*4 + c2;
            int nt = n >> 3;
            dst[((ks*NT + nt)*32 + (n & 7)*4 + kl)*2 + reg] =
                __floats2half2_rn(uu[c2], ww[c2]);
        }
    }
}

// ---- 128x128x64 pass, 8 warps (warp tile 32x64) ----
__device__ __forceinline__ void gemm64h(const __half2* __restrict__ Af,
                                        const __half2* __restrict__ Bf,
                                        int wm, int wn, int lane, float bacc[2][8][4]) {
    const uint4* A4 = (const uint4*)Af;
    const uint2* B2 = (const uint2*)Bf;
    #pragma unroll
    for (int ks = 0; ks < 4; ks++) {
        uint4 a0 = A4[(ks*8 + wm*2 + 0)*32 + lane];
        uint4 a1 = A4[(ks*8 + wm*2 + 1)*32 + lane];
        #pragma unroll
        for (int j = 0; j < 8; j++) {
            uint2 b = B2[(ks*16 + wn*8 + j)*32 + lane];
            mma16(bacc[0][j], a0, b);
            mma16(bacc[1][j], a1, b);
        }
    }
}

// ---- 128x64x64 pass, 8 warps ----
__device__ __forceinline__ void gemm64n64h(const __half2* __restrict__ Af,
                                           const __half2* __restrict__ Bf,
                                           int wid, int lane, float acc[8][4]) {
    const uint4* A4 = (const uint4*)Af;
    const uint2* B2 = (const uint2*)Bf;
    #pragma unroll
    for (int ks = 0; ks < 4; ks++) {
        uint4 a = A4[(ks*8 + wid)*32 + lane];
        #pragma unroll
        for (int j = 0; j < 8; j++) {
            uint2 b = B2[(ks*8 + j)*32 + lane];
            mma16(acc[j], a, b);
        }
    }
}

// ---- 128x128x64 pass, 16 warps (warp tile 32x32) ----
__device__ __forceinline__ void gemm32h(const __half2* __restrict__ Af,
                                        const __half2* __restrict__ Bf,
                                        int wm, int wn, int lane, float bacc[2][4][4]) {
    const uint4* A4 = (const uint4*)Af;
    const uint2* B2 = (const uint2*)Bf;
    #pragma unroll
    for (int ks = 0; ks < 4; ks++) {
        uint4 a0 = A4[(ks*8 + wm*2 + 0)*32 + lane];
        uint4 a1 = A4[(ks*8 + wm*2 + 1)*32 + lane];
        #pragma unroll
        for (int j = 0; j < 4; j++) {
            uint2 b = B2[(ks*16 + wn*4 + j)*32 + lane];
            mma16(bacc[0][j], a0, b);
            mma16(bacc[1][j], a1, b);
        }
    }
}

__device__ __forceinline__ void zero32(float a[2][4][4]) {
    #pragma unroll
    for (int i = 0; i < 2; i++)
        #pragma unroll
        for (int j = 0; j < 4; j++)
            #pragma unroll
            for (int c = 0; c < 4; c++) a[i][j][c] = 0.f;
}

// ============================================================
// K0: struct_matrix f32 -> fp16
// ============================================================
__global__ __launch_bounds__(256) void cvt_struct_kernel(const float* __restrict__ s)
{
    __half2* out = (__half2*)g_st;
    const size_t total4 = (size_t)5*BB*LL*LL/4;
    size_t i = (size_t)blockIdx.x*blockDim.x + threadIdx.x;
    const size_t stride = (size_t)gridDim.x*blockDim.x;
    for (; i < total4; i += stride) {
        float4 v = *(const float4*)(s + i*4);
        out[i*2+0] = __floats2half2_rn(v.x, v.y);
        out[i*2+1] = __floats2half2_rn(v.z, v.w);
    }
}

// ============================================================
// K1: QKV projection (fp16 mma, 256 thr); fp16 outputs, V transposed
// ============================================================
__global__ __launch_bounds__(256) void qkv_kernel(
    const float* __restrict__ hidden,
    const float* __restrict__ Wq, const float* __restrict__ bq,
    const float* __restrict__ Wk, const float* __restrict__ bk,
    const float* __restrict__ Wv, const float* __restrict__ bv)
{
    extern __shared__ __align__(16) char smraw[];
    __half2* Af = (__half2*)smraw;
    __half2* Bf = (__half2*)(smraw + 16384);

    const int mat = blockIdx.z;
    const float* W    = (mat==0) ? Wq : (mat==1 ? Wk : Wv);
    const float* bias = (mat==0) ? bq : (mat==1 ? bk : bv);

    const int n0 = blockIdx.x * 128;
    const int m0 = blockIdx.y * 128;
    const int tid = threadIdx.x, lane = tid & 31, wid = tid >> 5;
    const int wm = wid & 3, wn = wid >> 2;

    float acc[2][8][4];
    #pragma unroll
    for (int i = 0; i < 2; i++)
        #pragma unroll
        for (int j = 0; j < 8; j++)
            #pragma unroll
            for (int c = 0; c < 4; c++) acc[i][j][c] = 0.f;

    for (int kc0 = 0; kc0 < DD; kc0 += 64) {
        stageAh(Af, hidden + (size_t)m0*DD + kc0, DD, tid);
        stageBTh<128>(Bf, W + (size_t)kc0*DD + n0, DD, tid);
        __syncthreads();
        gemm64h(Af, Bf, wm, wn, lane, acc);
        __syncthreads();
    }

    const int r0 = wm*32 + (lane >> 2);
    const int c0 = wn*64 + (lane & 3)*2;
    #pragma unroll
    for (int i = 0; i < 2; i++)
        #pragma unroll
        for (int j = 0; j < 8; j++) {
            int cg = n0 + c0 + j*8;
            int h = cg >> 6, dh = cg & 63;
            float2 bb = *(const float2*)(bias + cg);
            #pragma unroll
            for (int half = 0; half < 2; half++) {
                int rg = m0 + r0 + i*16 + half*8;
                int b = rg >> 10, l = rg & 1023;
                float vx = acc[i][j][half*2+0] + bb.x;
                float vy = acc[i][j][half*2+1] + bb.y;
                if (mat == 2) {
                    g_vT[((size_t)((b*HH + h)*DHD + dh))*LL + l]     = __float2half_rn(vx);
                    g_vT[((size_t)((b*HH + h)*DHD + dh + 1))*LL + l] = __float2half_rn(vy);
                } else {
                    __half* outp = (mat==0) ? g_q : g_k;
                    *(__half2*)&outp[((size_t)((b*HH + h)*LL + l))*DHD + dh] =
                        __floats2half2_rn(vx, vy);
                }
            }
        }
}

// ============================================================
// K1b: qw precompute (fp16 mma, 256 thr); half in, half out
// ============================================================
__global__ __launch_bounds__(256) void qw_kernel(const float* __restrict__ ssw)
{
    extern __shared__ __align__(16) char smraw[];
    __half2* Af = (__half2*)smraw;
    __half2* Bf = (__half2*)(smraw + 16384);

    const int i5 = blockIdx.z;
    const int bh = blockIdx.y;
    const int h  = bh % HH;
    const int m0 = blockIdx.x * 128;
    const int tid = threadIdx.x, lane = tid & 31, wid = tid >> 5;

    uint4 vH[4];
    ldgH<4,256>(vH, g_q + (size_t)(bh*LL + m0)*DHD, DHD, tid);
    stsAhH<4,256>(Af, vH, tid);
    stageBTh<64>(Bf, ssw + (size_t)(i5*HH + h)*DHD*DHD, DHD, tid);
    __syncthreads();

    float acc[8][4];
    #pragma unroll
    for (int j = 0; j < 8; j++)
        #pragma unroll
        for (int c = 0; c < 4; c++) acc[j][c] = 0.f;

    gemm64n64h(Af, Bf, wid, lane, acc);

    __half* ob = g_qw + ((size_t)(i5*BHN + bh)*LL + m0)*DHD;
    const int r0 = wid*16 + (lane >> 2);
    const int c0 = (lane & 3)*2;
    #pragma unroll
    for (int j = 0; j < 8; j++) {
        int cc = c0 + j*8;
        *(__half2*)(ob + (size_t)r0*DHD + cc)     = __floats2half2_rn(acc[j][0], acc[j][1]);
        *(__half2*)(ob + (size_t)(r0+8)*DHD + cc) = __floats2half2_rn(acc[j][2], acc[j][3]);
    }
}

// ============================================================
// K2: fused scores + partial row stats
// smem: Q|Kb|Ka|E0|E1 (16K ea) + 2x QEb fp16 (128x132) = 149504
// ============================================================
#define SC_SMEM 149504

__global__ __launch_bounds__(512, 1) void scores_kernel(
    const float* __restrict__ mask,
    const float* __restrict__ dist,
    const float* __restrict__ abv)
{
    extern __shared__ __align__(16) char smraw[];
    __half2* Q   = (__half2*)smraw;
    __half2* Kb  = (__half2*)(smraw + 16384);
    __half2* Ka  = (__half2*)(smraw + 32768);
    __half2* E0  = (__half2*)(smraw + 49152);
    __half2* E1  = (__half2*)(smraw + 65536);
    __half*  QB0 = (__half*)(smraw + 81920);    // 128*132 fp16 (aliased by red)
    __half*  QB1 = (__half*)(smraw + 115712);
    float*   red = (float*)(smraw + 81920);     // stats scratch (aliases QB0)

    const int bh = blockIdx.x, kt = blockIdx.y, qt = blockIdx.z;
    const int b = bh / HH, h = bh % HH;
    const int m0 = qt*128, n0 = kt*128;
    const int tid = threadIdx.x, lane = tid & 31, wid = tid >> 5;
    const int wm = wid & 3, wn = wid >> 2;
    const int r0 = wm*32 + (lane >> 2);
    const int c0 = wn*32 + (lane & 3)*2;

    const int base = (qt - kt)*128 + 896;
    int nv1 = 1919 - base; if (nv1 > 128) nv1 = 128;

    const __half* qwbase = g_qw + ((size_t)bh*LL + m0)*DHD;
    const size_t qwstr = (size_t)BHN*LL*DHD;

    // prologue staging (fp16 direct for q/k; f32->fp16 for E bands)
    uint4 vq[2], vk[2], vH[2];
    float4 vA[4], vB[4];
    ldgH<2,512>(vq, g_q + (size_t)(bh*LL + m0)*DHD, DHD, tid);
    ldgH<2,512>(vk, g_k + (size_t)(bh*LL + n0)*DHD, DHD, tid);
    stsAhH<2,512>(Q, vq, tid);
    stsAhH<2,512>(Ka, vk, tid);
    stsBhH<2,512,16>(Kb, vk, tid);
    ldgT4<4,512>(vA, dist + (size_t)base*DHD, DHD, tid, 128);
    stsBh<4,512>(E0, vA, tid);
    ldgT4<4,512>(vB, dist + (size_t)(base + 128)*DHD, DHD, tid, nv1);
    stsBh<4,512>(E1, vB, tid);
    ldgH<2,512>(vH, qwbase, DHD, tid);          // qw0 prefetch
    __syncthreads();

    float acc[2][4][4];
    float bacc[2][4][4];
    zero32(acc);

    auto writeQEh = [&](__half* buf) {
        #pragma unroll
        for (int i = 0; i < 2; i++)
            #pragma unroll
            for (int j = 0; j < 4; j++) {
                int rr = r0 + i*16, cc = c0 + j*8;
                *(__half2*)(buf + rr*132 + cc)     = __floats2half2_rn(bacc[i][j][0], bacc[i][j][1]);
                *(__half2*)(buf + (rr+8)*132 + cc) = __floats2half2_rn(bacc[i][j][2], bacc[i][j][3]);
            }
    };
    auto gatherH = [&](const __half* buf, int off, bool useCol) {
        #pragma unroll
        for (int i = 0; i < 2; i++)
            #pragma unroll
            for (int j = 0; j < 4; j++) {
                int rr = r0 + i*16, cc = c0 + j*8;
                #pragma unroll
                for (int c2 = 0; c2 < 4; c2++) {
                    int R = rr + (c2 >> 1)*8;
                    int C = cc + (c2 & 1);
                    int J = R - C + off;
                    if ((unsigned)J < 128u) {
                        int rowi = useCol ? C : R;
                        acc[i][j][c2] += __half2float(buf[rowi*132 + J]);
                    }
                }
            }
    };

    // S1: KE0 -> QB0
    zero32(bacc); gemm32h(Ka, E0, wm, wn, lane, bacc);
    writeQEh(QB0);
    __syncthreads();

    // S2: KE1 -> QB1; gather KE0
    zero32(bacc); gemm32h(Ka, E1, wm, wn, lane, bacc);
    gatherH(QB0, 127, true);
    writeQEh(QB1);
    __syncthreads();

    // S3: QE0 -> QB0; gather KE1; stage qw0->Ka; ldg qw1
    zero32(bacc); gemm32h(Q, E0, wm, wn, lane, bacc);
    gatherH(QB1, -1, true);
    writeQEh(QB0);
    stsAhH<2,512>(Ka, vH, tid);
    ldgH<2,512>(vH, qwbase + qwstr, DHD, tid);
    __syncthreads();

    // S4: QE1 -> QB1; gather QE0; stage qw1->E0; ldg qw2
    zero32(bacc); gemm32h(Q, E1, wm, wn, lane, bacc);
    gatherH(QB0, 127, false);
    writeQEh(QB1);
    stsAhH<2,512>(E0, vH, tid);
    ldgH<2,512>(vH, qwbase + 2*qwstr, DHD, tid);
    __syncthreads();

    // S5: QK; gather QE1; scale+mask; stage qw2->E1; ldg qw3
    float2 mk[4];
    {
        const float* mrow = mask + b*LL + n0;
        #pragma unroll
        for (int j = 0; j < 4; j++) mk[j] = *(const float2*)(mrow + c0 + j*8);
    }
    zero32(bacc); gemm32h(Q, Kb, wm, wn, lane, bacc);
    gatherH(QB1, -1, false);
    #pragma unroll
    for (int j = 0; j < 4; j++)
        #pragma unroll
        for (int i = 0; i < 2; i++) {
            acc[i][j][0] = (acc[i][j][0] + bacc[i][j][0])*0.125f + mk[j].x;
            acc[i][j][1] = (acc[i][j][1] + bacc[i][j][1])*0.125f + mk[j].y;
            acc[i][j][2] = (acc[i][j][2] + bacc[i][j][2])*0.125f + mk[j].x;
            acc[i][j][3] = (acc[i][j][3] + bacc[i][j][3])*0.125f + mk[j].y;
        }
    stsAhH<2,512>(E1, vH, tid);
    ldgH<2,512>(vH, qwbase + 3*qwstr, DHD, tid);
    __syncthreads();

    // bilinear passes: qw0=Ka, qw1=E0, qw2=E1, qw3=Q, qw4=Ka(again)
    __half2 sv[8];
    float   ab;
    auto structPre = [&](int i5) {
        ab = __ldg(&abv[i5*HH + h]);
        const __half* stb = g_st + (((size_t)(i5*BB + b)*LL + m0)*LL) + n0;
        #pragma unroll
        for (int j = 0; j < 4; j++) {
            sv[j*2+0] = *(const __half2*)(stb + (size_t)r0*LL + c0 + j*8);
            sv[j*2+1] = *(const __half2*)(stb + (size_t)(r0+8)*LL + c0 + j*8);
        }
    };
    auto structEpi = [&](int i5) {
        #pragma unroll
        for (int j = 0; j < 4; j++) {
            float2 s0 = __half22float2(sv[j*2+0]);
            float2 s1 = __half22float2(sv[j*2+1]);
            acc[0][j][0] += (bacc[0][j][0] + ab)*s0.x;
            acc[0][j][1] += (bacc[0][j][1] + ab)*s0.y;
            acc[0][j][2] += (bacc[0][j][2] + ab)*s1.x;
            acc[0][j][3] += (bacc[0][j][3] + ab)*s1.y;
        }
        const __half* stb = g_st + (((size_t)(i5*BB + b)*LL + m0)*LL) + n0;
        #pragma unroll
        for (int j = 0; j < 4; j++) {
            float2 s0 = __half22float2(*(const __half2*)(stb + (size_t)(r0+16)*LL + c0 + j*8));
            float2 s1 = __half22float2(*(const __half2*)(stb + (size_t)(r0+24)*LL + c0 + j*8));
            acc[1][j][0] += (bacc[1][j][0] + ab)*s0.x;
            acc[1][j][1] += (bacc[1][j][1] + ab)*s0.y;
            acc[1][j][2] += (bacc[1][j][2] + ab)*s1.x;
            acc[1][j][3] += (bacc[1][j][3] + ab)*s1.y;
        }
    };

    // B1: bilinear0 (Ka=qw0); stage qw3->Q; ldg qw4
    structPre(0);
    zero32(bacc); gemm32h(Ka, Kb, wm, wn, lane, bacc);
    structEpi(0);
    stsAhH<2,512>(Q, vH, tid);
    ldgH<2,512>(vH, qwbase + 4*qwstr, DHD, tid);
    __syncthreads();

    // B2: bilinear1 (E0=qw1); stage qw4->Ka
    structPre(1);
    zero32(bacc); gemm32h(E0, Kb, wm, wn, lane, bacc);
    structEpi(1);
    stsAhH<2,512>(Ka, vH, tid);
    __syncthreads();

    // B3: bilinear2 (E1=qw2)
    structPre(2);
    zero32(bacc); gemm32h(E1, Kb, wm, wn, lane, bacc);
    structEpi(2);

    // B4: bilinear3 (Q=qw3)
    structPre(3);
    zero32(bacc); gemm32h(Q, Kb, wm, wn, lane, bacc);
    structEpi(3);

    // B5: bilinear4 (Ka=qw4)
    structPre(4);
    zero32(bacc); gemm32h(Ka, Kb, wm, wn, lane, bacc);
    structEpi(4);

    // store scores
    float* sp = g_s + ((size_t)bh*LL + m0)*LL + n0;
    #pragma unroll
    for (int i = 0; i < 2; i++)
        #pragma unroll
        for (int j = 0; j < 4; j++) {
            int rr = r0 + i*16, cc = c0 + j*8;
            *(float2*)(sp + (size_t)rr*LL + cc)     = make_float2(acc[i][j][0], acc[i][j][1]);
            *(float2*)(sp + (size_t)(rr+8)*LL + cc) = make_float2(acc[i][j][2], acc[i][j][3]);
        }

    // ---- partial row stats (max + sumexp over this 128-col tile) ----
    // thread rows: r0 + {0,8,16,24} (ridx: off = (ridx>>1)*16 + (ridx&1)*8)
    __syncthreads();   // QB0 region free; reuse as red
    float rm[4];
    #pragma unroll
    for (int ridx = 0; ridx < 4; ridx++) {
        int i = ridx >> 1, hh = ridx & 1;
        float m = acc[i][0][hh*2+0];
        #pragma unroll
        for (int j = 0; j < 4; j++) {
            m = fmaxf(m, acc[i][j][hh*2+0]);
            m = fmaxf(m, acc[i][j][hh*2+1]);
        }
        rm[ridx] = m;
    }
    #pragma unroll
    for (int o = 1; o <= 2; o <<= 1)
        #pragma unroll
        for (int r = 0; r < 4; r++)
            rm[r] = fmaxf(rm[r], __shfl_xor_sync(0xffffffffu, rm[r], o));
    if ((lane & 3) == 0) {
        #pragma unroll
        for (int r = 0; r < 4; r++) {
            int row = wm*32 + (lane >> 2) + (r >> 1)*16 + (r & 1)*8;
            red[row*4 + wn] = rm[r];
        }
    }
    __syncthreads();
    float rmf[4];
    #pragma unroll
    for (int r = 0; r < 4; r++) {
        int row = wm*32 + (lane >> 2) + (r >> 1)*16 + (r & 1)*8;
        rmf[r] = fmaxf(fmaxf(red[row*4+0], red[row*4+1]),
                       fmaxf(red[row*4+2], red[row*4+3]));
    }
    float* red2 = red + 512;
    float rs[4];
    #pragma unroll
    for (int ridx = 0; ridx < 4; ridx++) {
        int i = ridx >> 1, hh = ridx & 1;
        float s = 0.f;
        #pragma unroll
        for (int j = 0; j < 4; j++) {
            s += __expf(acc[i][j][hh*2+0] - rmf[ridx]);
            s += __expf(acc[i][j][hh*2+1] - rmf[ridx]);
        }
        rs[ridx] = s;
    }
    #pragma unroll
    for (int o = 1; o <= 2; o <<= 1)
        #pragma unroll
        for (int r = 0; r < 4; r++)
            rs[r] += __shfl_xor_sync(0xffffffffu, rs[r], o);
    if ((lane & 3) == 0) {
        #pragma unroll
        for (int r = 0; r < 4; r++) {
            int row = wm*32 + (lane >> 2) + (r >> 1)*16 + (r & 1)*8;
            red2[row*4 + wn] = rs[r];
        }
    }
    __syncthreads();
    if (wn == 0 && (lane & 3) == 0) {
        #pragma unroll
        for (int r = 0; r < 4; r++) {
            int row = wm*32 + (lane >> 2) + (r >> 1)*16 + (r & 1)*8;
            int gi = ((bh*8 + kt) << 10) + m0 + row;
            g_pm[gi] = rmf[r];
            g_ps[gi] = red2[row*4+0] + red2[row*4+1] + red2[row*4+2] + red2[row*4+3];
        }
    }
}

// ============================================================
// K4: ctx = softmax(scores) @ v, fused exp + stat combine
// smem: Af 16K + Bf 8K + stats 1K = 25600
// ============================================================
__global__ __launch_bounds__(256) void pv_kernel(float* __restrict__ out)
{
    extern __shared__ __align__(16) char smraw[];
    __half2* Af = (__half2*)smraw;
    __half2* Bf = (__half2*)(smraw + 16384);
    float* sm_m   = (float*)(smraw + 24576);
    float* sm_inv = (float*)(smraw + 25088);

    const int bh = blockIdx.y;
    const int b = bh / HH, h = bh % HH;
    const int m0 = blockIdx.x * 128;
    const int tid = threadIdx.x, lane = tid & 31, wid = tid >> 5;

    if (tid < 128) {
        float pm[8], ps[8];
        #pragma unroll
        for (int kt = 0; kt < 8; kt++) {
            int gi = ((bh*8 + kt) << 10) + m0 + tid;
            pm[kt] = g_pm[gi];
            ps[kt] = g_ps[gi];
        }
        float m = pm[0];
        #pragma unroll
        for (int kt = 1; kt < 8; kt++) m = fmaxf(m, pm[kt]);
        float s = 0.f;
        #pragma unroll
        for (int kt = 0; kt < 8; kt++) s += ps[kt]*__expf(pm[kt] - m);
        sm_m[tid]   = m;
        sm_inv[tid] = 1.f / s;
    }
    __syncthreads();

    const float* pb = g_s + (size_t)bh*LL*LL + (size_t)m0*LL;
    const __half* vb = g_vT + (size_t)bh*DHD*LL;

    float acc[8][4];
    #pragma unroll
    for (int j = 0; j < 8; j++)
        #pragma unroll
        for (int c = 0; c < 4; c++) acc[j][c] = 0.f;

    for (int kc0 = 0; kc0 < LL; kc0 += 64) {
        stageAhExp(Af, pb + kc0, LL, tid, sm_m);
        uint4 vH[2];
        ldgH<2,256>(vH, vb + kc0, LL, tid);     // [dh][l] n-major, 64x64
        stsBhH<2,256,8>(Bf, vH, tid);
        __syncthreads();
        gemm64n64h(Af, Bf, wid, lane, acc);
        __syncthreads();
    }

    const int r0 = wid*16 + (lane >> 2);
    const int c0 = (lane & 3)*2;
    const float inv0 = sm_inv[r0];
    const float inv1 = sm_inv[r0 + 8];
    #pragma unroll
    for (int j = 0; j < 8; j++) {
        int cc = c0 + j*8;
        int l0 = m0 + r0;
        *(float2*)&out[((size_t)b*LL + l0)*DD + h*DHD + cc] =
            make_float2(acc[j][0]*inv0, acc[j][1]*inv0);
        *(float2*)&out[((size_t)b*LL + l0 + 8)*DD + h*DHD + cc] =
            make_float2(acc[j][2]*inv1, acc[j][3]*inv1);
    }
}

// ============================================================
extern "C" void kernel_launch(void* const* d_in, const int* in_sizes, int n_in,
                              void* d_out, int out_size)
{
    const float* hidden  = (const float*)d_in[0];
    const float* mask    = (const float*)d_in[1];
    const float* structm = (const float*)d_in[2];
    const float* Wq      = (const float*)d_in[3];
    const float* bq      = (const float*)d_in[4];
    const float* Wk      = (const float*)d_in[5];
    const float* bk      = (const float*)d_in[6];
    const float* Wv      = (const float*)d_in[7];
    const float* bv      = (const float*)d_in[8];
    const float* dist    = (const float*)d_in[9];
    const float* ssw     = (const float*)d_in[10];
    const float* abv     = (const float*)d_in[11];
    float* out = (float*)d_out;

    cudaFuncSetAttribute(qkv_kernel,    cudaFuncAttributeMaxDynamicSharedMemorySize, 32768);
    cudaFuncSetAttribute(qw_kernel,     cudaFuncAttributeMaxDynamicSharedMemorySize, 24576);
    cudaFuncSetAttribute(pv_kernel,     cudaFuncAttributeMaxDynamicSharedMemorySize, 25600);
    cudaFuncSetAttribute(scores_kernel, cudaFuncAttributeMaxDynamicSharedMemorySize, SC_SMEM);

    cvt_struct_kernel<<<2560, 256>>>(structm);
    qkv_kernel    <<<dim3(6,16,3),  256, 32768>>>(hidden, Wq,bq, Wk,bk, Wv,bv);
    qw_kernel     <<<dim3(8,24,5),  256, 24576>>>(ssw);
    scores_kernel <<<dim3(24,8,8),  512, SC_SMEM>>>(mask, dist, abv);
    pv_kernel     <<<dim3(8,24),    256, 25600>>>(out);
}

// round 9
// speedup vs baseline: 1.0641x; 1.0641x over previous
#include <cuda_runtime.h>
#include <cuda_fp16.h>
#include <cstdint>

#define BB  2
#define LL  1024
#define DD  768
#define HH  12
#define DHD 64
#define BHN (BB*HH)

// ---- scratch ----
__device__ __half g_q [BHN*LL*DHD];            // [bh][l][dh] fp16
__device__ __half g_k [BHN*LL*DHD];            // [bh][l][dh] fp16
__device__ __half g_v [BHN*LL*DHD];            // [bh][l][dh] fp16
__device__ __half g_qw[5*BHN*LL*DHD];          // [i][bh][l][dh] fp16
__device__ float  g_s [(size_t)BHN*LL*LL];     // scores fp32
__device__ float  g_pm[BHN*8*4*LL];            // partial row max  [bh][kt][wn][l]
__device__ float  g_ps[BHN*8*4*LL];            // partial row sumexp

// ============================================================
// fp16 mma helpers (m16n8k16, f32 accum)
// ============================================================
__device__ __forceinline__ void mma16(float* c, const uint4 a, const uint2 b) {
    asm volatile(
        "mma.sync.aligned.m16n8k16.row.col.f32.f16.f16.f32 "
        "{%0,%1,%2,%3}, {%4,%5,%6,%7}, {%8,%9}, {%0,%1,%2,%3};"
        : "+f"(c[0]), "+f"(c[1]), "+f"(c[2]), "+f"(c[3])
        : "r"(a.x), "r"(a.y), "r"(a.z), "r"(a.w), "r"(b.x), "r"(b.y));
}

// ---- f32 register-tile loaders (row-major, row stride ld) ----
template<int ITERS, int TPB>
__device__ __forceinline__ void ldgT4(float4* v, const float* __restrict__ src,
                                      int ld, int tid, int nvalid) {
    #pragma unroll
    for (int it = 0; it < ITERS; it++) {
        int idx = tid + it*TPB;
        int m = idx >> 4, k4 = idx & 15;
        v[it] = (m < nvalid) ? *(const float4*)(src + (size_t)m*ld + k4*4)
                             : make_float4(0.f, 0.f, 0.f, 0.f);
    }
}

// ---- fp16 register-tile loader: each item = 8 halfs (m, k0..k0+7) ----
template<int ITERS, int TPB>
__device__ __forceinline__ void ldgH(uint4* v, const __half* __restrict__ src,
                                     int ld, int tid) {
    #pragma unroll
    for (int it = 0; it < ITERS; it++) {
        int idx = tid + it*TPB;
        int m = idx >> 3, k8 = idx & 7;
        v[it] = *(const uint4*)(src + (size_t)m*ld + k8*8);
    }
}

// ---- STS to A-fragment fp16 layout from f32 regs (16KB dst) ----
template<int ITERS, int TPB>
__device__ __forceinline__ void stsAh(__half2* dst, const float4* v, int tid) {
    #pragma unroll
    for (int it = 0; it < ITERS; it++) {
        int idx = tid + it*TPB;
        int m = idx >> 4, k4 = idx & 15;
        int mt = m >> 4, r = m & 15;
        int rbit = r >> 3, rlow = r & 7;
        {
            int k = k4*4;
            int ku = k & 15, ks = k >> 4, khigh = ku >> 3, kpair = (ku >> 1) & 3;
            dst[((ks*8 + mt)*32 + rlow*4 + kpair)*4 + rbit + 2*khigh] =
                __floats2half2_rn(v[it].x, v[it].y);
        }
        {
            int k = k4*4 + 2;
            int ku = k & 15, ks = k >> 4, khigh = ku >> 3, kpair = (ku >> 1) & 3;
            dst[((ks*8 + mt)*32 + rlow*4 + kpair)*4 + rbit + 2*khigh] =
                __floats2half2_rn(v[it].z, v[it].w);
        }
    }
}

// ---- STS to A-fragment from fp16 regs (no cvt) ----
template<int ITERS, int TPB>
__device__ __forceinline__ void stsAhH(__half2* dst, const uint4* v, int tid) {
    #pragma unroll
    for (int it = 0; it < ITERS; it++) {
        int idx = tid + it*TPB;
        int m = idx >> 3, k0 = (idx & 7)*8;
        int mt = m >> 4, r = m & 15;
        int rbit = r >> 3, rlow = r & 7;
        int ks = k0 >> 4, khigh = (k0 >> 3) & 1;
        int base = ((ks*8 + mt)*32 + rlow*4)*4 + rbit + 2*khigh;
        const __half2* p = (const __half2*)&v[it];
        dst[base + 0]  = p[0];
        dst[base + 4]  = p[1];
        dst[base + 8]  = p[2];
        dst[base + 12] = p[3];
    }
}

// ---- STS to B-fragment (NT = N/8) from fp16 regs, n-major source ----
template<int ITERS, int TPB, int NT>
__device__ __forceinline__ void stsBhH(__half2* dst, const uint4* v, int tid) {
    #pragma unroll
    for (int it = 0; it < ITERS; it++) {
        int idx = tid + it*TPB;
        int n = idx >> 3, k0 = (idx & 7)*8;
        int nt = n >> 3, nlow = n & 7;
        int ks = k0 >> 4, reg = (k0 >> 3) & 1;
        int base = ((ks*NT + nt)*32 + nlow*4)*2 + reg;
        const __half2* p = (const __half2*)&v[it];
        dst[base + 0] = p[0];
        dst[base + 2] = p[1];
        dst[base + 4] = p[2];
        dst[base + 6] = p[3];
    }
}

// ---- STS to B-fragment (NT=16) from f32 n-major regs (for dist E bands) ----
template<int ITERS, int TPB>
__device__ __forceinline__ void stsBh(__half2* dst, const float4* v, int tid) {
    #pragma unroll
    for (int it = 0; it < ITERS; it++) {
        int idx = tid + it*TPB;
        int n = idx >> 4, k4 = idx & 15;
        int nt = n >> 3, nlow = n & 7;
        {
            int k = k4*4;
            int ku = k & 15, ks = k >> 4;
            dst[((ks*16 + nt)*32 + nlow*4 + ((ku & 7) >> 1))*2 + (ku >> 3)] =
                __floats2half2_rn(v[it].x, v[it].y);
        }
        {
            int k = k4*4 + 2;
            int ku = k & 15, ks = k >> 4;
            dst[((ks*16 + nt)*32 + nlow*4 + ((ku & 7) >> 1))*2 + (ku >> 3)] =
                __floats2half2_rn(v[it].z, v[it].w);
        }
    }
}

// ---- fused stage: f32 row-major 128x64 -> A-frag (256 threads) ----
__device__ __forceinline__ void stageAh(__half2* dst, const float* __restrict__ src,
                                        int ld, int tid) {
    float4 v[8];
    ldgT4<8,256>(v, src, ld, tid, 128);
    stsAh<8,256>(dst, v, tid);
}

// A-frag staging with fused exp(x - rowmax): for pv probs (f32 source)
__device__ __forceinline__ void stageAhExp(__half2* dst, const float* __restrict__ src,
                                           int ld, int tid, const float* __restrict__ rm) {
    float4 v[8];
    ldgT4<8,256>(v, src, ld, tid, 128);
    #pragma unroll
    for (int it = 0; it < 8; it++) {
        int m = (tid + it*256) >> 4;
        float mm = rm[m];
        v[it].x = __expf(v[it].x - mm);
        v[it].y = __expf(v[it].y - mm);
        v[it].z = __expf(v[it].z - mm);
        v[it].w = __expf(v[it].w - mm);
    }
    stsAh<8,256>(dst, v, tid);
}

// ---- fused stage: f32 k-major 64xN (stride ldn) -> B-frag (256 thr) ----
template<int N>
__device__ __forceinline__ void stageBTh(__half2* dst, const float* __restrict__ src,
                                         int ldn, int tid) {
    constexpr int NT = N / 8;
    constexpr int F4 = N / 4;
    constexpr int ITEMS = 32 * F4;
    #pragma unroll
    for (int it = 0; it < ITEMS/256; it++) {
        int idx = tid + it*256;
        int k2 = idx / F4, nq = idx % F4;
        int k = k2*2;
        float4 u = *(const float4*)(src + (size_t)k*ldn + nq*4);
        float4 w = *(const float4*)(src + (size_t)(k+1)*ldn + nq*4);
        int ku = k & 15, ks = k >> 4, reg = ku >> 3;
        int kl = (ku & 7) >> 1;
        float uu[4] = {u.x,u.y,u.z,u.w};
        float ww[4] = {w.x,w.y,w.z,w.w};
        #pragma unroll
        for (int c2 = 0; c2 < 4; c2++) {
            int n = nq*4 + c2;
            int nt = n >> 3;
            dst[((ks*NT + nt)*32 + (n & 7)*4 + kl)*2 + reg] =
                __floats2half2_rn(uu[c2], ww[c2]);
        }
    }
}

// ---- fp16 k-major 64x64 -> B-frag (NT=8), PRMT row-pair interleave (256 thr) ----
__device__ __forceinline__ void stageBThH64(__half2* dst, const __half* __restrict__ src,
                                            int ldn, int tid) {
    int k2 = tid >> 3, n8 = tid & 7;
    int k = k2*2;
    uint4 u = *(const uint4*)(src + (size_t)k*ldn + n8*8);
    uint4 w = *(const uint4*)(src + (size_t)(k+1)*ldn + n8*8);
    int ks = k >> 4, kl = (k & 7) >> 1, reg = (k >> 3) & 1;
    const unsigned* ua = (const unsigned*)&u;
    const unsigned* wa = (const unsigned*)&w;
    unsigned* d = (unsigned*)dst;
    #pragma unroll
    for (int c = 0; c < 4; c++) {
        unsigned lo, hi;
        asm("prmt.b32 %0, %1, %2, 0x5410;" : "=r"(lo) : "r"(ua[c]), "r"(wa[c]));
        asm("prmt.b32 %0, %1, %2, 0x7632;" : "=r"(hi) : "r"(ua[c]), "r"(wa[c]));
        int nlo = c*2, nhi = c*2 + 1;
        d[((ks*8 + n8)*32 + nlo*4 + kl)*2 + reg] = lo;
        d[((ks*8 + n8)*32 + nhi*4 + kl)*2 + reg] = hi;
    }
}

// ---- 128x128x64 pass, 8 warps (warp tile 32x64) ----
__device__ __forceinline__ void gemm64h(const __half2* __restrict__ Af,
                                        const __half2* __restrict__ Bf,
                                        int wm, int wn, int lane, float bacc[2][8][4]) {
    const uint4* A4 = (const uint4*)Af;
    const uint2* B2 = (const uint2*)Bf;
    #pragma unroll
    for (int ks = 0; ks < 4; ks++) {
        uint4 a0 = A4[(ks*8 + wm*2 + 0)*32 + lane];
        uint4 a1 = A4[(ks*8 + wm*2 + 1)*32 + lane];
        #pragma unroll
        for (int j = 0; j < 8; j++) {
            uint2 b = B2[(ks*16 + wn*8 + j)*32 + lane];
            mma16(bacc[0][j], a0, b);
            mma16(bacc[1][j], a1, b);
        }
    }
}

// ---- 128x64x64 pass, 8 warps ----
__device__ __forceinline__ void gemm64n64h(const __half2* __restrict__ Af,
                                           const __half2* __restrict__ Bf,
                                           int wid, int lane, float acc[8][4]) {
    const uint4* A4 = (const uint4*)Af;
    const uint2* B2 = (const uint2*)Bf;
    #pragma unroll
    for (int ks = 0; ks < 4; ks++) {
        uint4 a = A4[(ks*8 + wid)*32 + lane];
        #pragma unroll
        for (int j = 0; j < 8; j++) {
            uint2 b = B2[(ks*8 + j)*32 + lane];
            mma16(acc[j], a, b);
        }
    }
}

// ---- 128x128x64 pass, 16 warps (warp tile 32x32) ----
__device__ __forceinline__ void gemm32h(const __half2* __restrict__ Af,
                                        const __half2* __restrict__ Bf,
                                        int wm, int wn, int lane, float bacc[2][4][4]) {
    const uint4* A4 = (const uint4*)Af;
    const uint2* B2 = (const uint2*)Bf;
    #pragma unroll
    for (int ks = 0; ks < 4; ks++) {
        uint4 a0 = A4[(ks*8 + wm*2 + 0)*32 + lane];
        uint4 a1 = A4[(ks*8 + wm*2 + 1)*32 + lane];
        #pragma unroll
        for (int j = 0; j < 4; j++) {
            uint2 b = B2[(ks*16 + wn*4 + j)*32 + lane];
            mma16(bacc[0][j], a0, b);
            mma16(bacc[1][j], a1, b);
        }
    }
}

__device__ __forceinline__ void zero32(float a[2][4][4]) {
    #pragma unroll
    for (int i = 0; i < 2; i++)
        #pragma unroll
        for (int j = 0; j < 4; j++)
            #pragma unroll
            for (int c = 0; c < 4; c++) a[i][j][c] = 0.f;
}

// ============================================================
// K1: QKV projection (fp16 mma, 256 thr); fp16 [l][dh] outputs
// ============================================================
__global__ __launch_bounds__(256) void qkv_kernel(
    const float* __restrict__ hidden,
    const float* __restrict__ Wq, const float* __restrict__ bq,
    const float* __restrict__ Wk, const float* __restrict__ bk,
    const float* __restrict__ Wv, const float* __restrict__ bv)
{
    extern __shared__ __align__(16) char smraw[];
    __half2* Af = (__half2*)smraw;
    __half2* Bf = (__half2*)(smraw + 16384);

    const int mat = blockIdx.z;
    const float* W    = (mat==0) ? Wq : (mat==1 ? Wk : Wv);
    const float* bias = (mat==0) ? bq : (mat==1 ? bk : bv);
    __half* outp      = (mat==0) ? g_q : (mat==1 ? g_k : g_v);

    const int n0 = blockIdx.x * 128;
    const int m0 = blockIdx.y * 128;
    const int tid = threadIdx.x, lane = tid & 31, wid = tid >> 5;
    const int wm = wid & 3, wn = wid >> 2;

    float acc[2][8][4];
    #pragma unroll
    for (int i = 0; i < 2; i++)
        #pragma unroll
        for (int j = 0; j < 8; j++)
            #pragma unroll
            for (int c = 0; c < 4; c++) acc[i][j][c] = 0.f;

    for (int kc0 = 0; kc0 < DD; kc0 += 64) {
        stageAh(Af, hidden + (size_t)m0*DD + kc0, DD, tid);
        stageBTh<128>(Bf, W + (size_t)kc0*DD + n0, DD, tid);
        __syncthreads();
        gemm64h(Af, Bf, wm, wn, lane, acc);
        __syncthreads();
    }

    const int r0 = wm*32 + (lane >> 2);
    const int c0 = wn*64 + (lane & 3)*2;
    #pragma unroll
    for (int i = 0; i < 2; i++)
        #pragma unroll
        for (int j = 0; j < 8; j++) {
            int cg = n0 + c0 + j*8;
            int h = cg >> 6, dh = cg & 63;
            float2 bb = *(const float2*)(bias + cg);
            #pragma unroll
            for (int half = 0; half < 2; half++) {
                int rg = m0 + r0 + i*16 + half*8;
                int b = rg >> 10, l = rg & 1023;
                *(__half2*)&outp[((size_t)((b*HH + h)*LL + l))*DHD + dh] =
                    __floats2half2_rn(acc[i][j][half*2+0] + bb.x,
                                      acc[i][j][half*2+1] + bb.y);
            }
        }
}

// ============================================================
// K1b: qw precompute (fp16 mma, 256 thr); half in, half out
// ============================================================
__global__ __launch_bounds__(256) void qw_kernel(const float* __restrict__ ssw)
{
    extern __shared__ __align__(16) char smraw[];
    __half2* Af = (__half2*)smraw;
    __half2* Bf = (__half2*)(smraw + 16384);

    const int i5 = blockIdx.z;
    const int bh = blockIdx.y;
    const int h  = bh % HH;
    const int m0 = blockIdx.x * 128;
    const int tid = threadIdx.x, lane = tid & 31, wid = tid >> 5;

    uint4 vH[4];
    ldgH<4,256>(vH, g_q + (size_t)(bh*LL + m0)*DHD, DHD, tid);
    stsAhH<4,256>(Af, vH, tid);
    stageBTh<64>(Bf, ssw + (size_t)(i5*HH + h)*DHD*DHD, DHD, tid);
    __syncthreads();

    float acc[8][4];
    #pragma unroll
    for (int j = 0; j < 8; j++)
        #pragma unroll
        for (int c = 0; c < 4; c++) acc[j][c] = 0.f;

    gemm64n64h(Af, Bf, wid, lane, acc);

    __half* ob = g_qw + ((size_t)(i5*BHN + bh)*LL + m0)*DHD;
    const int r0 = wid*16 + (lane >> 2);
    const int c0 = (lane & 3)*2;
    #pragma unroll
    for (int j = 0; j < 8; j++) {
        int cc = c0 + j*8;
        *(__half2*)(ob + (size_t)r0*DHD + cc)     = __floats2half2_rn(acc[j][0], acc[j][1]);
        *(__half2*)(ob + (size_t)(r0+8)*DHD + cc) = __floats2half2_rn(acc[j][2], acc[j][3]);
    }
}

// ============================================================
// K2: fused scores + register-only partial row stats
// smem: Q|Kb|Ka|E0|E1 (16K ea) + 2x QEb fp16 (128x132) = 149504
// ============================================================
#define SC_SMEM 149504

__global__ __launch_bounds__(512, 1) void scores_kernel(
    const float* __restrict__ mask,
    const float* __restrict__ structm,
    const float* __restrict__ dist,
    const float* __restrict__ abv)
{
    extern __shared__ __align__(16) char smraw[];
    __half2* Q   = (__half2*)smraw;
    __half2* Kb  = (__half2*)(smraw + 16384);
    __half2* Ka  = (__half2*)(smraw + 32768);
    __half2* E0  = (__half2*)(smraw + 49152);
    __half2* E1  = (__half2*)(smraw + 65536);
    __half*  QB0 = (__half*)(smraw + 81920);
    __half*  QB1 = (__half*)(smraw + 115712);

    const int bh = blockIdx.x, kt = blockIdx.y, qt = blockIdx.z;
    const int b = bh / HH, h = bh % HH;
    const int m0 = qt*128, n0 = kt*128;
    const int tid = threadIdx.x, lane = tid & 31, wid = tid >> 5;
    const int wm = wid & 3, wn = wid >> 2;
    const int r0 = wm*32 + (lane >> 2);
    const int c0 = wn*32 + (lane & 3)*2;

    const int base = (qt - kt)*128 + 896;
    int nv1 = 1919 - base; if (nv1 > 128) nv1 = 128;

    const __half* qwbase = g_qw + ((size_t)bh*LL + m0)*DHD;
    const size_t qwstr = (size_t)BHN*LL*DHD;

    // prologue staging (fp16 direct for q/k; f32->fp16 for E bands)
    uint4 vq[2], vk[2], vH[2];
    float4 vA[4], vB[4];
    ldgH<2,512>(vq, g_q + (size_t)(bh*LL + m0)*DHD, DHD, tid);
    ldgH<2,512>(vk, g_k + (size_t)(bh*LL + n0)*DHD, DHD, tid);
    stsAhH<2,512>(Q, vq, tid);
    stsAhH<2,512>(Ka, vk, tid);
    stsBhH<2,512,16>(Kb, vk, tid);
    ldgT4<4,512>(vA, dist + (size_t)base*DHD, DHD, tid, 128);
    stsBh<4,512>(E0, vA, tid);
    ldgT4<4,512>(vB, dist + (size_t)(base + 128)*DHD, DHD, tid, nv1);
    stsBh<4,512>(E1, vB, tid);
    ldgH<2,512>(vH, qwbase, DHD, tid);          // qw0 prefetch
    __syncthreads();

    float acc[2][4][4];
    float bacc[2][4][4];
    zero32(acc);

    auto writeQEh = [&](__half* buf) {
        #pragma unroll
        for (int i = 0; i < 2; i++)
            #pragma unroll
            for (int j = 0; j < 4; j++) {
                int rr = r0 + i*16, cc = c0 + j*8;
                *(__half2*)(buf + rr*132 + cc)     = __floats2half2_rn(bacc[i][j][0], bacc[i][j][1]);
                *(__half2*)(buf + (rr+8)*132 + cc) = __floats2half2_rn(bacc[i][j][2], bacc[i][j][3]);
            }
    };
    auto gatherH = [&](const __half* buf, int off, bool useCol) {
        #pragma unroll
        for (int i = 0; i < 2; i++)
            #pragma unroll
            for (int j = 0; j < 4; j++) {
                int rr = r0 + i*16, cc = c0 + j*8;
                #pragma unroll
                for (int c2 = 0; c2 < 4; c2++) {
                    int R = rr + (c2 >> 1)*8;
                    int C = cc + (c2 & 1);
                    int J = R - C + off;
                    if ((unsigned)J < 128u) {
                        int rowi = useCol ? C : R;
                        acc[i][j][c2] += __half2float(buf[rowi*132 + J]);
                    }
                }
            }
    };

    // S1: KE0 -> QB0
    zero32(bacc); gemm32h(Ka, E0, wm, wn, lane, bacc);
    writeQEh(QB0);
    __syncthreads();

    // S2: KE1 -> QB1; gather KE0
    zero32(bacc); gemm32h(Ka, E1, wm, wn, lane, bacc);
    gatherH(QB0, 127, true);
    writeQEh(QB1);
    __syncthreads();

    // S3: QE0 -> QB0; gather KE1; stage qw0->Ka; ldg qw1
    zero32(bacc); gemm32h(Q, E0, wm, wn, lane, bacc);
    gatherH(QB1, -1, true);
    writeQEh(QB0);
    stsAhH<2,512>(Ka, vH, tid);
    ldgH<2,512>(vH, qwbase + qwstr, DHD, tid);
    __syncthreads();

    // S4: QE1 -> QB1; gather QE0; stage qw1->E0; ldg qw2
    zero32(bacc); gemm32h(Q, E1, wm, wn, lane, bacc);
    gatherH(QB0, 127, false);
    writeQEh(QB1);
    stsAhH<2,512>(E0, vH, tid);
    ldgH<2,512>(vH, qwbase + 2*qwstr, DHD, tid);
    __syncthreads();

    // S5: QK; gather QE1; scale+mask; stage qw2->E1; ldg qw3
    float2 mk[4];
    {
        const float* mrow = mask + b*LL + n0;
        #pragma unroll
        for (int j = 0; j < 4; j++) mk[j] = *(const float2*)(mrow + c0 + j*8);
    }
    zero32(bacc); gemm32h(Q, Kb, wm, wn, lane, bacc);
    gatherH(QB1, -1, false);
    #pragma unroll
    for (int j = 0; j < 4; j++)
        #pragma unroll
        for (int i = 0; i < 2; i++) {
            acc[i][j][0] = (acc[i][j][0] + bacc[i][j][0])*0.125f + mk[j].x;
            acc[i][j][1] = (acc[i][j][1] + bacc[i][j][1])*0.125f + mk[j].y;
            acc[i][j][2] = (acc[i][j][2] + bacc[i][j][2])*0.125f + mk[j].x;
            acc[i][j][3] = (acc[i][j][3] + bacc[i][j][3])*0.125f + mk[j].y;
        }
    stsAhH<2,512>(E1, vH, tid);
    ldgH<2,512>(vH, qwbase + 3*qwstr, DHD, tid);
    __syncthreads();

    // bilinear passes: qw0=Ka, qw1=E0, qw2=E1, qw3=Q, qw4=Ka(again)
    float2 sv[8];
    float  ab;
    auto structPre = [&](int i5) {
        ab = __ldg(&abv[i5*HH + h]);
        const float* stb = structm + (((size_t)(i5*BB + b)*LL + m0)*LL) + n0;
        #pragma unroll
        for (int j = 0; j < 4; j++) {
            sv[j*2+0] = *(const float2*)(stb + (size_t)r0*LL + c0 + j*8);
            sv[j*2+1] = *(const float2*)(stb + (size_t)(r0+8)*LL + c0 + j*8);
        }
    };
    auto structEpi = [&](int i5) {
        #pragma unroll
        for (int j = 0; j < 4; j++) {
            acc[0][j][0] += (bacc[0][j][0] + ab)*sv[j*2+0].x;
            acc[0][j][1] += (bacc[0][j][1] + ab)*sv[j*2+0].y;
            acc[0][j][2] += (bacc[0][j][2] + ab)*sv[j*2+1].x;
            acc[0][j][3] += (bacc[0][j][3] + ab)*sv[j*2+1].y;
        }
        const float* stb = structm + (((size_t)(i5*BB + b)*LL + m0)*LL) + n0;
        #pragma unroll
        for (int j = 0; j < 4; j++) {
            float2 s0 = *(const float2*)(stb + (size_t)(r0+16)*LL + c0 + j*8);
            float2 s1 = *(const float2*)(stb + (size_t)(r0+24)*LL + c0 + j*8);
            acc[1][j][0] += (bacc[1][j][0] + ab)*s0.x;
            acc[1][j][1] += (bacc[1][j][1] + ab)*s0.y;
            acc[1][j][2] += (bacc[1][j][2] + ab)*s1.x;
            acc[1][j][3] += (bacc[1][j][3] + ab)*s1.y;
        }
    };

    // B1: bilinear0 (Ka=qw0); stage qw3->Q; ldg qw4
    structPre(0);
    zero32(bacc); gemm32h(Ka, Kb, wm, wn, lane, bacc);
    structEpi(0);
    stsAhH<2,512>(Q, vH, tid);
    ldgH<2,512>(vH, qwbase + 4*qwstr, DHD, tid);
    __syncthreads();

    // B2: bilinear1 (E0=qw1); stage qw4->Ka
    structPre(1);
    zero32(bacc); gemm32h(E0, Kb, wm, wn, lane, bacc);
    structEpi(1);
    stsAhH<2,512>(Ka, vH, tid);
    __syncthreads();

    // B3: bilinear2 (E1=qw2)
    structPre(2);
    zero32(bacc); gemm32h(E1, Kb, wm, wn, lane, bacc);
    structEpi(2);

    // B4: bilinear3 (Q=qw3)
    structPre(3);
    zero32(bacc); gemm32h(Q, Kb, wm, wn, lane, bacc);
    structEpi(3);

    // B5: bilinear4 (Ka=qw4)
    structPre(4);
    zero32(bacc); gemm32h(Ka, Kb, wm, wn, lane, bacc);
    structEpi(4);

    // store scores
    float* sp = g_s + ((size_t)bh*LL + m0)*LL + n0;
    #pragma unroll
    for (int i = 0; i < 2; i++)
        #pragma unroll
        for (int j = 0; j < 4; j++) {
            int rr = r0 + i*16, cc = c0 + j*8;
            *(float2*)(sp + (size_t)rr*LL + cc)     = make_float2(acc[i][j][0], acc[i][j][1]);
            *(float2*)(sp + (size_t)(rr+8)*LL + cc) = make_float2(acc[i][j][2], acc[i][j][3]);
        }

    // ---- per-wn partial row stats: registers + quad shuffles only ----
    float rm[4], rs[4];
    #pragma unroll
    for (int ridx = 0; ridx < 4; ridx++) {
        int i = ridx >> 1, hh = ridx & 1;
        float m = acc[i][0][hh*2+0];
        #pragma unroll
        for (int j = 0; j < 4; j++) {
            m = fmaxf(m, acc[i][j][hh*2+0]);
            m = fmaxf(m, acc[i][j][hh*2+1]);
        }
        rm[ridx] = m;
    }
    #pragma unroll
    for (int o = 1; o <= 2; o <<= 1)
        #pragma unroll
        for (int r = 0; r < 4; r++)
            rm[r] = fmaxf(rm[r], __shfl_xor_sync(0xffffffffu, rm[r], o));
    #pragma unroll
    for (int ridx = 0; ridx < 4; ridx++) {
        int i = ridx >> 1, hh = ridx & 1;
        float s = 0.f;
        #pragma unroll
        for (int j = 0; j < 4; j++) {
            s += __expf(acc[i][j][hh*2+0] - rm[ridx]);
            s += __expf(acc[i][j][hh*2+1] - rm[ridx]);
        }
        rs[ridx] = s;
    }
    #pragma unroll
    for (int o = 1; o <= 2; o <<= 1)
        #pragma unroll
        for (int r = 0; r < 4; r++)
            rs[r] += __shfl_xor_sync(0xffffffffu, rs[r], o);
    if ((lane & 3) == 0) {
        #pragma unroll
        for (int r = 0; r < 4; r++) {
            int row = r0 + (r >> 1)*16 + (r & 1)*8;
            int gi = ((((bh*8 + kt)*4) + wn) << 10) + m0 + row;
            g_pm[gi] = rm[r];
            g_ps[gi] = rs[r];
        }
    }
}

// ============================================================
// K4: ctx = softmax(scores) @ v, fused exp + 32-partial combine
// smem: Af 16K + Bf 8K + stats 1K = 25600
// ============================================================
__global__ __launch_bounds__(256) void pv_kernel(float* __restrict__ out)
{
    extern __shared__ __align__(16) char smraw[];
    __half2* Af = (__half2*)smraw;
    __half2* Bf = (__half2*)(smraw + 16384);
    float* sm_m   = (float*)(smraw + 24576);
    float* sm_inv = (float*)(smraw + 25088);

    const int bh = blockIdx.y;
    const int b = bh / HH, h = bh % HH;
    const int m0 = blockIdx.x * 128;
    const int tid = threadIdx.x, lane = tid & 31, wid = tid >> 5;

    if (tid < 128) {
        float m = -1e30f;
        #pragma unroll
        for (int p = 0; p < 32; p++) {
            int gi = (((bh*8 + (p >> 2))*4 + (p & 3)) << 10) + m0 + tid;
            m = fmaxf(m, g_pm[gi]);
        }
        float s = 0.f;
        #pragma unroll
        for (int p = 0; p < 32; p++) {
            int gi = (((bh*8 + (p >> 2))*4 + (p & 3)) << 10) + m0 + tid;
            s += g_ps[gi]*__expf(g_pm[gi] - m);
        }
        sm_m[tid]   = m;
        sm_inv[tid] = 1.f / s;
    }
    __syncthreads();

    const float* pb = g_s + (size_t)bh*LL*LL + (size_t)m0*LL;
    const __half* vb = g_v + (size_t)bh*LL*DHD;

    float acc[8][4];
    #pragma unroll
    for (int j = 0; j < 8; j++)
        #pragma unroll
        for (int c = 0; c < 4; c++) acc[j][c] = 0.f;

    for (int kc0 = 0; kc0 < LL; kc0 += 64) {
        stageAhExp(Af, pb + kc0, LL, tid, sm_m);
        stageBThH64(Bf, vb + (size_t)kc0*DHD, DHD, tid);
        __syncthreads();
        gemm64n64h(Af, Bf, wid, lane, acc);
        __syncthreads();
    }

    const int r0 = wid*16 + (lane >> 2);
    const int c0 = (lane & 3)*2;
    const float inv0 = sm_inv[r0];
    const float inv1 = sm_inv[r0 + 8];
    #pragma unroll
    for (int j = 0; j < 8; j++) {
        int cc = c0 + j*8;
        int l0 = m0 + r0;
        *(float2*)&out[((size_t)b*LL + l0)*DD + h*DHD + cc] =
            make_float2(acc[j][0]*inv0, acc[j][1]*inv0);
        *(float2*)&out[((size_t)b*LL + l0 + 8)*DD + h*DHD + cc] =
            make_float2(acc[j][2]*inv1, acc[j][3]*inv1);
    }
}

// ============================================================
extern "C" void kernel_launch(void* const* d_in, const int* in_sizes, int n_in,
                              void* d_out, int out_size)
{
    const float* hidden  = (const float*)d_in[0];
    const float* mask    = (const float*)d_in[1];
    const float* structm = (const float*)d_in[2];
    const float* Wq      = (const float*)d_in[3];
    const float* bq      = (const float*)d_in[4];
    const float* Wk      = (const float*)d_in[5];
    const float* bk      = (const float*)d_in[6];
    const float* Wv      = (const float*)d_in[7];
    const float* bv      = (const float*)d_in[8];
    const float* dist    = (const float*)d_in[9];
    const float* ssw     = (const float*)d_in[10];
    const float* abv     = (const float*)d_in[11];
    float* out = (float*)d_out;

    cudaFuncSetAttribute(qkv_kernel,    cudaFuncAttributeMaxDynamicSharedMemorySize, 32768);
    cudaFuncSetAttribute(qw_kernel,     cudaFuncAttributeMaxDynamicSharedMemorySize, 24576);
    cudaFuncSetAttribute(pv_kernel,     cudaFuncAttributeMaxDynamicSharedMemorySize, 25600);
    cudaFuncSetAttribute(scores_kernel, cudaFuncAttributeMaxDynamicSharedMemorySize, SC_SMEM);

    qkv_kernel    <<<dim3(6,16,3),  256, 32768>>>(hidden, Wq,bq, Wk,bk, Wv,bv);
    qw_kernel     <<<dim3(8,24,5),  256, 24576>>>(ssw);
    scores_kernel <<<dim3(24,8,8),  512, SC_SMEM>>>(mask, structm, dist, abv);
    pv_kernel     <<<dim3(8,24),    256, 25600>>>(out);
}

// round 10
// speedup vs baseline: 1.1218x; 1.0543x over previous
#include <cuda_runtime.h>
#include <cuda_fp16.h>
#include <cstdint>

#define BB  2
#define LL  1024
#define DD  768
#define HH  12
#define DHD 64
#define BHN (BB*HH)

// ---- scratch ----
__device__ __half g_q [BHN*LL*DHD];            // [bh][l][dh] fp16
__device__ __half g_k [BHN*LL*DHD];            // [bh][l][dh] fp16
__device__ __half g_v [BHN*LL*DHD];            // [bh][l][dh] fp16
__device__ __half g_qw[5*BHN*LL*DHD];          // [i][bh][l][dh] fp16
__device__ float  g_s [(size_t)BHN*LL*LL];     // scores fp32
__device__ float  g_pm[BHN*8*4*LL];            // partial row max  [bh][kt][wn][l]
__device__ float  g_ps[BHN*8*4*LL];            // partial row sumexp

// ============================================================
// fp16 mma helpers (m16n8k16, f32 accum)
// ============================================================
__device__ __forceinline__ void mma16(float* c, const uint4 a, const uint2 b) {
    asm volatile(
        "mma.sync.aligned.m16n8k16.row.col.f32.f16.f16.f32 "
        "{%0,%1,%2,%3}, {%4,%5,%6,%7}, {%8,%9}, {%0,%1,%2,%3};"
        : "+f"(c[0]), "+f"(c[1]), "+f"(c[2]), "+f"(c[3])
        : "r"(a.x), "r"(a.y), "r"(a.z), "r"(a.w), "r"(b.x), "r"(b.y));
}

// ---- f32 register-tile loaders (row-major, row stride ld) ----
template<int ITERS, int TPB>
__device__ __forceinline__ void ldgT4(float4* v, const float* __restrict__ src,
                                      int ld, int tid, int nvalid) {
    #pragma unroll
    for (int it = 0; it < ITERS; it++) {
        int idx = tid + it*TPB;
        int m = idx >> 4, k4 = idx & 15;
        v[it] = (m < nvalid) ? *(const float4*)(src + (size_t)m*ld + k4*4)
                             : make_float4(0.f, 0.f, 0.f, 0.f);
    }
}

// ---- fp16 register-tile loader: each item = 8 halfs (m, k0..k0+7) ----
template<int ITERS, int TPB>
__device__ __forceinline__ void ldgH(uint4* v, const __half* __restrict__ src,
                                     int ld, int tid) {
    #pragma unroll
    for (int it = 0; it < ITERS; it++) {
        int idx = tid + it*TPB;
        int m = idx >> 3, k8 = idx & 7;
        v[it] = *(const uint4*)(src + (size_t)m*ld + k8*8);
    }
}

// ---- STS to A-fragment fp16 layout from f32 regs (MT m-tiles) ----
template<int ITERS, int TPB, int MT>
__device__ __forceinline__ void stsAh(__half2* dst, const float4* v, int tid) {
    #pragma unroll
    for (int it = 0; it < ITERS; it++) {
        int idx = tid + it*TPB;
        int m = idx >> 4, k4 = idx & 15;
        int mt = m >> 4, r = m & 15;
        int rbit = r >> 3, rlow = r & 7;
        {
            int k = k4*4;
            int ku = k & 15, ks = k >> 4, khigh = ku >> 3, kpair = (ku >> 1) & 3;
            dst[((ks*MT + mt)*32 + rlow*4 + kpair)*4 + rbit + 2*khigh] =
                __floats2half2_rn(v[it].x, v[it].y);
        }
        {
            int k = k4*4 + 2;
            int ku = k & 15, ks = k >> 4, khigh = ku >> 3, kpair = (ku >> 1) & 3;
            dst[((ks*MT + mt)*32 + rlow*4 + kpair)*4 + rbit + 2*khigh] =
                __floats2half2_rn(v[it].z, v[it].w);
        }
    }
}

// ---- STS to A-fragment from fp16 regs (no cvt, MT=8) ----
template<int ITERS, int TPB>
__device__ __forceinline__ void stsAhH(__half2* dst, const uint4* v, int tid) {
    #pragma unroll
    for (int it = 0; it < ITERS; it++) {
        int idx = tid + it*TPB;
        int m = idx >> 3, k0 = (idx & 7)*8;
        int mt = m >> 4, r = m & 15;
        int rbit = r >> 3, rlow = r & 7;
        int ks = k0 >> 4, khigh = (k0 >> 3) & 1;
        int base = ((ks*8 + mt)*32 + rlow*4)*4 + rbit + 2*khigh;
        const __half2* p = (const __half2*)&v[it];
        dst[base + 0]  = p[0];
        dst[base + 4]  = p[1];
        dst[base + 8]  = p[2];
        dst[base + 12] = p[3];
    }
}

// ---- STS to B-fragment (NT = N/8) from fp16 regs, n-major source ----
template<int ITERS, int TPB, int NT>
__device__ __forceinline__ void stsBhH(__half2* dst, const uint4* v, int tid) {
    #pragma unroll
    for (int it = 0; it < ITERS; it++) {
        int idx = tid + it*TPB;
        int n = idx >> 3, k0 = (idx & 7)*8;
        int nt = n >> 3, nlow = n & 7;
        int ks = k0 >> 4, reg = (k0 >> 3) & 1;
        int base = ((ks*NT + nt)*32 + nlow*4)*2 + reg;
        const __half2* p = (const __half2*)&v[it];
        dst[base + 0] = p[0];
        dst[base + 2] = p[1];
        dst[base + 4] = p[2];
        dst[base + 6] = p[3];
    }
}

// ---- STS to B-fragment (NT=16) from f32 n-major regs (for dist E bands) ----
template<int ITERS, int TPB>
__device__ __forceinline__ void stsBh(__half2* dst, const float4* v, int tid) {
    #pragma unroll
    for (int it = 0; it < ITERS; it++) {
        int idx = tid + it*TPB;
        int n = idx >> 4, k4 = idx & 15;
        int nt = n >> 3, nlow = n & 7;
        {
            int k = k4*4;
            int ku = k & 15, ks = k >> 4;
            dst[((ks*16 + nt)*32 + nlow*4 + ((ku & 7) >> 1))*2 + (ku >> 3)] =
                __floats2half2_rn(v[it].x, v[it].y);
        }
        {
            int k = k4*4 + 2;
            int ku = k & 15, ks = k >> 4;
            dst[((ks*16 + nt)*32 + nlow*4 + ((ku & 7) >> 1))*2 + (ku >> 3)] =
                __floats2half2_rn(v[it].z, v[it].w);
        }
    }
}

// ---- fused stage: f32 row-major 128x64 -> A-frag (256 threads) ----
__device__ __forceinline__ void stageAh(__half2* dst, const float* __restrict__ src,
                                        int ld, int tid) {
    float4 v[8];
    ldgT4<8,256>(v, src, ld, tid, 128);
    stsAh<8,256,8>(dst, v, tid);
}

// ---- fused stage: f32 k-major 64xN (stride ldn) -> B-frag (256 thr) ----
template<int N>
__device__ __forceinline__ void stageBTh(__half2* dst, const float* __restrict__ src,
                                         int ldn, int tid) {
    constexpr int NT = N / 8;
    constexpr int F4 = N / 4;
    constexpr int ITEMS = 32 * F4;
    #pragma unroll
    for (int it = 0; it < ITEMS/256; it++) {
        int idx = tid + it*256;
        int k2 = idx / F4, nq = idx % F4;
        int k = k2*2;
        float4 u = *(const float4*)(src + (size_t)k*ldn + nq*4);
        float4 w = *(const float4*)(src + (size_t)(k+1)*ldn + nq*4);
        int ku = k & 15, ks = k >> 4, reg = ku >> 3;
        int kl = (ku & 7) >> 1;
        float uu[4] = {u.x,u.y,u.z,u.w};
        float ww[4] = {w.x,w.y,w.z,w.w};
        #pragma unroll
        for (int c2 = 0; c2 < 4; c2++) {
            int n = nq*4 + c2;
            int nt = n >> 3;
            dst[((ks*NT + nt)*32 + (n & 7)*4 + kl)*2 + reg] =
                __floats2half2_rn(uu[c2], ww[c2]);
        }
    }
}

// ---- fp16 k-major 64x64 V chunk: split ldg / sts (PRMT interleave) ----
__device__ __forceinline__ void ldgV(uint4& u, uint4& w, const __half* __restrict__ src,
                                     int tid) {
    int k2 = tid >> 3, n8 = tid & 7;
    int k = k2*2;
    u = *(const uint4*)(src + (size_t)k*DHD + n8*8);
    w = *(const uint4*)(src + (size_t)(k+1)*DHD + n8*8);
}
__device__ __forceinline__ void stsV(__half2* dst, const uint4 u, const uint4 w, int tid) {
    int k2 = tid >> 3, n8 = tid & 7;
    int k = k2*2;
    int ks = k >> 4, kl = (k & 7) >> 1, reg = (k >> 3) & 1;
    const unsigned* ua = (const unsigned*)&u;
    const unsigned* wa = (const unsigned*)&w;
    unsigned* d = (unsigned*)dst;
    #pragma unroll
    for (int c = 0; c < 4; c++) {
        unsigned lo, hi;
        asm("prmt.b32 %0, %1, %2, 0x5410;" : "=r"(lo) : "r"(ua[c]), "r"(wa[c]));
        asm("prmt.b32 %0, %1, %2, 0x7632;" : "=r"(hi) : "r"(ua[c]), "r"(wa[c]));
        int nlo = c*2, nhi = c*2 + 1;
        d[((ks*8 + n8)*32 + nlo*4 + kl)*2 + reg] = lo;
        d[((ks*8 + n8)*32 + nhi*4 + kl)*2 + reg] = hi;
    }
}

// ---- 128x128x64 pass, 8 warps (warp tile 32x64) ----
__device__ __forceinline__ void gemm64h(const __half2* __restrict__ Af,
                                        const __half2* __restrict__ Bf,
                                        int wm, int wn, int lane, float bacc[2][8][4]) {
    const uint4* A4 = (const uint4*)Af;
    const uint2* B2 = (const uint2*)Bf;
    #pragma unroll
    for (int ks = 0; ks < 4; ks++) {
        uint4 a0 = A4[(ks*8 + wm*2 + 0)*32 + lane];
        uint4 a1 = A4[(ks*8 + wm*2 + 1)*32 + lane];
        #pragma unroll
        for (int j = 0; j < 8; j++) {
            uint2 b = B2[(ks*16 + wn*8 + j)*32 + lane];
            mma16(bacc[0][j], a0, b);
            mma16(bacc[1][j], a1, b);
        }
    }
}

// ---- 128x64x64 pass, 8 warps ----
__device__ __forceinline__ void gemm64n64h(const __half2* __restrict__ Af,
                                           const __half2* __restrict__ Bf,
                                           int wid, int lane, float acc[8][4]) {
    const uint4* A4 = (const uint4*)Af;
    const uint2* B2 = (const uint2*)Bf;
    #pragma unroll
    for (int ks = 0; ks < 4; ks++) {
        uint4 a = A4[(ks*8 + wid)*32 + lane];
        #pragma unroll
        for (int j = 0; j < 8; j++) {
            uint2 b = B2[(ks*8 + j)*32 + lane];
            mma16(acc[j], a, b);
        }
    }
}

// ---- 64x64x64 pass, 8 warps (warp tile 16x32), MT=4, NT=8 ----
__device__ __forceinline__ void gemm6464h(const __half2* __restrict__ Af,
                                          const __half2* __restrict__ Bf,
                                          int wm, int wn, int lane, float acc[4][4]) {
    const uint4* A4 = (const uint4*)Af;
    const uint2* B2 = (const uint2*)Bf;
    #pragma unroll
    for (int ks = 0; ks < 4; ks++) {
        uint4 a = A4[(ks*4 + wm)*32 + lane];
        #pragma unroll
        for (int j = 0; j < 4; j++) {
            uint2 b = B2[(ks*8 + wn*4 + j)*32 + lane];
            mma16(acc[j], a, b);
        }
    }
}

// ---- 128x128x64 pass, 16 warps (warp tile 32x32) ----
__device__ __forceinline__ void gemm32h(const __half2* __restrict__ Af,
                                        const __half2* __restrict__ Bf,
                                        int wm, int wn, int lane, float bacc[2][4][4]) {
    const uint4* A4 = (const uint4*)Af;
    const uint2* B2 = (const uint2*)Bf;
    #pragma unroll
    for (int ks = 0; ks < 4; ks++) {
        uint4 a0 = A4[(ks*8 + wm*2 + 0)*32 + lane];
        uint4 a1 = A4[(ks*8 + wm*2 + 1)*32 + lane];
        #pragma unroll
        for (int j = 0; j < 4; j++) {
            uint2 b = B2[(ks*16 + wn*4 + j)*32 + lane];
            mma16(bacc[0][j], a0, b);
            mma16(bacc[1][j], a1, b);
        }
    }
}

__device__ __forceinline__ void zero32(float a[2][4][4]) {
    #pragma unroll
    for (int i = 0; i < 2; i++)
        #pragma unroll
        for (int j = 0; j < 4; j++)
            #pragma unroll
            for (int c = 0; c < 4; c++) a[i][j][c] = 0.f;
}

// ============================================================
// K1: QKV projection (fp16 mma, 256 thr); fp16 [l][dh] outputs
// ============================================================
__global__ __launch_bounds__(256) void qkv_kernel(
    const float* __restrict__ hidden,
    const float* __restrict__ Wq, const float* __restrict__ bq,
    const float* __restrict__ Wk, const float* __restrict__ bk,
    const float* __restrict__ Wv, const float* __restrict__ bv)
{
    extern __shared__ __align__(16) char smraw[];
    __half2* Af = (__half2*)smraw;
    __half2* Bf = (__half2*)(smraw + 16384);

    const int mat = blockIdx.z;
    const float* W    = (mat==0) ? Wq : (mat==1 ? Wk : Wv);
    const float* bias = (mat==0) ? bq : (mat==1 ? bk : bv);
    __half* outp      = (mat==0) ? g_q : (mat==1 ? g_k : g_v);

    const int n0 = blockIdx.x * 128;
    const int m0 = blockIdx.y * 128;
    const int tid = threadIdx.x, lane = tid & 31, wid = tid >> 5;
    const int wm = wid & 3, wn = wid >> 2;

    float acc[2][8][4];
    #pragma unroll
    for (int i = 0; i < 2; i++)
        #pragma unroll
        for (int j = 0; j < 8; j++)
            #pragma unroll
            for (int c = 0; c < 4; c++) acc[i][j][c] = 0.f;

    for (int kc0 = 0; kc0 < DD; kc0 += 64) {
        stageAh(Af, hidden + (size_t)m0*DD + kc0, DD, tid);
        stageBTh<128>(Bf, W + (size_t)kc0*DD + n0, DD, tid);
        __syncthreads();
        gemm64h(Af, Bf, wm, wn, lane, acc);
        __syncthreads();
    }

    const int r0 = wm*32 + (lane >> 2);
    const int c0 = wn*64 + (lane & 3)*2;
    #pragma unroll
    for (int i = 0; i < 2; i++)
        #pragma unroll
        for (int j = 0; j < 8; j++) {
            int cg = n0 + c0 + j*8;
            int h = cg >> 6, dh = cg & 63;
            float2 bb = *(const float2*)(bias + cg);
            #pragma unroll
            for (int half = 0; half < 2; half++) {
                int rg = m0 + r0 + i*16 + half*8;
                int b = rg >> 10, l = rg & 1023;
                *(__half2*)&outp[((size_t)((b*HH + h)*LL + l))*DHD + dh] =
                    __floats2half2_rn(acc[i][j][half*2+0] + bb.x,
                                      acc[i][j][half*2+1] + bb.y);
            }
        }
}

// ============================================================
// K1b: qw precompute (fp16 mma, 256 thr); half in, half out
// ============================================================
__global__ __launch_bounds__(256) void qw_kernel(const float* __restrict__ ssw)
{
    extern __shared__ __align__(16) char smraw[];
    __half2* Af = (__half2*)smraw;
    __half2* Bf = (__half2*)(smraw + 16384);

    const int i5 = blockIdx.z;
    const int bh = blockIdx.y;
    const int h  = bh % HH;
    const int m0 = blockIdx.x * 128;
    const int tid = threadIdx.x, lane = tid & 31, wid = tid >> 5;

    uint4 vH[4];
    ldgH<4,256>(vH, g_q + (size_t)(bh*LL + m0)*DHD, DHD, tid);
    stsAhH<4,256>(Af, vH, tid);
    stageBTh<64>(Bf, ssw + (size_t)(i5*HH + h)*DHD*DHD, DHD, tid);
    __syncthreads();

    float acc[8][4];
    #pragma unroll
    for (int j = 0; j < 8; j++)
        #pragma unroll
        for (int c = 0; c < 4; c++) acc[j][c] = 0.f;

    gemm64n64h(Af, Bf, wid, lane, acc);

    __half* ob = g_qw + ((size_t)(i5*BHN + bh)*LL + m0)*DHD;
    const int r0 = wid*16 + (lane >> 2);
    const int c0 = (lane & 3)*2;
    #pragma unroll
    for (int j = 0; j < 8; j++) {
        int cc = c0 + j*8;
        *(__half2*)(ob + (size_t)r0*DHD + cc)     = __floats2half2_rn(acc[j][0], acc[j][1]);
        *(__half2*)(ob + (size_t)(r0+8)*DHD + cc) = __floats2half2_rn(acc[j][2], acc[j][3]);
    }
}

// ============================================================
// K2: fused scores + register-only partial row stats (R9 version)
// smem: Q|Kb|Ka|E0|E1 (16K ea) + 2x QEb fp16 (128x132) = 149504
// ============================================================
#define SC_SMEM 149504

__global__ __launch_bounds__(512, 1) void scores_kernel(
    const float* __restrict__ mask,
    const float* __restrict__ structm,
    const float* __restrict__ dist,
    const float* __restrict__ abv)
{
    extern __shared__ __align__(16) char smraw[];
    __half2* Q   = (__half2*)smraw;
    __half2* Kb  = (__half2*)(smraw + 16384);
    __half2* Ka  = (__half2*)(smraw + 32768);
    __half2* E0  = (__half2*)(smraw + 49152);
    __half2* E1  = (__half2*)(smraw + 65536);
    __half*  QB0 = (__half*)(smraw + 81920);
    __half*  QB1 = (__half*)(smraw + 115712);

    const int bh = blockIdx.x, kt = blockIdx.y, qt = blockIdx.z;
    const int b = bh / HH, h = bh % HH;
    const int m0 = qt*128, n0 = kt*128;
    const int tid = threadIdx.x, lane = tid & 31, wid = tid >> 5;
    const int wm = wid & 3, wn = wid >> 2;
    const int r0 = wm*32 + (lane >> 2);
    const int c0 = wn*32 + (lane & 3)*2;

    const int base = (qt - kt)*128 + 896;
    int nv1 = 1919 - base; if (nv1 > 128) nv1 = 128;

    const __half* qwbase = g_qw + ((size_t)bh*LL + m0)*DHD;
    const size_t qwstr = (size_t)BHN*LL*DHD;

    uint4 vq[2], vk[2], vH[2];
    float4 vA[4], vB[4];
    ldgH<2,512>(vq, g_q + (size_t)(bh*LL + m0)*DHD, DHD, tid);
    ldgH<2,512>(vk, g_k + (size_t)(bh*LL + n0)*DHD, DHD, tid);
    stsAhH<2,512>(Q, vq, tid);
    stsAhH<2,512>(Ka, vk, tid);
    stsBhH<2,512,16>(Kb, vk, tid);
    ldgT4<4,512>(vA, dist + (size_t)base*DHD, DHD, tid, 128);
    stsBh<4,512>(E0, vA, tid);
    ldgT4<4,512>(vB, dist + (size_t)(base + 128)*DHD, DHD, tid, nv1);
    stsBh<4,512>(E1, vB, tid);
    ldgH<2,512>(vH, qwbase, DHD, tid);
    __syncthreads();

    float acc[2][4][4];
    float bacc[2][4][4];
    zero32(acc);

    auto writeQEh = [&](__half* buf) {
        #pragma unroll
        for (int i = 0; i < 2; i++)
            #pragma unroll
            for (int j = 0; j < 4; j++) {
                int rr = r0 + i*16, cc = c0 + j*8;
                *(__half2*)(buf + rr*132 + cc)     = __floats2half2_rn(bacc[i][j][0], bacc[i][j][1]);
                *(__half2*)(buf + (rr+8)*132 + cc) = __floats2half2_rn(bacc[i][j][2], bacc[i][j][3]);
            }
    };
    auto gatherH = [&](const __half* buf, int off, bool useCol) {
        #pragma unroll
        for (int i = 0; i < 2; i++)
            #pragma unroll
            for (int j = 0; j < 4; j++) {
                int rr = r0 + i*16, cc = c0 + j*8;
                #pragma unroll
                for (int c2 = 0; c2 < 4; c2++) {
                    int R = rr + (c2 >> 1)*8;
                    int C = cc + (c2 & 1);
                    int J = R - C + off;
                    if ((unsigned)J < 128u) {
                        int rowi = useCol ? C : R;
                        acc[i][j][c2] += __half2float(buf[rowi*132 + J]);
                    }
                }
            }
    };

    // S1: KE0 -> QB0
    zero32(bacc); gemm32h(Ka, E0, wm, wn, lane, bacc);
    writeQEh(QB0);
    __syncthreads();

    // S2: KE1 -> QB1; gather KE0
    zero32(bacc); gemm32h(Ka, E1, wm, wn, lane, bacc);
    gatherH(QB0, 127, true);
    writeQEh(QB1);
    __syncthreads();

    // S3: QE0 -> QB0; gather KE1; stage qw0->Ka; ldg qw1
    zero32(bacc); gemm32h(Q, E0, wm, wn, lane, bacc);
    gatherH(QB1, -1, true);
    writeQEh(QB0);
    stsAhH<2,512>(Ka, vH, tid);
    ldgH<2,512>(vH, qwbase + qwstr, DHD, tid);
    __syncthreads();

    // S4: QE1 -> QB1; gather QE0; stage qw1->E0; ldg qw2
    zero32(bacc); gemm32h(Q, E1, wm, wn, lane, bacc);
    gatherH(QB0, 127, false);
    writeQEh(QB1);
    stsAhH<2,512>(E0, vH, tid);
    ldgH<2,512>(vH, qwbase + 2*qwstr, DHD, tid);
    __syncthreads();

    // S5: QK; gather QE1; scale+mask; stage qw2->E1; ldg qw3
    float2 mk[4];
    {
        const float* mrow = mask + b*LL + n0;
        #pragma unroll
        for (int j = 0; j < 4; j++) mk[j] = *(const float2*)(mrow + c0 + j*8);
    }
    zero32(bacc); gemm32h(Q, Kb, wm, wn, lane, bacc);
    gatherH(QB1, -1, false);
    #pragma unroll
    for (int j = 0; j < 4; j++)
        #pragma unroll
        for (int i = 0; i < 2; i++) {
            acc[i][j][0] = (acc[i][j][0] + bacc[i][j][0])*0.125f + mk[j].x;
            acc[i][j][1] = (acc[i][j][1] + bacc[i][j][1])*0.125f + mk[j].y;
            acc[i][j][2] = (acc[i][j][2] + bacc[i][j][2])*0.125f + mk[j].x;
            acc[i][j][3] = (acc[i][j][3] + bacc[i][j][3])*0.125f + mk[j].y;
        }
    stsAhH<2,512>(E1, vH, tid);
    ldgH<2,512>(vH, qwbase + 3*qwstr, DHD, tid);
    __syncthreads();

    // bilinear passes: qw0=Ka, qw1=E0, qw2=E1, qw3=Q, qw4=Ka(again)
    float2 sv[8];
    float  ab;
    auto structPre = [&](int i5) {
        ab = __ldg(&abv[i5*HH + h]);
        const float* stb = structm + (((size_t)(i5*BB + b)*LL + m0)*LL) + n0;
        #pragma unroll
        for (int j = 0; j < 4; j++) {
            sv[j*2+0] = *(const float2*)(stb + (size_t)r0*LL + c0 + j*8);
            sv[j*2+1] = *(const float2*)(stb + (size_t)(r0+8)*LL + c0 + j*8);
        }
    };
    auto structEpi = [&](int i5) {
        #pragma unroll
        for (int j = 0; j < 4; j++) {
            acc[0][j][0] += (bacc[0][j][0] + ab)*sv[j*2+0].x;
            acc[0][j][1] += (bacc[0][j][1] + ab)*sv[j*2+0].y;
            acc[0][j][2] += (bacc[0][j][2] + ab)*sv[j*2+1].x;
            acc[0][j][3] += (bacc[0][j][3] + ab)*sv[j*2+1].y;
        }
        const float* stb = structm + (((size_t)(i5*BB + b)*LL + m0)*LL) + n0;
        #pragma unroll
        for (int j = 0; j < 4; j++) {
            float2 s0 = *(const float2*)(stb + (size_t)(r0+16)*LL + c0 + j*8);
            float2 s1 = *(const float2*)(stb + (size_t)(r0+24)*LL + c0 + j*8);
            acc[1][j][0] += (bacc[1][j][0] + ab)*s0.x;
            acc[1][j][1] += (bacc[1][j][1] + ab)*s0.y;
            acc[1][j][2] += (bacc[1][j][2] + ab)*s1.x;
            acc[1][j][3] += (bacc[1][j][3] + ab)*s1.y;
        }
    };

    // B1: bilinear0 (Ka=qw0); stage qw3->Q; ldg qw4
    structPre(0);
    zero32(bacc); gemm32h(Ka, Kb, wm, wn, lane, bacc);
    structEpi(0);
    stsAhH<2,512>(Q, vH, tid);
    ldgH<2,512>(vH, qwbase + 4*qwstr, DHD, tid);
    __syncthreads();

    // B2: bilinear1 (E0=qw1); stage qw4->Ka
    structPre(1);
    zero32(bacc); gemm32h(E0, Kb, wm, wn, lane, bacc);
    structEpi(1);
    stsAhH<2,512>(Ka, vH, tid);
    __syncthreads();

    // B3: bilinear2 (E1=qw2)
    structPre(2);
    zero32(bacc); gemm32h(E1, Kb, wm, wn, lane, bacc);
    structEpi(2);

    // B4: bilinear3 (Q=qw3)
    structPre(3);
    zero32(bacc); gemm32h(Q, Kb, wm, wn, lane, bacc);
    structEpi(3);

    // B5: bilinear4 (Ka=qw4)
    structPre(4);
    zero32(bacc); gemm32h(Ka, Kb, wm, wn, lane, bacc);
    structEpi(4);

    // store scores
    float* sp = g_s + ((size_t)bh*LL + m0)*LL + n0;
    #pragma unroll
    for (int i = 0; i < 2; i++)
        #pragma unroll
        for (int j = 0; j < 4; j++) {
            int rr = r0 + i*16, cc = c0 + j*8;
            *(float2*)(sp + (size_t)rr*LL + cc)     = make_float2(acc[i][j][0], acc[i][j][1]);
            *(float2*)(sp + (size_t)(rr+8)*LL + cc) = make_float2(acc[i][j][2], acc[i][j][3]);
        }

    // ---- per-wn partial row stats: registers + quad shuffles only ----
    float rm[4], rs[4];
    #pragma unroll
    for (int ridx = 0; ridx < 4; ridx++) {
        int i = ridx >> 1, hh = ridx & 1;
        float m = acc[i][0][hh*2+0];
        #pragma unroll
        for (int j = 0; j < 4; j++) {
            m = fmaxf(m, acc[i][j][hh*2+0]);
            m = fmaxf(m, acc[i][j][hh*2+1]);
        }
        rm[ridx] = m;
    }
    #pragma unroll
    for (int o = 1; o <= 2; o <<= 1)
        #pragma unroll
        for (int r = 0; r < 4; r++)
            rm[r] = fmaxf(rm[r], __shfl_xor_sync(0xffffffffu, rm[r], o));
    #pragma unroll
    for (int ridx = 0; ridx < 4; ridx++) {
        int i = ridx >> 1, hh = ridx & 1;
        float s = 0.f;
        #pragma unroll
        for (int j = 0; j < 4; j++) {
            s += __expf(acc[i][j][hh*2+0] - rm[ridx]);
            s += __expf(acc[i][j][hh*2+1] - rm[ridx]);
        }
        rs[ridx] = s;
    }
    #pragma unroll
    for (int o = 1; o <= 2; o <<= 1)
        #pragma unroll
        for (int r = 0; r < 4; r++)
            rs[r] += __shfl_xor_sync(0xffffffffu, rs[r], o);
    if ((lane & 3) == 0) {
        #pragma unroll
        for (int r = 0; r < 4; r++) {
            int row = r0 + (r >> 1)*16 + (r & 1)*8;
            int gi = ((((bh*8 + kt)*4) + wn) << 10) + m0 + row;
            g_pm[gi] = rm[r];
            g_ps[gi] = rs[r];
        }
    }
}

// ============================================================
// K4: ctx = softmax(scores) @ v — 64-row tiles, double-buffered
// grid (16, 24), 256 thr. smem: 2x(A 8K + B 8K) + stats 512B
// ============================================================
#define PV_SMEM 33536

__global__ __launch_bounds__(256) void pv_kernel(float* __restrict__ out)
{
    extern __shared__ __align__(16) char smraw[];
    __half2* Abuf[2] = { (__half2*)smraw,           (__half2*)(smraw + 16384) };
    __half2* Bbuf[2] = { (__half2*)(smraw + 8192),  (__half2*)(smraw + 24576) };
    float* sm_m   = (float*)(smraw + 32768);
    float* sm_inv = (float*)(smraw + 33024);

    const int bh = blockIdx.y;
    const int b = bh / HH, h = bh % HH;
    const int m0 = blockIdx.x * 64;
    const int tid = threadIdx.x, lane = tid & 31, wid = tid >> 5;
    const int wm = wid & 3, wn = wid >> 2;

    if (tid < 64) {
        float m = -1e30f;
        #pragma unroll
        for (int p = 0; p < 32; p++) {
            int gi = (((bh*8 + (p >> 2))*4 + (p & 3)) << 10) + m0 + tid;
            m = fmaxf(m, g_pm[gi]);
        }
        float s = 0.f;
        #pragma unroll
        for (int p = 0; p < 32; p++) {
            int gi = (((bh*8 + (p >> 2))*4 + (p & 3)) << 10) + m0 + tid;
            s += g_ps[gi]*__expf(g_pm[gi] - m);
        }
        sm_m[tid]   = m;
        sm_inv[tid] = 1.f / s;
    }
    __syncthreads();

    const float* pb = g_s + (size_t)bh*LL*LL + (size_t)m0*LL;
    const __half* vb = g_v + (size_t)bh*LL*DHD;

    float acc[4][4];
    #pragma unroll
    for (int j = 0; j < 4; j++)
        #pragma unroll
        for (int c = 0; c < 4; c++) acc[j][c] = 0.f;

    float4 rA[4];
    uint4 rU, rW;

    auto ldExpA = [&](int kc0) {
        ldgT4<4,256>(rA, pb + kc0, LL, tid, 64);
        #pragma unroll
        for (int it = 0; it < 4; it++) {
            int m = (tid + it*256) >> 4;
            float mm = sm_m[m];
            rA[it].x = __expf(rA[it].x - mm);
            rA[it].y = __expf(rA[it].y - mm);
            rA[it].z = __expf(rA[it].z - mm);
            rA[it].w = __expf(rA[it].w - mm);
        }
    };

    // prologue: chunk 0 staged, chunk 1 in regs
    ldExpA(0);
    ldgV(rU, rW, vb, tid);
    stsAh<4,256,4>(Abuf[0], rA, tid);
    stsV(Bbuf[0], rU, rW, tid);
    ldExpA(64);
    ldgV(rU, rW, vb + (size_t)64*DHD, tid);
    __syncthreads();

    for (int c = 0; c < 16; c++) {
        int cur = c & 1;
        if (c < 15) {
            stsAh<4,256,4>(Abuf[1-cur], rA, tid);
            stsV(Bbuf[1-cur], rU, rW, tid);
        }
        if (c < 14) {
            ldExpA((c+2)*64);
            ldgV(rU, rW, vb + (size_t)(c+2)*64*DHD, tid);
        }
        gemm6464h(Abuf[cur], Bbuf[cur], wm, wn, lane, acc);
        __syncthreads();
    }

    const int r0 = wm*16 + (lane >> 2);
    const int c0 = wn*32 + (lane & 3)*2;
    const float inv0 = sm_inv[r0];
    const float inv1 = sm_inv[r0 + 8];
    #pragma unroll
    for (int j = 0; j < 4; j++) {
        int cc = c0 + j*8;
        int l0 = m0 + r0;
        *(float2*)&out[((size_t)b*LL + l0)*DD + h*DHD + cc] =
            make_float2(acc[j][0]*inv0, acc[j][1]*inv0);
        *(float2*)&out[((size_t)b*LL + l0 + 8)*DD + h*DHD + cc] =
            make_float2(acc[j][2]*inv1, acc[j][3]*inv1);
    }
}

// ============================================================
extern "C" void kernel_launch(void* const* d_in, const int* in_sizes, int n_in,
                              void* d_out, int out_size)
{
    const float* hidden  = (const float*)d_in[0];
    const float* mask    = (const float*)d_in[1];
    const float* structm = (const float*)d_in[2];
    const float* Wq      = (const float*)d_in[3];
    const float* bq      = (const float*)d_in[4];
    const float* Wk      = (const float*)d_in[5];
    const float* bk      = (const float*)d_in[6];
    const float* Wv      = (const float*)d_in[7];
    const float* bv      = (const float*)d_in[8];
    const float* dist    = (const float*)d_in[9];
    const float* ssw     = (const float*)d_in[10];
    const float* abv     = (const float*)d_in[11];
    float* out = (float*)d_out;

    cudaFuncSetAttribute(qkv_kernel,    cudaFuncAttributeMaxDynamicSharedMemorySize, 32768);
    cudaFuncSetAttribute(qw_kernel,     cudaFuncAttributeMaxDynamicSharedMemorySize, 24576);
    cudaFuncSetAttribute(pv_kernel,     cudaFuncAttributeMaxDynamicSharedMemorySize, PV_SMEM);
    cudaFuncSetAttribute(scores_kernel, cudaFuncAttributeMaxDynamicSharedMemorySize, SC_SMEM);

    qkv_kernel    <<<dim3(6,16,3),  256, 32768>>>(hidden, Wq,bq, Wk,bk, Wv,bv);
    qw_kernel     <<<dim3(8,24,5),  256, 24576>>>(ssw);
    scores_kernel <<<dim3(24,8,8),  512, SC_SMEM>>>(mask, structm, dist, abv);
    pv_kernel     <<<dim3(16,24),   256, PV_SMEM>>>(out);
}

// round 12
// speedup vs baseline: 1.1348x; 1.0116x over previous
#include <cuda_runtime.h>
#include <cuda_fp16.h>
#include <cstdint>

#define BB  2
#define LL  1024
#define DD  768
#define HH  12
#define DHD 64
#define BHN (BB*HH)

// ---- scratch ----
__device__ __half g_q [BHN*LL*DHD];            // [bh][l][dh] fp16
__device__ __half g_k [BHN*LL*DHD];            // [bh][l][dh] fp16
__device__ __half g_v [BHN*LL*DHD];            // [bh][l][dh] fp16
__device__ __half g_qw[5*BHN*LL*DHD];          // [i][bh][l][dh] fp16
__device__ float  g_s [(size_t)BHN*LL*LL];     // scores fp32
__device__ float  g_pm[BHN*8*4*LL];            // partial row max  [bh][kt][wn][l]
__device__ float  g_ps[BHN*8*4*LL];            // partial row sumexp

// ============================================================
// fp16 mma helpers (m16n8k16, f32 accum)
// ============================================================
__device__ __forceinline__ void mma16(float* c, const uint4 a, const uint2 b) {
    asm volatile(
        "mma.sync.aligned.m16n8k16.row.col.f32.f16.f16.f32 "
        "{%0,%1,%2,%3}, {%4,%5,%6,%7}, {%8,%9}, {%0,%1,%2,%3};"
        : "+f"(c[0]), "+f"(c[1]), "+f"(c[2]), "+f"(c[3])
        : "r"(a.x), "r"(a.y), "r"(a.z), "r"(a.w), "r"(b.x), "r"(b.y));
}

// ---- f32 register-tile loaders (row-major, row stride ld) ----
template<int ITERS, int TPB>
__device__ __forceinline__ void ldgT4(float4* v, const float* __restrict__ src,
                                      int ld, int tid, int nvalid) {
    #pragma unroll
    for (int it = 0; it < ITERS; it++) {
        int idx = tid + it*TPB;
        int m = idx >> 4, k4 = idx & 15;
        v[it] = (m < nvalid) ? *(const float4*)(src + (size_t)m*ld + k4*4)
                             : make_float4(0.f, 0.f, 0.f, 0.f);
    }
}

// ---- fp16 register-tile loader: each item = 8 halfs (m, k0..k0+7) ----
template<int ITERS, int TPB>
__device__ __forceinline__ void ldgH(uint4* v, const __half* __restrict__ src,
                                     int ld, int tid) {
    #pragma unroll
    for (int it = 0; it < ITERS; it++) {
        int idx = tid + it*TPB;
        int m = idx >> 3, k8 = idx & 7;
        v[it] = *(const uint4*)(src + (size_t)m*ld + k8*8);
    }
}

// ---- STS to A-fragment fp16 layout from f32 regs (MT m-tiles) ----
template<int ITERS, int TPB, int MT>
__device__ __forceinline__ void stsAh(__half2* dst, const float4* v, int tid) {
    #pragma unroll
    for (int it = 0; it < ITERS; it++) {
        int idx = tid + it*TPB;
        int m = idx >> 4, k4 = idx & 15;
        int mt = m >> 4, r = m & 15;
        int rbit = r >> 3, rlow = r & 7;
        {
            int k = k4*4;
            int ku = k & 15, ks = k >> 4, khigh = ku >> 3, kpair = (ku >> 1) & 3;
            dst[((ks*MT + mt)*32 + rlow*4 + kpair)*4 + rbit + 2*khigh] =
                __floats2half2_rn(v[it].x, v[it].y);
        }
        {
            int k = k4*4 + 2;
            int ku = k & 15, ks = k >> 4, khigh = ku >> 3, kpair = (ku >> 1) & 3;
            dst[((ks*MT + mt)*32 + rlow*4 + kpair)*4 + rbit + 2*khigh] =
                __floats2half2_rn(v[it].z, v[it].w);
        }
    }
}

// ---- STS to A-fragment from fp16 regs (no cvt, MT=8) ----
template<int ITERS, int TPB>
__device__ __forceinline__ void stsAhH(__half2* dst, const uint4* v, int tid) {
    #pragma unroll
    for (int it = 0; it < ITERS; it++) {
        int idx = tid + it*TPB;
        int m = idx >> 3, k0 = (idx & 7)*8;
        int mt = m >> 4, r = m & 15;
        int rbit = r >> 3, rlow = r & 7;
        int ks = k0 >> 4, khigh = (k0 >> 3) & 1;
        int base = ((ks*8 + mt)*32 + rlow*4)*4 + rbit + 2*khigh;
        const __half2* p = (const __half2*)&v[it];
        dst[base + 0]  = p[0];
        dst[base + 4]  = p[1];
        dst[base + 8]  = p[2];
        dst[base + 12] = p[3];
    }
}

// ---- STS to B-fragment (NT = N/8) from fp16 regs, n-major source ----
template<int ITERS, int TPB, int NT>
__device__ __forceinline__ void stsBhH(__half2* dst, const uint4* v, int tid) {
    #pragma unroll
    for (int it = 0; it < ITERS; it++) {
        int idx = tid + it*TPB;
        int n = idx >> 3, k0 = (idx & 7)*8;
        int nt = n >> 3, nlow = n & 7;
        int ks = k0 >> 4, reg = (k0 >> 3) & 1;
        int base = ((ks*NT + nt)*32 + nlow*4)*2 + reg;
        const __half2* p = (const __half2*)&v[it];
        dst[base + 0] = p[0];
        dst[base + 2] = p[1];
        dst[base + 4] = p[2];
        dst[base + 6] = p[3];
    }
}

// ---- STS to B-fragment (NT=16) from f32 n-major regs (for dist E bands) ----
template<int ITERS, int TPB>
__device__ __forceinline__ void stsBh(__half2* dst, const float4* v, int tid) {
    #pragma unroll
    for (int it = 0; it < ITERS; it++) {
        int idx = tid + it*TPB;
        int n = idx >> 4, k4 = idx & 15;
        int nt = n >> 3, nlow = n & 7;
        {
            int k = k4*4;
            int ku = k & 15, ks = k >> 4;
            dst[((ks*16 + nt)*32 + nlow*4 + ((ku & 7) >> 1))*2 + (ku >> 3)] =
                __floats2half2_rn(v[it].x, v[it].y);
        }
        {
            int k = k4*4 + 2;
            int ku = k & 15, ks = k >> 4;
            dst[((ks*16 + nt)*32 + nlow*4 + ((ku & 7) >> 1))*2 + (ku >> 3)] =
                __floats2half2_rn(v[it].z, v[it].w);
        }
    }
}

// ---- fused stage: f32 row-major 128x64 -> A-frag (256 threads) ----
__device__ __forceinline__ void stageAh(__half2* dst, const float* __restrict__ src,
                                        int ld, int tid) {
    float4 v[8];
    ldgT4<8,256>(v, src, ld, tid, 128);
    stsAh<8,256,8>(dst, v, tid);
}

// ---- fused stage: f32 k-major 64xN (stride ldn) -> B-frag (256 thr) ----
template<int N>
__device__ __forceinline__ void stageBTh(__half2* dst, const float* __restrict__ src,
                                         int ldn, int tid) {
    constexpr int NT = N / 8;
    constexpr int F4 = N / 4;
    constexpr int ITEMS = 32 * F4;
    #pragma unroll
    for (int it = 0; it < ITEMS/256; it++) {
        int idx = tid + it*256;
        int k2 = idx / F4, nq = idx % F4;
        int k = k2*2;
        float4 u = *(const float4*)(src + (size_t)k*ldn + nq*4);
        float4 w = *(const float4*)(src + (size_t)(k+1)*ldn + nq*4);
        int ku = k & 15, ks = k >> 4, reg = ku >> 3;
        int kl = (ku & 7) >> 1;
        float uu[4] = {u.x,u.y,u.z,u.w};
        float ww[4] = {w.x,w.y,w.z,w.w};
        #pragma unroll
        for (int c2 = 0; c2 < 4; c2++) {
            int n = nq*4 + c2;
            int nt = n >> 3;
            dst[((ks*NT + nt)*32 + (n & 7)*4 + kl)*2 + reg] =
                __floats2half2_rn(uu[c2], ww[c2]);
        }
    }
}

// ---- fp16 k-major 64x64 V chunk: split ldg / sts (PRMT interleave) ----
__device__ __forceinline__ void ldgV(uint4& u, uint4& w, const __half* __restrict__ src,
                                     int tid) {
    int k2 = tid >> 3, n8 = tid & 7;
    int k = k2*2;
    u = *(const uint4*)(src + (size_t)k*DHD + n8*8);
    w = *(const uint4*)(src + (size_t)(k+1)*DHD + n8*8);
}
__device__ __forceinline__ void stsV(__half2* dst, const uint4 u, const uint4 w, int tid) {
    int k2 = tid >> 3, n8 = tid & 7;
    int k = k2*2;
    int ks = k >> 4, kl = (k & 7) >> 1, reg = (k >> 3) & 1;
    const unsigned* ua = (const unsigned*)&u;
    const unsigned* wa = (const unsigned*)&w;
    unsigned* d = (unsigned*)dst;
    #pragma unroll
    for (int c = 0; c < 4; c++) {
        unsigned lo, hi;
        asm("prmt.b32 %0, %1, %2, 0x5410;" : "=r"(lo) : "r"(ua[c]), "r"(wa[c]));
        asm("prmt.b32 %0, %1, %2, 0x7632;" : "=r"(hi) : "r"(ua[c]), "r"(wa[c]));
        int nlo = c*2, nhi = c*2 + 1;
        d[((ks*8 + n8)*32 + nlo*4 + kl)*2 + reg] = lo;
        d[((ks*8 + n8)*32 + nhi*4 + kl)*2 + reg] = hi;
    }
}

// ---- 128x128x64 pass, 8 warps (warp tile 32x64) ----
__device__ __forceinline__ void gemm64h(const __half2* __restrict__ Af,
                                        const __half2* __restrict__ Bf,
                                        int wm, int wn, int lane, float bacc[2][8][4]) {
    const uint4* A4 = (const uint4*)Af;
    const uint2* B2 = (const uint2*)Bf;
    #pragma unroll
    for (int ks = 0; ks < 4; ks++) {
        uint4 a0 = A4[(ks*8 + wm*2 + 0)*32 + lane];
        uint4 a1 = A4[(ks*8 + wm*2 + 1)*32 + lane];
        #pragma unroll
        for (int j = 0; j < 8; j++) {
            uint2 b = B2[(ks*16 + wn*8 + j)*32 + lane];
            mma16(bacc[0][j], a0, b);
            mma16(bacc[1][j], a1, b);
        }
    }
}

// ---- 128x64x64 pass, 8 warps ----
__device__ __forceinline__ void gemm64n64h(const __half2* __restrict__ Af,
                                           const __half2* __restrict__ Bf,
                                           int wid, int lane, float acc[8][4]) {
    const uint4* A4 = (const uint4*)Af;
    const uint2* B2 = (const uint2*)Bf;
    #pragma unroll
    for (int ks = 0; ks < 4; ks++) {
        uint4 a = A4[(ks*8 + wid)*32 + lane];
        #pragma unroll
        for (int j = 0; j < 8; j++) {
            uint2 b = B2[(ks*8 + j)*32 + lane];
            mma16(acc[j], a, b);
        }
    }
}

// ---- 64x64x64 pass, 8 warps (warp tile 16x32), MT=4, NT=8 ----
__device__ __forceinline__ void gemm6464h(const __half2* __restrict__ Af,
                                          const __half2* __restrict__ Bf,
                                          int wm, int wn, int lane, float acc[4][4]) {
    const uint4* A4 = (const uint4*)Af;
    const uint2* B2 = (const uint2*)Bf;
    #pragma unroll
    for (int ks = 0; ks < 4; ks++) {
        uint4 a = A4[(ks*4 + wm)*32 + lane];
        #pragma unroll
        for (int j = 0; j < 4; j++) {
            uint2 b = B2[(ks*8 + wn*4 + j)*32 + lane];
            mma16(acc[j], a, b);
        }
    }
}

// ---- 128x128x64 pass, 16 warps (warp tile 32x32) ----
__device__ __forceinline__ void gemm32h(const __half2* __restrict__ Af,
                                        const __half2* __restrict__ Bf,
                                        int wm, int wn, int lane, float bacc[2][4][4]) {
    const uint4* A4 = (const uint4*)Af;
    const uint2* B2 = (const uint2*)Bf;
    #pragma unroll
    for (int ks = 0; ks < 4; ks++) {
        uint4 a0 = A4[(ks*8 + wm*2 + 0)*32 + lane];
        uint4 a1 = A4[(ks*8 + wm*2 + 1)*32 + lane];
        #pragma unroll
        for (int j = 0; j < 4; j++) {
            uint2 b = B2[(ks*16 + wn*4 + j)*32 + lane];
            mma16(bacc[0][j], a0, b);
            mma16(bacc[1][j], a1, b);
        }
    }
}

__device__ __forceinline__ void zero32(float a[2][4][4]) {
    #pragma unroll
    for (int i = 0; i < 2; i++)
        #pragma unroll
        for (int j = 0; j < 4; j++)
            #pragma unroll
            for (int c = 0; c < 4; c++) a[i][j][c] = 0.f;
}

// ============================================================
// K1: QKV projection (fp16 mma, 256 thr); fp16 [l][dh] outputs
// ============================================================
__global__ __launch_bounds__(256) void qkv_kernel(
    const float* __restrict__ hidden,
    const float* __restrict__ Wq, const float* __restrict__ bq,
    const float* __restrict__ Wk, const float* __restrict__ bk,
    const float* __restrict__ Wv, const float* __restrict__ bv)
{
    extern __shared__ __align__(16) char smraw[];
    __half2* Af = (__half2*)smraw;
    __half2* Bf = (__half2*)(smraw + 16384);

    const int mat = blockIdx.z;
    const float* W    = (mat==0) ? Wq : (mat==1 ? Wk : Wv);
    const float* bias = (mat==0) ? bq : (mat==1 ? bk : bv);
    __half* outp      = (mat==0) ? g_q : (mat==1 ? g_k : g_v);

    const int n0 = blockIdx.x * 128;
    const int m0 = blockIdx.y * 128;
    const int tid = threadIdx.x, lane = tid & 31, wid = tid >> 5;
    const int wm = wid & 3, wn = wid >> 2;

    float acc[2][8][4];
    #pragma unroll
    for (int i = 0; i < 2; i++)
        #pragma unroll
        for (int j = 0; j < 8; j++)
            #pragma unroll
            for (int c = 0; c < 4; c++) acc[i][j][c] = 0.f;

    for (int kc0 = 0; kc0 < DD; kc0 += 64) {
        stageAh(Af, hidden + (size_t)m0*DD + kc0, DD, tid);
        stageBTh<128>(Bf, W + (size_t)kc0*DD + n0, DD, tid);
        __syncthreads();
        gemm64h(Af, Bf, wm, wn, lane, acc);
        __syncthreads();
    }

    const int r0 = wm*32 + (lane >> 2);
    const int c0 = wn*64 + (lane & 3)*2;
    #pragma unroll
    for (int i = 0; i < 2; i++)
        #pragma unroll
        for (int j = 0; j < 8; j++) {
            int cg = n0 + c0 + j*8;
            int h = cg >> 6, dh = cg & 63;
            float2 bb = *(const float2*)(bias + cg);
            #pragma unroll
            for (int half = 0; half < 2; half++) {
                int rg = m0 + r0 + i*16 + half*8;
                int b = rg >> 10, l = rg & 1023;
                *(__half2*)&outp[((size_t)((b*HH + h)*LL + l))*DHD + dh] =
                    __floats2half2_rn(acc[i][j][half*2+0] + bb.x,
                                      acc[i][j][half*2+1] + bb.y);
            }
        }
}

// ============================================================
// K1b: qw precompute (fp16 mma, 256 thr); half in, half out
// ============================================================
__global__ __launch_bounds__(256) void qw_kernel(const float* __restrict__ ssw)
{
    extern __shared__ __align__(16) char smraw[];
    __half2* Af = (__half2*)smraw;
    __half2* Bf = (__half2*)(smraw + 16384);

    const int i5 = blockIdx.z;
    const int bh = blockIdx.y;
    const int h  = bh % HH;
    const int m0 = blockIdx.x * 128;
    const int tid = threadIdx.x, lane = tid & 31, wid = tid >> 5;

    uint4 vH[4];
    ldgH<4,256>(vH, g_q + (size_t)(bh*LL + m0)*DHD, DHD, tid);
    stsAhH<4,256>(Af, vH, tid);
    stageBTh<64>(Bf, ssw + (size_t)(i5*HH + h)*DHD*DHD, DHD, tid);
    __syncthreads();

    float acc[8][4];
    #pragma unroll
    for (int j = 0; j < 8; j++)
        #pragma unroll
        for (int c = 0; c < 4; c++) acc[j][c] = 0.f;

    gemm64n64h(Af, Bf, wid, lane, acc);

    __half* ob = g_qw + ((size_t)(i5*BHN + bh)*LL + m0)*DHD;
    const int r0 = wid*16 + (lane >> 2);
    const int c0 = (lane & 3)*2;
    #pragma unroll
    for (int j = 0; j < 8; j++) {
        int cc = c0 + j*8;
        *(__half2*)(ob + (size_t)r0*DHD + cc)     = __floats2half2_rn(acc[j][0], acc[j][1]);
        *(__half2*)(ob + (size_t)(r0+8)*DHD + cc) = __floats2half2_rn(acc[j][2], acc[j][3]);
    }
}

// ============================================================
// K2: fused scores — shear-on-WRITE positional buffers (fixed
// qw0 staging order). 4 positional gemms barrier-free.
// smem: Q|Kb|Ka|E0|E1 (16K ea) + bufQ/bufK (128x136 fp16 ea) = 151552
// ============================================================
#define SC_SMEM 151552

__global__ __launch_bounds__(512, 1) void scores_kernel(
    const float* __restrict__ mask,
    const float* __restrict__ structm,
    const float* __restrict__ dist,
    const float* __restrict__ abv)
{
    extern __shared__ __align__(16) char smraw[];
    __half2* Q   = (__half2*)smraw;
    __half2* Kb  = (__half2*)(smraw + 16384);
    __half2* Ka  = (__half2*)(smraw + 32768);
    __half2* E0  = (__half2*)(smraw + 49152);
    __half2* E1  = (__half2*)(smraw + 65536);
    __half* bufQ = (__half*)(smraw + 81920);    // [128][136]
    __half* bufK = (__half*)(smraw + 116736);   // [128][136]

    const int bh = blockIdx.x, kt = blockIdx.y, qt = blockIdx.z;
    const int b = bh / HH, h = bh % HH;
    const int m0 = qt*128, n0 = kt*128;
    const int tid = threadIdx.x, lane = tid & 31, wid = tid >> 5;
    const int wm = wid & 3, wn = wid >> 2;
    const int r0 = wm*32 + (lane >> 2);
    const int c0 = wn*32 + (lane & 3)*2;

    const int base = (qt - kt)*128 + 896;
    int nv1 = 1919 - base; if (nv1 > 128) nv1 = 128;

    const __half* qwbase = g_qw + ((size_t)bh*LL + m0)*DHD;
    const size_t qwstr = (size_t)BHN*LL*DHD;

    uint4 vq[2], vk[2], vH[2];
    float4 vA[4], vB[4];
    ldgH<2,512>(vq, g_q + (size_t)(bh*LL + m0)*DHD, DHD, tid);
    ldgH<2,512>(vk, g_k + (size_t)(bh*LL + n0)*DHD, DHD, tid);
    stsAhH<2,512>(Q, vq, tid);
    stsAhH<2,512>(Ka, vk, tid);
    stsBhH<2,512,16>(Kb, vk, tid);
    ldgT4<4,512>(vA, dist + (size_t)base*DHD, DHD, tid, 128);
    stsBh<4,512>(E0, vA, tid);
    ldgT4<4,512>(vB, dist + (size_t)(base + 128)*DHD, DHD, tid, nv1);
    stsBh<4,512>(E1, vB, tid);
    ldgH<2,512>(vH, qwbase, DHD, tid);          // qw0 prefetch
    __syncthreads();

    float acc[2][4][4];
    float bacc[2][4][4];
    zero32(acc);

    // shear-write: QE element (R, Jcol) contributes at C = R - (Jcol+128h) + 127
    auto shearQE = [&](int h128) {
        #pragma unroll
        for (int i = 0; i < 2; i++)
            #pragma unroll
            for (int j = 0; j < 4; j++)
                #pragma unroll
                for (int c2 = 0; c2 < 4; c2++) {
                    int R    = r0 + i*16 + (c2 >> 1)*8;
                    int Jcol = c0 + j*8 + (c2 & 1);
                    int C = R - Jcol + 127 - h128;
                    if ((unsigned)C < 128u)
                        bufQ[R*136 + C] = __float2half(bacc[i][j][c2]);
                }
    };
    // shear-write: KE element (rowK, Jcol) contributes at R = rowK + Jcol + 128h - 127
    auto shearKE = [&](int h128) {
        #pragma unroll
        for (int i = 0; i < 2; i++)
            #pragma unroll
            for (int j = 0; j < 4; j++)
                #pragma unroll
                for (int c2 = 0; c2 < 4; c2++) {
                    int rowK = r0 + i*16 + (c2 >> 1)*8;
                    int Jcol = c0 + j*8 + (c2 & 1);
                    int R = rowK + Jcol + h128 - 127;
                    if ((unsigned)R < 128u)
                        bufK[R*136 + rowK] = __float2half(bacc[i][j][c2]);
                }
    };

    // ---- positional phase: 4 gemms back-to-back, no barriers ----
    zero32(bacc); gemm32h(Ka, E0, wm, wn, lane, bacc); shearKE(0);
    zero32(bacc); gemm32h(Ka, E1, wm, wn, lane, bacc); shearKE(128);
    zero32(bacc); gemm32h(Q,  E0, wm, wn, lane, bacc); shearQE(0);
    zero32(bacc); gemm32h(Q,  E1, wm, wn, lane, bacc); shearQE(128);
    __syncthreads();

    // ---- stage qw0 (held in vH) -> E0 FIRST, then prefetch qw1 ----
    stsAhH<2,512>(E0, vH, tid);                 // qw0 -> E0 (E0 free after positional)
    ldgH<2,512>(vH, qwbase + qwstr, DHD, tid);  // qw1

    // ---- coalesced read-add of both positional terms ----
    #pragma unroll
    for (int i = 0; i < 2; i++)
        #pragma unroll
        for (int hh = 0; hh < 2; hh++) {
            int rr = r0 + i*16 + hh*8;
            #pragma unroll
            for (int j = 0; j < 4; j++) {
                int cc = c0 + j*8;
                __half2 a = *(const __half2*)(bufQ + rr*136 + cc);
                __half2 bvl = *(const __half2*)(bufK + rr*136 + cc);
                float2 af = __half22float2(a);
                float2 bf = __half22float2(bvl);
                acc[i][j][hh*2+0] += af.x + bf.x;
                acc[i][j][hh*2+1] += af.y + bf.y;
            }
        }

    // ---- QK pass: gemm(Q,Kb); scale + mask ----
    float2 mk[4];
    {
        const float* mrow = mask + b*LL + n0;
        #pragma unroll
        for (int j = 0; j < 4; j++) mk[j] = *(const float2*)(mrow + c0 + j*8);
    }
    zero32(bacc); gemm32h(Q, Kb, wm, wn, lane, bacc);
    #pragma unroll
    for (int j = 0; j < 4; j++)
        #pragma unroll
        for (int i = 0; i < 2; i++) {
            acc[i][j][0] = (acc[i][j][0] + bacc[i][j][0])*0.125f + mk[j].x;
            acc[i][j][1] = (acc[i][j][1] + bacc[i][j][1])*0.125f + mk[j].y;
            acc[i][j][2] = (acc[i][j][2] + bacc[i][j][2])*0.125f + mk[j].x;
            acc[i][j][3] = (acc[i][j][3] + bacc[i][j][3])*0.125f + mk[j].y;
        }
    __syncthreads();

    // bilinear passes: qw0=E0, qw1=E1, qw2=Q, qw3=Ka, qw4=E0(again)
    float2 sv[8];
    float  ab;
    auto structPre = [&](int i5) {
        ab = __ldg(&abv[i5*HH + h]);
        const float* stb = structm + (((size_t)(i5*BB + b)*LL + m0)*LL) + n0;
        #pragma unroll
        for (int j = 0; j < 4; j++) {
            sv[j*2+0] = *(const float2*)(stb + (size_t)r0*LL + c0 + j*8);
            sv[j*2+1] = *(const float2*)(stb + (size_t)(r0+8)*LL + c0 + j*8);
        }
    };
    auto structEpi = [&](int i5) {
        #pragma unroll
        for (int j = 0; j < 4; j++) {
            acc[0][j][0] += (bacc[0][j][0] + ab)*sv[j*2+0].x;
            acc[0][j][1] += (bacc[0][j][1] + ab)*sv[j*2+0].y;
            acc[0][j][2] += (bacc[0][j][2] + ab)*sv[j*2+1].x;
            acc[0][j][3] += (bacc[0][j][3] + ab)*sv[j*2+1].y;
        }
        const float* stb = structm + (((size_t)(i5*BB + b)*LL + m0)*LL) + n0;
        #pragma unroll
        for (int j = 0; j < 4; j++) {
            float2 s0 = *(const float2*)(stb + (size_t)(r0+16)*LL + c0 + j*8);
            float2 s1 = *(const float2*)(stb + (size_t)(r0+24)*LL + c0 + j*8);
            acc[1][j][0] += (bacc[1][j][0] + ab)*s0.x;
            acc[1][j][1] += (bacc[1][j][1] + ab)*s0.y;
            acc[1][j][2] += (bacc[1][j][2] + ab)*s1.x;
            acc[1][j][3] += (bacc[1][j][3] + ab)*s1.y;
        }
    };

    // B1: bilinear0 (E0=qw0); stage qw1->E1; ldg qw2
    structPre(0);
    zero32(bacc); gemm32h(E0, Kb, wm, wn, lane, bacc);
    structEpi(0);
    stsAhH<2,512>(E1, vH, tid);
    ldgH<2,512>(vH, qwbase + 2*qwstr, DHD, tid);
    __syncthreads();

    // B2: bilinear1 (E1=qw1); stage qw2->Q; ldg qw3
    structPre(1);
    zero32(bacc); gemm32h(E1, Kb, wm, wn, lane, bacc);
    structEpi(1);
    stsAhH<2,512>(Q, vH, tid);
    ldgH<2,512>(vH, qwbase + 3*qwstr, DHD, tid);
    __syncthreads();

    // B3: bilinear2 (Q=qw2); stage qw3->Ka; ldg qw4
    structPre(2);
    zero32(bacc); gemm32h(Q, Kb, wm, wn, lane, bacc);
    structEpi(2);
    stsAhH<2,512>(Ka, vH, tid);
    ldgH<2,512>(vH, qwbase + 4*qwstr, DHD, tid);
    __syncthreads();

    // B4: bilinear3 (Ka=qw3); stage qw4->E0
    structPre(3);
    zero32(bacc); gemm32h(Ka, Kb, wm, wn, lane, bacc);
    structEpi(3);
    stsAhH<2,512>(E0, vH, tid);
    __syncthreads();

    // B5: bilinear4 (E0=qw4)
    structPre(4);
    zero32(bacc); gemm32h(E0, Kb, wm, wn, lane, bacc);
    structEpi(4);

    // store scores
    float* sp = g_s + ((size_t)bh*LL + m0)*LL + n0;
    #pragma unroll
    for (int i = 0; i < 2; i++)
        #pragma unroll
        for (int j = 0; j < 4; j++) {
            int rr = r0 + i*16, cc = c0 + j*8;
            *(float2*)(sp + (size_t)rr*LL + cc)     = make_float2(acc[i][j][0], acc[i][j][1]);
            *(float2*)(sp + (size_t)(rr+8)*LL + cc) = make_float2(acc[i][j][2], acc[i][j][3]);
        }

    // ---- per-wn partial row stats: registers + quad shuffles only ----
    float rm[4], rs[4];
    #pragma unroll
    for (int ridx = 0; ridx < 4; ridx++) {
        int i = ridx >> 1, hh = ridx & 1;
        float m = acc[i][0][hh*2+0];
        #pragma unroll
        for (int j = 0; j < 4; j++) {
            m = fmaxf(m, acc[i][j][hh*2+0]);
            m = fmaxf(m, acc[i][j][hh*2+1]);
        }
        rm[ridx] = m;
    }
    #pragma unroll
    for (int o = 1; o <= 2; o <<= 1)
        #pragma unroll
        for (int r = 0; r < 4; r++)
            rm[r] = fmaxf(rm[r], __shfl_xor_sync(0xffffffffu, rm[r], o));
    #pragma unroll
    for (int ridx = 0; ridx < 4; ridx++) {
        int i = ridx >> 1, hh = ridx & 1;
        float s = 0.f;
        #pragma unroll
        for (int j = 0; j < 4; j++) {
            s += __expf(acc[i][j][hh*2+0] - rm[ridx]);
            s += __expf(acc[i][j][hh*2+1] - rm[ridx]);
        }
        rs[ridx] = s;
    }
    #pragma unroll
    for (int o = 1; o <= 2; o <<= 1)
        #pragma unroll
        for (int r = 0; r < 4; r++)
            rs[r] += __shfl_xor_sync(0xffffffffu, rs[r], o);
    if ((lane & 3) == 0) {
        #pragma unroll
        for (int r = 0; r < 4; r++) {
            int row = r0 + (r >> 1)*16 + (r & 1)*8;
            int gi = ((((bh*8 + kt)*4) + wn) << 10) + m0 + row;
            g_pm[gi] = rm[r];
            g_ps[gi] = rs[r];
        }
    }
}

// ============================================================
// K4: ctx = softmax(scores) @ v — 64-row tiles, double-buffered
// grid (16, 24), 256 thr. smem: 2x(A 8K + B 8K) + stats 512B
// ============================================================
#define PV_SMEM 33536

__global__ __launch_bounds__(256) void pv_kernel(float* __restrict__ out)
{
    extern __shared__ __align__(16) char smraw[];
    __half2* Abuf[2] = { (__half2*)smraw,           (__half2*)(smraw + 16384) };
    __half2* Bbuf[2] = { (__half2*)(smraw + 8192),  (__half2*)(smraw + 24576) };
    float* sm_m   = (float*)(smraw + 32768);
    float* sm_inv = (float*)(smraw + 33024);

    const int bh = blockIdx.y;
    const int b = bh / HH, h = bh % HH;
    const int m0 = blockIdx.x * 64;
    const int tid = threadIdx.x, lane = tid & 31, wid = tid >> 5;
    const int wm = wid & 3, wn = wid >> 2;

    if (tid < 64) {
        float m = -1e30f;
        #pragma unroll
        for (int p = 0; p < 32; p++) {
            int gi = (((bh*8 + (p >> 2))*4 + (p & 3)) << 10) + m0 + tid;
            m = fmaxf(m, g_pm[gi]);
        }
        float s = 0.f;
        #pragma unroll
        for (int p = 0; p < 32; p++) {
            int gi = (((bh*8 + (p >> 2))*4 + (p & 3)) << 10) + m0 + tid;
            s += g_ps[gi]*__expf(g_pm[gi] - m);
        }
        sm_m[tid]   = m;
        sm_inv[tid] = 1.f / s;
    }
    __syncthreads();

    const float* pb = g_s + (size_t)bh*LL*LL + (size_t)m0*LL;
    const __half* vb = g_v + (size_t)bh*LL*DHD;

    float acc[4][4];
    #pragma unroll
    for (int j = 0; j < 4; j++)
        #pragma unroll
        for (int c = 0; c < 4; c++) acc[j][c] = 0.f;

    float4 rA[4];
    uint4 rU, rW;

    auto ldExpA = [&](int kc0) {
        ldgT4<4,256>(rA, pb + kc0, LL, tid, 64);
        #pragma unroll
        for (int it = 0; it < 4; it++) {
            int m = (tid + it*256) >> 4;
            float mm = sm_m[m];
            rA[it].x = __expf(rA[it].x - mm);
            rA[it].y = __expf(rA[it].y - mm);
            rA[it].z = __expf(rA[it].z - mm);
            rA[it].w = __expf(rA[it].w - mm);
        }
    };

    // prologue: chunk 0 staged, chunk 1 in regs
    ldExpA(0);
    ldgV(rU, rW, vb, tid);
    stsAh<4,256,4>(Abuf[0], rA, tid);
    stsV(Bbuf[0], rU, rW, tid);
    ldExpA(64);
    ldgV(rU, rW, vb + (size_t)64*DHD, tid);
    __syncthreads();

    for (int c = 0; c < 16; c++) {
        int cur = c & 1;
        if (c < 15) {
            stsAh<4,256,4>(Abuf[1-cur], rA, tid);
            stsV(Bbuf[1-cur], rU, rW, tid);
        }
        if (c < 14) {
            ldExpA((c+2)*64);
            ldgV(rU, rW, vb + (size_t)(c+2)*64*DHD, tid);
        }
        gemm6464h(Abuf[cur], Bbuf[cur], wm, wn, lane, acc);
        __syncthreads();
    }

    const int r0 = wm*16 + (lane >> 2);
    const int c0 = wn*32 + (lane & 3)*2;
    const float inv0 = sm_inv[r0];
    const float inv1 = sm_inv[r0 + 8];
    #pragma unroll
    for (int j = 0; j < 4; j++) {
        int cc = c0 + j*8;
        int l0 = m0 + r0;
        *(float2*)&out[((size_t)b*LL + l0)*DD + h*DHD + cc] =
            make_float2(acc[j][0]*inv0, acc[j][1]*inv0);
        *(float2*)&out[((size_t)b*LL + l0 + 8)*DD + h*DHD + cc] =
            make_float2(acc[j][2]*inv1, acc[j][3]*inv1);
    }
}

// ============================================================
extern "C" void kernel_launch(void* const* d_in, const int* in_sizes, int n_in,
                              void* d_out, int out_size)
{
    const float* hidden  = (const float*)d_in[0];
    const float* mask    = (const float*)d_in[1];
    const float* structm = (const float*)d_in[2];
    const float* Wq      = (const float*)d_in[3];
    const float* bq      = (const float*)d_in[4];
    const float* Wk      = (const float*)d_in[5];
    const float* bk      = (const float*)d_in[6];
    const float* Wv      = (const float*)d_in[7];
    const float* bv      = (const float*)d_in[8];
    const float* dist    = (const float*)d_in[9];
    const float* ssw     = (const float*)d_in[10];
    const float* abv     = (const float*)d_in[11];
    float* out = (float*)d_out;

    cudaFuncSetAttribute(qkv_kernel,    cudaFuncAttributeMaxDynamicSharedMemorySize, 32768);
    cudaFuncSetAttribute(qw_kernel,     cudaFuncAttributeMaxDynamicSharedMemorySize, 24576);
    cudaFuncSetAttribute(pv_kernel,     cudaFuncAttributeMaxDynamicSharedMemorySize, PV_SMEM);
    cudaFuncSetAttribute(scores_kernel, cudaFuncAttributeMaxDynamicSharedMemorySize, SC_SMEM);

    qkv_kernel    <<<dim3(6,16,3),  256, 32768>>>(hidden, Wq,bq, Wk,bk, Wv,bv);
    qw_kernel     <<<dim3(8,24,5),  256, 24576>>>(ssw);
    scores_kernel <<<dim3(24,8,8),  512, SC_SMEM>>>(mask, structm, dist, abv);
    pv_kernel     <<<dim3(16,24),   256, PV_SMEM>>>(out);
}

// round 13
// speedup vs baseline: 1.1848x; 1.0441x over previous
#include <cuda_runtime.h>
#include <cuda_fp16.h>
#include <cstdint>

#define BB  2
#define LL  1024
#define DD  768
#define HH  12
#define DHD 64
#define BHN (BB*HH)

// ---- scratch ----
__device__ __half g_q [BHN*LL*DHD];            // [bh][l][dh] fp16
__device__ __half g_k [BHN*LL*DHD];            // [bh][l][dh] fp16
__device__ __half g_v [BHN*LL*DHD];            // [bh][l][dh] fp16
__device__ __half g_qw[5*BHN*LL*DHD];          // [i][bh][l][dh] fp16
__device__ float  g_s [(size_t)BHN*LL*LL];     // scores fp32
__device__ float  g_pm[BHN*8*4*LL];            // partial row max  [bh][kt][wn][l]
__device__ float  g_ps[BHN*8*4*LL];            // partial row sumexp

// ============================================================
// fp16 mma helpers (m16n8k16, f32 accum)
// ============================================================
__device__ __forceinline__ void mma16(float* c, const uint4 a, const uint2 b) {
    asm volatile(
        "mma.sync.aligned.m16n8k16.row.col.f32.f16.f16.f32 "
        "{%0,%1,%2,%3}, {%4,%5,%6,%7}, {%8,%9}, {%0,%1,%2,%3};"
        : "+f"(c[0]), "+f"(c[1]), "+f"(c[2]), "+f"(c[3])
        : "r"(a.x), "r"(a.y), "r"(a.z), "r"(a.w), "r"(b.x), "r"(b.y));
}

// ---- f32 register-tile loaders (row-major, row stride ld) ----
template<int ITERS, int TPB>
__device__ __forceinline__ void ldgT4(float4* v, const float* __restrict__ src,
                                      int ld, int tid, int nvalid) {
    #pragma unroll
    for (int it = 0; it < ITERS; it++) {
        int idx = tid + it*TPB;
        int m = idx >> 4, k4 = idx & 15;
        v[it] = (m < nvalid) ? *(const float4*)(src + (size_t)m*ld + k4*4)
                             : make_float4(0.f, 0.f, 0.f, 0.f);
    }
}

// ---- fp16 register-tile loader: each item = 8 halfs (m, k0..k0+7) ----
template<int ITERS, int TPB>
__device__ __forceinline__ void ldgH(uint4* v, const __half* __restrict__ src,
                                     int ld, int tid) {
    #pragma unroll
    for (int it = 0; it < ITERS; it++) {
        int idx = tid + it*TPB;
        int m = idx >> 3, k8 = idx & 7;
        v[it] = *(const uint4*)(src + (size_t)m*ld + k8*8);
    }
}

// ---- STS to A-fragment fp16 layout from f32 regs (MT m-tiles) ----
template<int ITERS, int TPB, int MT>
__device__ __forceinline__ void stsAh(__half2* dst, const float4* v, int tid) {
    #pragma unroll
    for (int it = 0; it < ITERS; it++) {
        int idx = tid + it*TPB;
        int m = idx >> 4, k4 = idx & 15;
        int mt = m >> 4, r = m & 15;
        int rbit = r >> 3, rlow = r & 7;
        {
            int k = k4*4;
            int ku = k & 15, ks = k >> 4, khigh = ku >> 3, kpair = (ku >> 1) & 3;
            dst[((ks*MT + mt)*32 + rlow*4 + kpair)*4 + rbit + 2*khigh] =
                __floats2half2_rn(v[it].x, v[it].y);
        }
        {
            int k = k4*4 + 2;
            int ku = k & 15, ks = k >> 4, khigh = ku >> 3, kpair = (ku >> 1) & 3;
            dst[((ks*MT + mt)*32 + rlow*4 + kpair)*4 + rbit + 2*khigh] =
                __floats2half2_rn(v[it].z, v[it].w);
        }
    }
}

// ---- STS to A-fragment from fp16 regs (no cvt, MT=8) ----
template<int ITERS, int TPB>
__device__ __forceinline__ void stsAhH(__half2* dst, const uint4* v, int tid) {
    #pragma unroll
    for (int it = 0; it < ITERS; it++) {
        int idx = tid + it*TPB;
        int m = idx >> 3, k0 = (idx & 7)*8;
        int mt = m >> 4, r = m & 15;
        int rbit = r >> 3, rlow = r & 7;
        int ks = k0 >> 4, khigh = (k0 >> 3) & 1;
        int base = ((ks*8 + mt)*32 + rlow*4)*4 + rbit + 2*khigh;
        const __half2* p = (const __half2*)&v[it];
        dst[base + 0]  = p[0];
        dst[base + 4]  = p[1];
        dst[base + 8]  = p[2];
        dst[base + 12] = p[3];
    }
}

// ---- STS to B-fragment (NT = N/8) from fp16 regs, n-major source ----
template<int ITERS, int TPB, int NT>
__device__ __forceinline__ void stsBhH(__half2* dst, const uint4* v, int tid) {
    #pragma unroll
    for (int it = 0; it < ITERS; it++) {
        int idx = tid + it*TPB;
        int n = idx >> 3, k0 = (idx & 7)*8;
        int nt = n >> 3, nlow = n & 7;
        int ks = k0 >> 4, reg = (k0 >> 3) & 1;
        int base = ((ks*NT + nt)*32 + nlow*4)*2 + reg;
        const __half2* p = (const __half2*)&v[it];
        dst[base + 0] = p[0];
        dst[base + 2] = p[1];
        dst[base + 4] = p[2];
        dst[base + 6] = p[3];
    }
}

// ---- STS to B-fragment (NT=16) from f32 n-major regs (for dist E bands) ----
template<int ITERS, int TPB>
__device__ __forceinline__ void stsBh(__half2* dst, const float4* v, int tid) {
    #pragma unroll
    for (int it = 0; it < ITERS; it++) {
        int idx = tid + it*TPB;
        int n = idx >> 4, k4 = idx & 15;
        int nt = n >> 3, nlow = n & 7;
        {
            int k = k4*4;
            int ku = k & 15, ks = k >> 4;
            dst[((ks*16 + nt)*32 + nlow*4 + ((ku & 7) >> 1))*2 + (ku >> 3)] =
                __floats2half2_rn(v[it].x, v[it].y);
        }
        {
            int k = k4*4 + 2;
            int ku = k & 15, ks = k >> 4;
            dst[((ks*16 + nt)*32 + nlow*4 + ((ku & 7) >> 1))*2 + (ku >> 3)] =
                __floats2half2_rn(v[it].z, v[it].w);
        }
    }
}

// ---- fused stage: f32 row-major 128x64 -> A-frag (256 threads) ----
__device__ __forceinline__ void stageAh(__half2* dst, const float* __restrict__ src,
                                        int ld, int tid) {
    float4 v[8];
    ldgT4<8,256>(v, src, ld, tid, 128);
    stsAh<8,256,8>(dst, v, tid);
}

// ---- fused stage: f32 k-major 64xN (stride ldn) -> B-frag (256 thr) ----
template<int N>
__device__ __forceinline__ void stageBTh(__half2* dst, const float* __restrict__ src,
                                         int ldn, int tid) {
    constexpr int NT = N / 8;
    constexpr int F4 = N / 4;
    constexpr int ITEMS = 32 * F4;
    #pragma unroll
    for (int it = 0; it < ITEMS/256; it++) {
        int idx = tid + it*256;
        int k2 = idx / F4, nq = idx % F4;
        int k = k2*2;
        float4 u = *(const float4*)(src + (size_t)k*ldn + nq*4);
        float4 w = *(const float4*)(src + (size_t)(k+1)*ldn + nq*4);
        int ku = k & 15, ks = k >> 4, reg = ku >> 3;
        int kl = (ku & 7) >> 1;
        float uu[4] = {u.x,u.y,u.z,u.w};
        float ww[4] = {w.x,w.y,w.z,w.w};
        #pragma unroll
        for (int c2 = 0; c2 < 4; c2++) {
            int n = nq*4 + c2;
            int nt = n >> 3;
            dst[((ks*NT + nt)*32 + (n & 7)*4 + kl)*2 + reg] =
                __floats2half2_rn(uu[c2], ww[c2]);
        }
    }
}

// ---- fp16 k-major 64x64 V chunk: split ldg / sts (PRMT interleave) ----
__device__ __forceinline__ void ldgV(uint4& u, uint4& w, const __half* __restrict__ src,
                                     int tid) {
    int k2 = tid >> 3, n8 = tid & 7;
    int k = k2*2;
    u = *(const uint4*)(src + (size_t)k*DHD + n8*8);
    w = *(const uint4*)(src + (size_t)(k+1)*DHD + n8*8);
}
__device__ __forceinline__ void stsV(__half2* dst, const uint4 u, const uint4 w, int tid) {
    int k2 = tid >> 3, n8 = tid & 7;
    int k = k2*2;
    int ks = k >> 4, kl = (k & 7) >> 1, reg = (k >> 3) & 1;
    const unsigned* ua = (const unsigned*)&u;
    const unsigned* wa = (const unsigned*)&w;
    unsigned* d = (unsigned*)dst;
    #pragma unroll
    for (int c = 0; c < 4; c++) {
        unsigned lo, hi;
        asm("prmt.b32 %0, %1, %2, 0x5410;" : "=r"(lo) : "r"(ua[c]), "r"(wa[c]));
        asm("prmt.b32 %0, %1, %2, 0x7632;" : "=r"(hi) : "r"(ua[c]), "r"(wa[c]));
        int nlo = c*2, nhi = c*2 + 1;
        d[((ks*8 + n8)*32 + nlo*4 + kl)*2 + reg] = lo;
        d[((ks*8 + n8)*32 + nhi*4 + kl)*2 + reg] = hi;
    }
}

// ---- 128x128x64 pass, 8 warps (warp tile 32x64) ----
__device__ __forceinline__ void gemm64h(const __half2* __restrict__ Af,
                                        const __half2* __restrict__ Bf,
                                        int wm, int wn, int lane, float bacc[2][8][4]) {
    const uint4* A4 = (const uint4*)Af;
    const uint2* B2 = (const uint2*)Bf;
    #pragma unroll
    for (int ks = 0; ks < 4; ks++) {
        uint4 a0 = A4[(ks*8 + wm*2 + 0)*32 + lane];
        uint4 a1 = A4[(ks*8 + wm*2 + 1)*32 + lane];
        #pragma unroll
        for (int j = 0; j < 8; j++) {
            uint2 b = B2[(ks*16 + wn*8 + j)*32 + lane];
            mma16(bacc[0][j], a0, b);
            mma16(bacc[1][j], a1, b);
        }
    }
}

// ---- 128x64x64 pass, 8 warps ----
__device__ __forceinline__ void gemm64n64h(const __half2* __restrict__ Af,
                                           const __half2* __restrict__ Bf,
                                           int wid, int lane, float acc[8][4]) {
    const uint4* A4 = (const uint4*)Af;
    const uint2* B2 = (const uint2*)Bf;
    #pragma unroll
    for (int ks = 0; ks < 4; ks++) {
        uint4 a = A4[(ks*8 + wid)*32 + lane];
        #pragma unroll
        for (int j = 0; j < 8; j++) {
            uint2 b = B2[(ks*8 + j)*32 + lane];
            mma16(acc[j], a, b);
        }
    }
}

// ---- 64x64x64 pass, 8 warps (warp tile 16x32), MT=4, NT=8 ----
__device__ __forceinline__ void gemm6464h(const __half2* __restrict__ Af,
                                          const __half2* __restrict__ Bf,
                                          int wm, int wn, int lane, float acc[4][4]) {
    const uint4* A4 = (const uint4*)Af;
    const uint2* B2 = (const uint2*)Bf;
    #pragma unroll
    for (int ks = 0; ks < 4; ks++) {
        uint4 a = A4[(ks*4 + wm)*32 + lane];
        #pragma unroll
        for (int j = 0; j < 4; j++) {
            uint2 b = B2[(ks*8 + wn*4 + j)*32 + lane];
            mma16(acc[j], a, b);
        }
    }
}

// ---- 128x128x64 pass, 16 warps (warp tile 32x32) ----
__device__ __forceinline__ void gemm32h(const __half2* __restrict__ Af,
                                        const __half2* __restrict__ Bf,
                                        int wm, int wn, int lane, float bacc[2][4][4]) {
    const uint4* A4 = (const uint4*)Af;
    const uint2* B2 = (const uint2*)Bf;
    #pragma unroll
    for (int ks = 0; ks < 4; ks++) {
        uint4 a0 = A4[(ks*8 + wm*2 + 0)*32 + lane];
        uint4 a1 = A4[(ks*8 + wm*2 + 1)*32 + lane];
        #pragma unroll
        for (int j = 0; j < 4; j++) {
            uint2 b = B2[(ks*16 + wn*4 + j)*32 + lane];
            mma16(bacc[0][j], a0, b);
            mma16(bacc[1][j], a1, b);
        }
    }
}

__device__ __forceinline__ void zero32(float a[2][4][4]) {
    #pragma unroll
    for (int i = 0; i < 2; i++)
        #pragma unroll
        for (int j = 0; j < 4; j++)
            #pragma unroll
            for (int c = 0; c < 4; c++) a[i][j][c] = 0.f;
}

// ============================================================
// K1: QKV projection (fp16 mma, 256 thr); fp16 [l][dh] outputs
// ============================================================
__global__ __launch_bounds__(256) void qkv_kernel(
    const float* __restrict__ hidden,
    const float* __restrict__ Wq, const float* __restrict__ bq,
    const float* __restrict__ Wk, const float* __restrict__ bk,
    const float* __restrict__ Wv, const float* __restrict__ bv)
{
    extern __shared__ __align__(16) char smraw[];
    __half2* Af = (__half2*)smraw;
    __half2* Bf = (__half2*)(smraw + 16384);

    const int mat = blockIdx.z;
    const float* W    = (mat==0) ? Wq : (mat==1 ? Wk : Wv);
    const float* bias = (mat==0) ? bq : (mat==1 ? bk : bv);
    __half* outp      = (mat==0) ? g_q : (mat==1 ? g_k : g_v);

    const int n0 = blockIdx.x * 128;
    const int m0 = blockIdx.y * 128;
    const int tid = threadIdx.x, lane = tid & 31, wid = tid >> 5;
    const int wm = wid & 3, wn = wid >> 2;

    float acc[2][8][4];
    #pragma unroll
    for (int i = 0; i < 2; i++)
        #pragma unroll
        for (int j = 0; j < 8; j++)
            #pragma unroll
            for (int c = 0; c < 4; c++) acc[i][j][c] = 0.f;

    for (int kc0 = 0; kc0 < DD; kc0 += 64) {
        stageAh(Af, hidden + (size_t)m0*DD + kc0, DD, tid);
        stageBTh<128>(Bf, W + (size_t)kc0*DD + n0, DD, tid);
        __syncthreads();
        gemm64h(Af, Bf, wm, wn, lane, acc);
        __syncthreads();
    }

    const int r0 = wm*32 + (lane >> 2);
    const int c0 = wn*64 + (lane & 3)*2;
    #pragma unroll
    for (int i = 0; i < 2; i++)
        #pragma unroll
        for (int j = 0; j < 8; j++) {
            int cg = n0 + c0 + j*8;
            int h = cg >> 6, dh = cg & 63;
            float2 bb = *(const float2*)(bias + cg);
            #pragma unroll
            for (int half = 0; half < 2; half++) {
                int rg = m0 + r0 + i*16 + half*8;
                int b = rg >> 10, l = rg & 1023;
                *(__half2*)&outp[((size_t)((b*HH + h)*LL + l))*DHD + dh] =
                    __floats2half2_rn(acc[i][j][half*2+0] + bb.x,
                                      acc[i][j][half*2+1] + bb.y);
            }
        }
}

// ============================================================
// K1b: qw precompute (fp16 mma, 256 thr); half in, half out
// ============================================================
__global__ __launch_bounds__(256) void qw_kernel(const float* __restrict__ ssw)
{
    extern __shared__ __align__(16) char smraw[];
    __half2* Af = (__half2*)smraw;
    __half2* Bf = (__half2*)(smraw + 16384);

    const int i5 = blockIdx.z;
    const int bh = blockIdx.y;
    const int h  = bh % HH;
    const int m0 = blockIdx.x * 128;
    const int tid = threadIdx.x, lane = tid & 31, wid = tid >> 5;

    uint4 vH[4];
    ldgH<4,256>(vH, g_q + (size_t)(bh*LL + m0)*DHD, DHD, tid);
    stsAhH<4,256>(Af, vH, tid);
    stageBTh<64>(Bf, ssw + (size_t)(i5*HH + h)*DHD*DHD, DHD, tid);
    __syncthreads();

    float acc[8][4];
    #pragma unroll
    for (int j = 0; j < 8; j++)
        #pragma unroll
        for (int c = 0; c < 4; c++) acc[j][c] = 0.f;

    gemm64n64h(Af, Bf, wid, lane, acc);

    __half* ob = g_qw + ((size_t)(i5*BHN + bh)*LL + m0)*DHD;
    const int r0 = wid*16 + (lane >> 2);
    const int c0 = (lane & 3)*2;
    #pragma unroll
    for (int j = 0; j < 8; j++) {
        int cc = c0 + j*8;
        *(__half2*)(ob + (size_t)r0*DHD + cc)     = __floats2half2_rn(acc[j][0], acc[j][1]);
        *(__half2*)(ob + (size_t)(r0+8)*DHD + cc) = __floats2half2_rn(acc[j][2], acc[j][3]);
    }
}

// ============================================================
// K2: fused scores — shear-on-write + TRIANGULAR WARP SKIPPING
// in positional phase (out-of-band 32x32 warp tiles do no work).
// smem: Q|Kb|Ka|E0|E1 (16K ea) + bufQ/bufK (128x136 fp16 ea) = 151552
// ============================================================
#define SC_SMEM 151552

__global__ __launch_bounds__(512, 1) void scores_kernel(
    const float* __restrict__ mask,
    const float* __restrict__ structm,
    const float* __restrict__ dist,
    const float* __restrict__ abv)
{
    extern __shared__ __align__(16) char smraw[];
    __half2* Q   = (__half2*)smraw;
    __half2* Kb  = (__half2*)(smraw + 16384);
    __half2* Ka  = (__half2*)(smraw + 32768);
    __half2* E0  = (__half2*)(smraw + 49152);
    __half2* E1  = (__half2*)(smraw + 65536);
    __half* bufQ = (__half*)(smraw + 81920);    // [128][136]
    __half* bufK = (__half*)(smraw + 116736);   // [128][136]

    const int bh = blockIdx.x, kt = blockIdx.y, qt = blockIdx.z;
    const int b = bh / HH, h = bh % HH;
    const int m0 = qt*128, n0 = kt*128;
    const int tid = threadIdx.x, lane = tid & 31, wid = tid >> 5;
    const int wm = wid & 3, wn = wid >> 2;
    const int r0 = wm*32 + (lane >> 2);
    const int c0 = wn*32 + (lane & 3)*2;

    const int base = (qt - kt)*128 + 896;
    int nv1 = 1919 - base; if (nv1 > 128) nv1 = 128;

    const __half* qwbase = g_qw + ((size_t)bh*LL + m0)*DHD;
    const size_t qwstr = (size_t)BHN*LL*DHD;

    uint4 vq[2], vk[2], vH[2];
    float4 vA[4], vB[4];
    ldgH<2,512>(vq, g_q + (size_t)(bh*LL + m0)*DHD, DHD, tid);
    ldgH<2,512>(vk, g_k + (size_t)(bh*LL + n0)*DHD, DHD, tid);
    stsAhH<2,512>(Q, vq, tid);
    stsAhH<2,512>(Ka, vk, tid);
    stsBhH<2,512,16>(Kb, vk, tid);
    ldgT4<4,512>(vA, dist + (size_t)base*DHD, DHD, tid, 128);
    stsBh<4,512>(E0, vA, tid);
    ldgT4<4,512>(vB, dist + (size_t)(base + 128)*DHD, DHD, tid, nv1);
    stsBh<4,512>(E1, vB, tid);
    ldgH<2,512>(vH, qwbase, DHD, tid);          // qw0 prefetch
    __syncthreads();

    float acc[2][4][4];
    float bacc[2][4][4];
    zero32(acc);

    // shear-write: QE element (R, Jcol) contributes at C = R - (Jcol+128h) + 127
    auto shearQE = [&](int h128) {
        #pragma unroll
        for (int i = 0; i < 2; i++)
            #pragma unroll
            for (int j = 0; j < 4; j++)
                #pragma unroll
                for (int c2 = 0; c2 < 4; c2++) {
                    int R    = r0 + i*16 + (c2 >> 1)*8;
                    int Jcol = c0 + j*8 + (c2 & 1);
                    int C = R - Jcol + 127 - h128;
                    if ((unsigned)C < 128u)
                        bufQ[R*136 + C] = __float2half(bacc[i][j][c2]);
                }
    };
    // shear-write: KE element (rowK, Jcol) contributes at R = rowK + Jcol + 128h - 127
    auto shearKE = [&](int h128) {
        #pragma unroll
        for (int i = 0; i < 2; i++)
            #pragma unroll
            for (int j = 0; j < 4; j++)
                #pragma unroll
                for (int c2 = 0; c2 < 4; c2++) {
                    int rowK = r0 + i*16 + (c2 >> 1)*8;
                    int Jcol = c0 + j*8 + (c2 & 1);
                    int R = rowK + Jcol + h128 - 127;
                    if ((unsigned)R < 128u)
                        bufK[R*136 + rowK] = __float2half(bacc[i][j][c2]);
                }
    };

    // ---- positional phase: triangular warp-tile skipping ----
    // QE half0 in-band iff exists J>=R in tile      -> wn >= wm
    // QE half1 in-band iff exists J<=R-1 in tile    -> wn <= wm
    // KE half0 in-band iff exists rowK+J >= 127     -> wm+wn >= 3
    // KE half1 in-band iff exists rowK+J <= 126     -> wm+wn <= 3
    if (wm + wn >= 3) { zero32(bacc); gemm32h(Ka, E0, wm, wn, lane, bacc); shearKE(0);   }
    if (wm + wn <= 3) { zero32(bacc); gemm32h(Ka, E1, wm, wn, lane, bacc); shearKE(128); }
    if (wn >= wm)     { zero32(bacc); gemm32h(Q,  E0, wm, wn, lane, bacc); shearQE(0);   }
    if (wn <= wm)     { zero32(bacc); gemm32h(Q,  E1, wm, wn, lane, bacc); shearQE(128); }
    __syncthreads();

    // ---- stage qw0 (held in vH) -> E0 FIRST, then prefetch qw1 ----
    stsAhH<2,512>(E0, vH, tid);                 // qw0 -> E0 (E0 free after positional)
    ldgH<2,512>(vH, qwbase + qwstr, DHD, tid);  // qw1

    // ---- coalesced read-add of both positional terms ----
    #pragma unroll
    for (int i = 0; i < 2; i++)
        #pragma unroll
        for (int hh = 0; hh < 2; hh++) {
            int rr = r0 + i*16 + hh*8;
            #pragma unroll
            for (int j = 0; j < 4; j++) {
                int cc = c0 + j*8;
                __half2 a = *(const __half2*)(bufQ + rr*136 + cc);
                __half2 bvl = *(const __half2*)(bufK + rr*136 + cc);
                float2 af = __half22float2(a);
                float2 bf = __half22float2(bvl);
                acc[i][j][hh*2+0] += af.x + bf.x;
                acc[i][j][hh*2+1] += af.y + bf.y;
            }
        }

    // ---- QK pass: gemm(Q,Kb); scale + mask ----
    float2 mk[4];
    {
        const float* mrow = mask + b*LL + n0;
        #pragma unroll
        for (int j = 0; j < 4; j++) mk[j] = *(const float2*)(mrow + c0 + j*8);
    }
    zero32(bacc); gemm32h(Q, Kb, wm, wn, lane, bacc);
    #pragma unroll
    for (int j = 0; j < 4; j++)
        #pragma unroll
        for (int i = 0; i < 2; i++) {
            acc[i][j][0] = (acc[i][j][0] + bacc[i][j][0])*0.125f + mk[j].x;
            acc[i][j][1] = (acc[i][j][1] + bacc[i][j][1])*0.125f + mk[j].y;
            acc[i][j][2] = (acc[i][j][2] + bacc[i][j][2])*0.125f + mk[j].x;
            acc[i][j][3] = (acc[i][j][3] + bacc[i][j][3])*0.125f + mk[j].y;
        }
    __syncthreads();

    // bilinear passes: qw0=E0, qw1=E1, qw2=Q, qw3=Ka, qw4=E0(again)
    float2 sv[8];
    float  ab;
    auto structPre = [&](int i5) {
        ab = __ldg(&abv[i5*HH + h]);
        const float* stb = structm + (((size_t)(i5*BB + b)*LL + m0)*LL) + n0;
        #pragma unroll
        for (int j = 0; j < 4; j++) {
            sv[j*2+0] = *(const float2*)(stb + (size_t)r0*LL + c0 + j*8);
            sv[j*2+1] = *(const float2*)(stb + (size_t)(r0+8)*LL + c0 + j*8);
        }
    };
    auto structEpi = [&](int i5) {
        #pragma unroll
        for (int j = 0; j < 4; j++) {
            acc[0][j][0] += (bacc[0][j][0] + ab)*sv[j*2+0].x;
            acc[0][j][1] += (bacc[0][j][1] + ab)*sv[j*2+0].y;
            acc[0][j][2] += (bacc[0][j][2] + ab)*sv[j*2+1].x;
            acc[0][j][3] += (bacc[0][j][3] + ab)*sv[j*2+1].y;
        }
        const float* stb = structm + (((size_t)(i5*BB + b)*LL + m0)*LL) + n0;
        #pragma unroll
        for (int j = 0; j < 4; j++) {
            float2 s0 = *(const float2*)(stb + (size_t)(r0+16)*LL + c0 + j*8);
            float2 s1 = *(const float2*)(stb + (size_t)(r0+24)*LL + c0 + j*8);
            acc[1][j][0] += (bacc[1][j][0] + ab)*s0.x;
            acc[1][j][1] += (bacc[1][j][1] + ab)*s0.y;
            acc[1][j][2] += (bacc[1][j][2] + ab)*s1.x;
            acc[1][j][3] += (bacc[1][j][3] + ab)*s1.y;
        }
    };

    // B1: bilinear0 (E0=qw0); stage qw1->E1; ldg qw2
    structPre(0);
    zero32(bacc); gemm32h(E0, Kb, wm, wn, lane, bacc);
    structEpi(0);
    stsAhH<2,512>(E1, vH, tid);
    ldgH<2,512>(vH, qwbase + 2*qwstr, DHD, tid);
    __syncthreads();

    // B2: bilinear1 (E1=qw1); stage qw2->Q; ldg qw3
    structPre(1);
    zero32(bacc); gemm32h(E1, Kb, wm, wn, lane, bacc);
    structEpi(1);
    stsAhH<2,512>(Q, vH, tid);
    ldgH<2,512>(vH, qwbase + 3*qwstr, DHD, tid);
    __syncthreads();

    // B3: bilinear2 (Q=qw2); stage qw3->Ka; ldg qw4
    structPre(2);
    zero32(bacc); gemm32h(Q, Kb, wm, wn, lane, bacc);
    structEpi(2);
    stsAhH<2,512>(Ka, vH, tid);
    ldgH<2,512>(vH, qwbase + 4*qwstr, DHD, tid);
    __syncthreads();

    // B4: bilinear3 (Ka=qw3); stage qw4->E0
    structPre(3);
    zero32(bacc); gemm32h(Ka, Kb, wm, wn, lane, bacc);
    structEpi(3);
    stsAhH<2,512>(E0, vH, tid);
    __syncthreads();

    // B5: bilinear4 (E0=qw4)
    structPre(4);
    zero32(bacc); gemm32h(E0, Kb, wm, wn, lane, bacc);
    structEpi(4);

    // store scores
    float* sp = g_s + ((size_t)bh*LL + m0)*LL + n0;
    #pragma unroll
    for (int i = 0; i < 2; i++)
        #pragma unroll
        for (int j = 0; j < 4; j++) {
            int rr = r0 + i*16, cc = c0 + j*8;
            *(float2*)(sp + (size_t)rr*LL + cc)     = make_float2(acc[i][j][0], acc[i][j][1]);
            *(float2*)(sp + (size_t)(rr+8)*LL + cc) = make_float2(acc[i][j][2], acc[i][j][3]);
        }

    // ---- per-wn partial row stats: registers + quad shuffles only ----
    float rm[4], rs[4];
    #pragma unroll
    for (int ridx = 0; ridx < 4; ridx++) {
        int i = ridx >> 1, hh = ridx & 1;
        float m = acc[i][0][hh*2+0];
        #pragma unroll
        for (int j = 0; j < 4; j++) {
            m = fmaxf(m, acc[i][j][hh*2+0]);
            m = fmaxf(m, acc[i][j][hh*2+1]);
        }
        rm[ridx] = m;
    }
    #pragma unroll
    for (int o = 1; o <= 2; o <<= 1)
        #pragma unroll
        for (int r = 0; r < 4; r++)
            rm[r] = fmaxf(rm[r], __shfl_xor_sync(0xffffffffu, rm[r], o));
    #pragma unroll
    for (int ridx = 0; ridx < 4; ridx++) {
        int i = ridx >> 1, hh = ridx & 1;
        float s = 0.f;
        #pragma unroll
        for (int j = 0; j < 4; j++) {
            s += __expf(acc[i][j][hh*2+0] - rm[ridx]);
            s += __expf(acc[i][j][hh*2+1] - rm[ridx]);
        }
        rs[ridx] = s;
    }
    #pragma unroll
    for (int o = 1; o <= 2; o <<= 1)
        #pragma unroll
        for (int r = 0; r < 4; r++)
            rs[r] += __shfl_xor_sync(0xffffffffu, rs[r], o);
    if ((lane & 3) == 0) {
        #pragma unroll
        for (int r = 0; r < 4; r++) {
            int row = r0 + (r >> 1)*16 + (r & 1)*8;
            int gi = ((((bh*8 + kt)*4) + wn) << 10) + m0 + row;
            g_pm[gi] = rm[r];
            g_ps[gi] = rs[r];
        }
    }
}

// ============================================================
// K4: ctx = softmax(scores) @ v — 64-row tiles, double-buffered
// grid (16, 24), 256 thr. smem: 2x(A 8K + B 8K) + stats 512B
// ============================================================
#define PV_SMEM 33536

__global__ __launch_bounds__(256) void pv_kernel(float* __restrict__ out)
{
    extern __shared__ __align__(16) char smraw[];
    __half2* Abuf[2] = { (__half2*)smraw,           (__half2*)(smraw + 16384) };
    __half2* Bbuf[2] = { (__half2*)(smraw + 8192),  (__half2*)(smraw + 24576) };
    float* sm_m   = (float*)(smraw + 32768);
    float* sm_inv = (float*)(smraw + 33024);

    const int bh = blockIdx.y;
    const int b = bh / HH, h = bh % HH;
    const int m0 = blockIdx.x * 64;
    const int tid = threadIdx.x, lane = tid & 31, wid = tid >> 5;
    const int wm = wid & 3, wn = wid >> 2;

    if (tid < 64) {
        float m = -1e30f;
        #pragma unroll
        for (int p = 0; p < 32; p++) {
            int gi = (((bh*8 + (p >> 2))*4 + (p & 3)) << 10) + m0 + tid;
            m = fmaxf(m, g_pm[gi]);
        }
        float s = 0.f;
        #pragma unroll
        for (int p = 0; p < 32; p++) {
            int gi = (((bh*8 + (p >> 2))*4 + (p & 3)) << 10) + m0 + tid;
            s += g_ps[gi]*__expf(g_pm[gi] - m);
        }
        sm_m[tid]   = m;
        sm_inv[tid] = 1.f / s;
    }
    __syncthreads();

    const float* pb = g_s + (size_t)bh*LL*LL + (size_t)m0*LL;
    const __half* vb = g_v + (size_t)bh*LL*DHD;

    float acc[4][4];
    #pragma unroll
    for (int j = 0; j < 4; j++)
        #pragma unroll
        for (int c = 0; c < 4; c++) acc[j][c] = 0.f;

    float4 rA[4];
    uint4 rU, rW;

    auto ldExpA = [&](int kc0) {
        ldgT4<4,256>(rA, pb + kc0, LL, tid, 64);
        #pragma unroll
        for (int it = 0; it < 4; it++) {
            int m = (tid + it*256) >> 4;
            float mm = sm_m[m];
            rA[it].x = __expf(rA[it].x - mm);
            rA[it].y = __expf(rA[it].y - mm);
            rA[it].z = __expf(rA[it].z - mm);
            rA[it].w = __expf(rA[it].w - mm);
        }
    };

    // prologue: chunk 0 staged, chunk 1 in regs
    ldExpA(0);
    ldgV(rU, rW, vb, tid);
    stsAh<4,256,4>(Abuf[0], rA, tid);
    stsV(Bbuf[0], rU, rW, tid);
    ldExpA(64);
    ldgV(rU, rW, vb + (size_t)64*DHD, tid);
    __syncthreads();

    for (int c = 0; c < 16; c++) {
        int cur = c & 1;
        if (c < 15) {
            stsAh<4,256,4>(Abuf[1-cur], rA, tid);
            stsV(Bbuf[1-cur], rU, rW, tid);
        }
        if (c < 14) {
            ldExpA((c+2)*64);
            ldgV(rU, rW, vb + (size_t)(c+2)*64*DHD, tid);
        }
        gemm6464h(Abuf[cur], Bbuf[cur], wm, wn, lane, acc);
        __syncthreads();
    }

    const int r0 = wm*16 + (lane >> 2);
    const int c0 = wn*32 + (lane & 3)*2;
    const float inv0 = sm_inv[r0];
    const float inv1 = sm_inv[r0 + 8];
    #pragma unroll
    for (int j = 0; j < 4; j++) {
        int cc = c0 + j*8;
        int l0 = m0 + r0;
        *(float2*)&out[((size_t)b*LL + l0)*DD + h*DHD + cc] =
            make_float2(acc[j][0]*inv0, acc[j][1]*inv0);
        *(float2*)&out[((size_t)b*LL + l0 + 8)*DD + h*DHD + cc] =
            make_float2(acc[j][2]*inv1, acc[j][3]*inv1);
    }
}

// ============================================================
extern "C" void kernel_launch(void* const* d_in, const int* in_sizes, int n_in,
                              void* d_out, int out_size)
{
    const float* hidden  = (const float*)d_in[0];
    const float* mask    = (const float*)d_in[1];
    const float* structm = (const float*)d_in[2];
    const float* Wq      = (const float*)d_in[3];
    const float* bq      = (const float*)d_in[4];
    const float* Wk      = (const float*)d_in[5];
    const float* bk      = (const float*)d_in[6];
    const float* Wv      = (const float*)d_in[7];
    const float* bv      = (const float*)d_in[8];
    const float* dist    = (const float*)d_in[9];
    const float* ssw     = (const float*)d_in[10];
    const float* abv     = (const float*)d_in[11];
    float* out = (float*)d_out;

    cudaFuncSetAttribute(qkv_kernel,    cudaFuncAttributeMaxDynamicSharedMemorySize, 32768);
    cudaFuncSetAttribute(qw_kernel,     cudaFuncAttributeMaxDynamicSharedMemorySize, 24576);
    cudaFuncSetAttribute(pv_kernel,     cudaFuncAttributeMaxDynamicSharedMemorySize, PV_SMEM);
    cudaFuncSetAttribute(scores_kernel, cudaFuncAttributeMaxDynamicSharedMemorySize, SC_SMEM);

    qkv_kernel    <<<dim3(6,16,3),  256, 32768>>>(hidden, Wq,bq, Wk,bk, Wv,bv);
    qw_kernel     <<<dim3(8,24,5),  256, 24576>>>(ssw);
    scores_kernel <<<dim3(24,8,8),  512, SC_SMEM>>>(mask, structm, dist, abv);
    pv_kernel     <<<dim3(16,24),   256, PV_SMEM>>>(out);
}

// round 14
// speedup vs baseline: 1.1949x; 1.0085x over previous
#include <cuda_runtime.h>
#include <cuda_fp16.h>
#include <cstdint>

#define BB  2
#define LL  1024
#define DD  768
#define HH  12
#define DHD 64
#define BHN (BB*HH)

// ---- scratch ----
__device__ __half g_q [BHN*LL*DHD];            // [bh][l][dh] fp16
__device__ __half g_k [BHN*LL*DHD];            // [bh][l][dh] fp16
__device__ __half g_v [BHN*LL*DHD];            // [bh][l][dh] fp16
__device__ __half g_qw[5*BHN*LL*DHD];          // [i][bh][l][dh] fp16
__device__ float  g_s [(size_t)BHN*LL*LL];     // scores fp32
__device__ float  g_pm[BHN*8*4*LL];            // partial row max  [bh][kt][wn][l]
__device__ float  g_ps[BHN*8*4*LL];            // partial row sumexp

// ============================================================
// fp16 mma helpers (m16n8k16, f32 accum)
// ============================================================
__device__ __forceinline__ void mma16(float* c, const uint4 a, const uint2 b) {
    asm volatile(
        "mma.sync.aligned.m16n8k16.row.col.f32.f16.f16.f32 "
        "{%0,%1,%2,%3}, {%4,%5,%6,%7}, {%8,%9}, {%0,%1,%2,%3};"
        : "+f"(c[0]), "+f"(c[1]), "+f"(c[2]), "+f"(c[3])
        : "r"(a.x), "r"(a.y), "r"(a.z), "r"(a.w), "r"(b.x), "r"(b.y));
}

// ---- f32 register-tile loaders (row-major, row stride ld) ----
template<int ITERS, int TPB>
__device__ __forceinline__ void ldgT4(float4* v, const float* __restrict__ src,
                                      int ld, int tid, int nvalid) {
    #pragma unroll
    for (int it = 0; it < ITERS; it++) {
        int idx = tid + it*TPB;
        int m = idx >> 4, k4 = idx & 15;
        v[it] = (m < nvalid) ? *(const float4*)(src + (size_t)m*ld + k4*4)
                             : make_float4(0.f, 0.f, 0.f, 0.f);
    }
}

// ---- fp16 register-tile loader: each item = 8 halfs (m, k0..k0+7) ----
template<int ITERS, int TPB>
__device__ __forceinline__ void ldgH(uint4* v, const __half* __restrict__ src,
                                     int ld, int tid) {
    #pragma unroll
    for (int it = 0; it < ITERS; it++) {
        int idx = tid + it*TPB;
        int m = idx >> 3, k8 = idx & 7;
        v[it] = *(const uint4*)(src + (size_t)m*ld + k8*8);
    }
}

// ---- STS to A-fragment fp16 layout from f32 regs (MT m-tiles) ----
template<int ITERS, int TPB, int MT>
__device__ __forceinline__ void stsAh(__half2* dst, const float4* v, int tid) {
    #pragma unroll
    for (int it = 0; it < ITERS; it++) {
        int idx = tid + it*TPB;
        int m = idx >> 4, k4 = idx & 15;
        int mt = m >> 4, r = m & 15;
        int rbit = r >> 3, rlow = r & 7;
        {
            int k = k4*4;
            int ku = k & 15, ks = k >> 4, khigh = ku >> 3, kpair = (ku >> 1) & 3;
            dst[((ks*MT + mt)*32 + rlow*4 + kpair)*4 + rbit + 2*khigh] =
                __floats2half2_rn(v[it].x, v[it].y);
        }
        {
            int k = k4*4 + 2;
            int ku = k & 15, ks = k >> 4, khigh = ku >> 3, kpair = (ku >> 1) & 3;
            dst[((ks*MT + mt)*32 + rlow*4 + kpair)*4 + rbit + 2*khigh] =
                __floats2half2_rn(v[it].z, v[it].w);
        }
    }
}

// ---- STS to A-fragment from fp16 regs (no cvt, MT=8) ----
template<int ITERS, int TPB>
__device__ __forceinline__ void stsAhH(__half2* dst, const uint4* v, int tid) {
    #pragma unroll
    for (int it = 0; it < ITERS; it++) {
        int idx = tid + it*TPB;
        int m = idx >> 3, k0 = (idx & 7)*8;
        int mt = m >> 4, r = m & 15;
        int rbit = r >> 3, rlow = r & 7;
        int ks = k0 >> 4, khigh = (k0 >> 3) & 1;
        int base = ((ks*8 + mt)*32 + rlow*4)*4 + rbit + 2*khigh;
        const __half2* p = (const __half2*)&v[it];
        dst[base + 0]  = p[0];
        dst[base + 4]  = p[1];
        dst[base + 8]  = p[2];
        dst[base + 12] = p[3];
    }
}

// ---- STS to B-fragment (NT = N/8) from fp16 regs, n-major source ----
template<int ITERS, int TPB, int NT>
__device__ __forceinline__ void stsBhH(__half2* dst, const uint4* v, int tid) {
    #pragma unroll
    for (int it = 0; it < ITERS; it++) {
        int idx = tid + it*TPB;
        int n = idx >> 3, k0 = (idx & 7)*8;
        int nt = n >> 3, nlow = n & 7;
        int ks = k0 >> 4, reg = (k0 >> 3) & 1;
        int base = ((ks*NT + nt)*32 + nlow*4)*2 + reg;
        const __half2* p = (const __half2*)&v[it];
        dst[base + 0] = p[0];
        dst[base + 2] = p[1];
        dst[base + 4] = p[2];
        dst[base + 6] = p[3];
    }
}

// ---- STS to B-fragment (NT=16) from f32 n-major regs (for dist E bands) ----
template<int ITERS, int TPB>
__device__ __forceinline__ void stsBh(__half2* dst, const float4* v, int tid) {
    #pragma unroll
    for (int it = 0; it < ITERS; it++) {
        int idx = tid + it*TPB;
        int n = idx >> 4, k4 = idx & 15;
        int nt = n >> 3, nlow = n & 7;
        {
            int k = k4*4;
            int ku = k & 15, ks = k >> 4;
            dst[((ks*16 + nt)*32 + nlow*4 + ((ku & 7) >> 1))*2 + (ku >> 3)] =
                __floats2half2_rn(v[it].x, v[it].y);
        }
        {
            int k = k4*4 + 2;
            int ku = k & 15, ks = k >> 4;
            dst[((ks*16 + nt)*32 + nlow*4 + ((ku & 7) >> 1))*2 + (ku >> 3)] =
                __floats2half2_rn(v[it].z, v[it].w);
        }
    }
}

// ---- fused stage: f32 row-major 128x64 -> A-frag (256 threads) ----
__device__ __forceinline__ void stageAh(__half2* dst, const float* __restrict__ src,
                                        int ld, int tid) {
    float4 v[8];
    ldgT4<8,256>(v, src, ld, tid, 128);
    stsAh<8,256,8>(dst, v, tid);
}

// ---- fused stage: f32 k-major 64xN (stride ldn) -> B-frag (256 thr) ----
template<int N>
__device__ __forceinline__ void stageBTh(__half2* dst, const float* __restrict__ src,
                                         int ldn, int tid) {
    constexpr int NT = N / 8;
    constexpr int F4 = N / 4;
    constexpr int ITEMS = 32 * F4;
    #pragma unroll
    for (int it = 0; it < ITEMS/256; it++) {
        int idx = tid + it*256;
        int k2 = idx / F4, nq = idx % F4;
        int k = k2*2;
        float4 u = *(const float4*)(src + (size_t)k*ldn + nq*4);
        float4 w = *(const float4*)(src + (size_t)(k+1)*ldn + nq*4);
        int ku = k & 15, ks = k >> 4, reg = ku >> 3;
        int kl = (ku & 7) >> 1;
        float uu[4] = {u.x,u.y,u.z,u.w};
        float ww[4] = {w.x,w.y,w.z,w.w};
        #pragma unroll
        for (int c2 = 0; c2 < 4; c2++) {
            int n = nq*4 + c2;
            int nt = n >> 3;
            dst[((ks*NT + nt)*32 + (n & 7)*4 + kl)*2 + reg] =
                __floats2half2_rn(uu[c2], ww[c2]);
        }
    }
}

// ---- fp16 k-major 64x64 V chunk: split ldg / sts (PRMT interleave) ----
__device__ __forceinline__ void ldgV(uint4& u, uint4& w, const __half* __restrict__ src,
                                     int tid) {
    int k2 = tid >> 3, n8 = tid & 7;
    int k = k2*2;
    u = *(const uint4*)(src + (size_t)k*DHD + n8*8);
    w = *(const uint4*)(src + (size_t)(k+1)*DHD + n8*8);
}
__device__ __forceinline__ void stsV(__half2* dst, const uint4 u, const uint4 w, int tid) {
    int k2 = tid >> 3, n8 = tid & 7;
    int k = k2*2;
    int ks = k >> 4, kl = (k & 7) >> 1, reg = (k >> 3) & 1;
    const unsigned* ua = (const unsigned*)&u;
    const unsigned* wa = (const unsigned*)&w;
    unsigned* d = (unsigned*)dst;
    #pragma unroll
    for (int c = 0; c < 4; c++) {
        unsigned lo, hi;
        asm("prmt.b32 %0, %1, %2, 0x5410;" : "=r"(lo) : "r"(ua[c]), "r"(wa[c]));
        asm("prmt.b32 %0, %1, %2, 0x7632;" : "=r"(hi) : "r"(ua[c]), "r"(wa[c]));
        int nlo = c*2, nhi = c*2 + 1;
        d[((ks*8 + n8)*32 + nlo*4 + kl)*2 + reg] = lo;
        d[((ks*8 + n8)*32 + nhi*4 + kl)*2 + reg] = hi;
    }
}

// ---- 128x128x64 pass, 8 warps (warp tile 32x64) ----
__device__ __forceinline__ void gemm64h(const __half2* __restrict__ Af,
                                        const __half2* __restrict__ Bf,
                                        int wm, int wn, int lane, float bacc[2][8][4]) {
    const uint4* A4 = (const uint4*)Af;
    const uint2* B2 = (const uint2*)Bf;
    #pragma unroll
    for (int ks = 0; ks < 4; ks++) {
        uint4 a0 = A4[(ks*8 + wm*2 + 0)*32 + lane];
        uint4 a1 = A4[(ks*8 + wm*2 + 1)*32 + lane];
        #pragma unroll
        for (int j = 0; j < 8; j++) {
            uint2 b = B2[(ks*16 + wn*8 + j)*32 + lane];
            mma16(bacc[0][j], a0, b);
            mma16(bacc[1][j], a1, b);
        }
    }
}

// ---- 128x64x64 pass, 8 warps ----
__device__ __forceinline__ void gemm64n64h(const __half2* __restrict__ Af,
                                           const __half2* __restrict__ Bf,
                                           int wid, int lane, float acc[8][4]) {
    const uint4* A4 = (const uint4*)Af;
    const uint2* B2 = (const uint2*)Bf;
    #pragma unroll
    for (int ks = 0; ks < 4; ks++) {
        uint4 a = A4[(ks*8 + wid)*32 + lane];
        #pragma unroll
        for (int j = 0; j < 8; j++) {
            uint2 b = B2[(ks*8 + j)*32 + lane];
            mma16(acc[j], a, b);
        }
    }
}

// ---- 64x64x64 pass, 8 warps (warp tile 16x32), MT=4, NT=8 ----
__device__ __forceinline__ void gemm6464h(const __half2* __restrict__ Af,
                                          const __half2* __restrict__ Bf,
                                          int wm, int wn, int lane, float acc[4][4]) {
    const uint4* A4 = (const uint4*)Af;
    const uint2* B2 = (const uint2*)Bf;
    #pragma unroll
    for (int ks = 0; ks < 4; ks++) {
        uint4 a = A4[(ks*4 + wm)*32 + lane];
        #pragma unroll
        for (int j = 0; j < 4; j++) {
            uint2 b = B2[(ks*8 + wn*4 + j)*32 + lane];
            mma16(acc[j], a, b);
        }
    }
}

// ---- 128x128x64 pass, 16 warps (warp tile 32x32) ----
__device__ __forceinline__ void gemm32h(const __half2* __restrict__ Af,
                                        const __half2* __restrict__ Bf,
                                        int wm, int wn, int lane, float bacc[2][4][4]) {
    const uint4* A4 = (const uint4*)Af;
    const uint2* B2 = (const uint2*)Bf;
    #pragma unroll
    for (int ks = 0; ks < 4; ks++) {
        uint4 a0 = A4[(ks*8 + wm*2 + 0)*32 + lane];
        uint4 a1 = A4[(ks*8 + wm*2 + 1)*32 + lane];
        #pragma unroll
        for (int j = 0; j < 4; j++) {
            uint2 b = B2[(ks*16 + wn*4 + j)*32 + lane];
            mma16(bacc[0][j], a0, b);
            mma16(bacc[1][j], a1, b);
        }
    }
}

__device__ __forceinline__ void zero32(float a[2][4][4]) {
    #pragma unroll
    for (int i = 0; i < 2; i++)
        #pragma unroll
        for (int j = 0; j < 4; j++)
            #pragma unroll
            for (int c = 0; c < 4; c++) a[i][j][c] = 0.f;
}

// ============================================================
// K1: QKV projection (fp16 mma, 256 thr); fp16 [l][dh] outputs
// ============================================================
__global__ __launch_bounds__(256) void qkv_kernel(
    const float* __restrict__ hidden,
    const float* __restrict__ Wq, const float* __restrict__ bq,
    const float* __restrict__ Wk, const float* __restrict__ bk,
    const float* __restrict__ Wv, const float* __restrict__ bv)
{
    extern __shared__ __align__(16) char smraw[];
    __half2* Af = (__half2*)smraw;
    __half2* Bf = (__half2*)(smraw + 16384);

    const int mat = blockIdx.z;
    const float* W    = (mat==0) ? Wq : (mat==1 ? Wk : Wv);
    const float* bias = (mat==0) ? bq : (mat==1 ? bk : bv);
    __half* outp      = (mat==0) ? g_q : (mat==1 ? g_k : g_v);

    const int n0 = blockIdx.x * 128;
    const int m0 = blockIdx.y * 128;
    const int tid = threadIdx.x, lane = tid & 31, wid = tid >> 5;
    const int wm = wid & 3, wn = wid >> 2;

    float acc[2][8][4];
    #pragma unroll
    for (int i = 0; i < 2; i++)
        #pragma unroll
        for (int j = 0; j < 8; j++)
            #pragma unroll
            for (int c = 0; c < 4; c++) acc[i][j][c] = 0.f;

    for (int kc0 = 0; kc0 < DD; kc0 += 64) {
        stageAh(Af, hidden + (size_t)m0*DD + kc0, DD, tid);
        stageBTh<128>(Bf, W + (size_t)kc0*DD + n0, DD, tid);
        __syncthreads();
        gemm64h(Af, Bf, wm, wn, lane, acc);
        __syncthreads();
    }

    const int r0 = wm*32 + (lane >> 2);
    const int c0 = wn*64 + (lane & 3)*2;
    #pragma unroll
    for (int i = 0; i < 2; i++)
        #pragma unroll
        for (int j = 0; j < 8; j++) {
            int cg = n0 + c0 + j*8;
            int h = cg >> 6, dh = cg & 63;
            float2 bb = *(const float2*)(bias + cg);
            #pragma unroll
            for (int half = 0; half < 2; half++) {
                int rg = m0 + r0 + i*16 + half*8;
                int b = rg >> 10, l = rg & 1023;
                *(__half2*)&outp[((size_t)((b*HH + h)*LL + l))*DHD + dh] =
                    __floats2half2_rn(acc[i][j][half*2+0] + bb.x,
                                      acc[i][j][half*2+1] + bb.y);
            }
        }
}

// ============================================================
// K1b: qw precompute (fp16 mma, 256 thr); half in, half out
// ============================================================
__global__ __launch_bounds__(256) void qw_kernel(const float* __restrict__ ssw)
{
    extern __shared__ __align__(16) char smraw[];
    __half2* Af = (__half2*)smraw;
    __half2* Bf = (__half2*)(smraw + 16384);

    const int i5 = blockIdx.z;
    const int bh = blockIdx.y;
    const int h  = bh % HH;
    const int m0 = blockIdx.x * 128;
    const int tid = threadIdx.x, lane = tid & 31, wid = tid >> 5;

    uint4 vH[4];
    ldgH<4,256>(vH, g_q + (size_t)(bh*LL + m0)*DHD, DHD, tid);
    stsAhH<4,256>(Af, vH, tid);
    stageBTh<64>(Bf, ssw + (size_t)(i5*HH + h)*DHD*DHD, DHD, tid);
    __syncthreads();

    float acc[8][4];
    #pragma unroll
    for (int j = 0; j < 8; j++)
        #pragma unroll
        for (int c = 0; c < 4; c++) acc[j][c] = 0.f;

    gemm64n64h(Af, Bf, wid, lane, acc);

    __half* ob = g_qw + ((size_t)(i5*BHN + bh)*LL + m0)*DHD;
    const int r0 = wid*16 + (lane >> 2);
    const int c0 = (lane & 3)*2;
    #pragma unroll
    for (int j = 0; j < 8; j++) {
        int cc = c0 + j*8;
        *(__half2*)(ob + (size_t)r0*DHD + cc)     = __floats2half2_rn(acc[j][0], acc[j][1]);
        *(__half2*)(ob + (size_t)(r0+8)*DHD + cc) = __floats2half2_rn(acc[j][2], acc[j][3]);
    }
}

// ============================================================
// K2: fused scores — shear-on-write + triangular skipping +
// FULL struct prefetch + paired barrier-free bilinear passes.
// smem: Q|Kb|Ka|E0|E1 (16K ea) + bufQ/bufK (128x136 fp16 ea) = 151552
// ============================================================
#define SC_SMEM 151552

__global__ __launch_bounds__(512, 1) void scores_kernel(
    const float* __restrict__ mask,
    const float* __restrict__ structm,
    const float* __restrict__ dist,
    const float* __restrict__ abv)
{
    extern __shared__ __align__(16) char smraw[];
    __half2* Q   = (__half2*)smraw;
    __half2* Kb  = (__half2*)(smraw + 16384);
    __half2* Ka  = (__half2*)(smraw + 32768);
    __half2* E0  = (__half2*)(smraw + 49152);
    __half2* E1  = (__half2*)(smraw + 65536);
    __half* bufQ = (__half*)(smraw + 81920);    // [128][136]
    __half* bufK = (__half*)(smraw + 116736);   // [128][136]

    const int bh = blockIdx.x, kt = blockIdx.y, qt = blockIdx.z;
    const int b = bh / HH, h = bh % HH;
    const int m0 = qt*128, n0 = kt*128;
    const int tid = threadIdx.x, lane = tid & 31, wid = tid >> 5;
    const int wm = wid & 3, wn = wid >> 2;
    const int r0 = wm*32 + (lane >> 2);
    const int c0 = wn*32 + (lane & 3)*2;

    const int base = (qt - kt)*128 + 896;
    int nv1 = 1919 - base; if (nv1 > 128) nv1 = 128;

    const __half* qwbase = g_qw + ((size_t)bh*LL + m0)*DHD;
    const size_t qwstr = (size_t)BHN*LL*DHD;

    uint4 vq[2], vk[2], vH[2], vG[2];
    float4 vA[4], vB[4];
    ldgH<2,512>(vq, g_q + (size_t)(bh*LL + m0)*DHD, DHD, tid);
    ldgH<2,512>(vk, g_k + (size_t)(bh*LL + n0)*DHD, DHD, tid);
    stsAhH<2,512>(Q, vq, tid);
    stsAhH<2,512>(Ka, vk, tid);
    stsBhH<2,512,16>(Kb, vk, tid);
    ldgT4<4,512>(vA, dist + (size_t)base*DHD, DHD, tid, 128);
    stsBh<4,512>(E0, vA, tid);
    ldgT4<4,512>(vB, dist + (size_t)(base + 128)*DHD, DHD, tid, nv1);
    stsBh<4,512>(E1, vB, tid);
    ldgH<2,512>(vH, qwbase, DHD, tid);          // qw0 prefetch
    __syncthreads();

    float acc[2][4][4];
    float bacc[2][4][4];
    zero32(acc);

    // shear-write: QE element (R, Jcol) contributes at C = R - (Jcol+128h) + 127
    auto shearQE = [&](int h128) {
        #pragma unroll
        for (int i = 0; i < 2; i++)
            #pragma unroll
            for (int j = 0; j < 4; j++)
                #pragma unroll
                for (int c2 = 0; c2 < 4; c2++) {
                    int R    = r0 + i*16 + (c2 >> 1)*8;
                    int Jcol = c0 + j*8 + (c2 & 1);
                    int C = R - Jcol + 127 - h128;
                    if ((unsigned)C < 128u)
                        bufQ[R*136 + C] = __float2half(bacc[i][j][c2]);
                }
    };
    // shear-write: KE element (rowK, Jcol) contributes at R = rowK + Jcol + 128h - 127
    auto shearKE = [&](int h128) {
        #pragma unroll
        for (int i = 0; i < 2; i++)
            #pragma unroll
            for (int j = 0; j < 4; j++)
                #pragma unroll
                for (int c2 = 0; c2 < 4; c2++) {
                    int rowK = r0 + i*16 + (c2 >> 1)*8;
                    int Jcol = c0 + j*8 + (c2 & 1);
                    int R = rowK + Jcol + h128 - 127;
                    if ((unsigned)R < 128u)
                        bufK[R*136 + rowK] = __float2half(bacc[i][j][c2]);
                }
    };

    // ---- positional phase: triangular warp-tile skipping ----
    if (wm + wn >= 3) { zero32(bacc); gemm32h(Ka, E0, wm, wn, lane, bacc); shearKE(0);   }
    if (wm + wn <= 3) { zero32(bacc); gemm32h(Ka, E1, wm, wn, lane, bacc); shearKE(128); }
    if (wn >= wm)     { zero32(bacc); gemm32h(Q,  E0, wm, wn, lane, bacc); shearQE(0);   }
    if (wn <= wm)     { zero32(bacc); gemm32h(Q,  E1, wm, wn, lane, bacc); shearQE(128); }
    __syncthreads();   // sync0

    // ---- stage qw0 -> E0, then prefetch qw1 ----
    stsAhH<2,512>(E0, vH, tid);                 // qw0 -> E0
    ldgH<2,512>(vH, qwbase + qwstr, DHD, tid);  // qw1

    // ---- coalesced read-add of both positional terms ----
    #pragma unroll
    for (int i = 0; i < 2; i++)
        #pragma unroll
        for (int hh = 0; hh < 2; hh++) {
            int rr = r0 + i*16 + hh*8;
            #pragma unroll
            for (int j = 0; j < 4; j++) {
                int cc = c0 + j*8;
                __half2 a = *(const __half2*)(bufQ + rr*136 + cc);
                __half2 bvl = *(const __half2*)(bufK + rr*136 + cc);
                float2 af = __half22float2(a);
                float2 bf = __half22float2(bvl);
                acc[i][j][hh*2+0] += af.x + bf.x;
                acc[i][j][hh*2+1] += af.y + bf.y;
            }
        }

    // ---- QK pass: gemm(Q,Kb); scale + mask ----
    float2 mk[4];
    {
        const float* mrow = mask + b*LL + n0;
        #pragma unroll
        for (int j = 0; j < 4; j++) mk[j] = *(const float2*)(mrow + c0 + j*8);
    }
    zero32(bacc); gemm32h(Q, Kb, wm, wn, lane, bacc);
    #pragma unroll
    for (int j = 0; j < 4; j++)
        #pragma unroll
        for (int i = 0; i < 2; i++) {
            acc[i][j][0] = (acc[i][j][0] + bacc[i][j][0])*0.125f + mk[j].x;
            acc[i][j][1] = (acc[i][j][1] + bacc[i][j][1])*0.125f + mk[j].y;
            acc[i][j][2] = (acc[i][j][2] + bacc[i][j][2])*0.125f + mk[j].x;
            acc[i][j][3] = (acc[i][j][3] + bacc[i][j][3])*0.125f + mk[j].y;
        }

    // stage qw1 -> E1 (E1 free after positional); prefetch qw2, qw3
    stsAhH<2,512>(E1, vH, tid);
    ldgH<2,512>(vH, qwbase + 2*qwstr, DHD, tid);  // qw2
    ldgH<2,512>(vG, qwbase + 3*qwstr, DHD, tid);  // qw3
    __syncthreads();   // sync1: E0(qw0), E1(qw1) visible

    // stage qw2 -> Q (Q free after QK gemm), qw3 -> Ka (free after positional)
    stsAhH<2,512>(Q, vH, tid);
    stsAhH<2,512>(Ka, vG, tid);
    ldgH<2,512>(vH, qwbase + 4*qwstr, DHD, tid);  // qw4

    // ---- bilinear passes: full struct prefetch, paired barrier-free ----
    float2 sv[16];
    float  ab;
    auto structPre = [&](int i5) {
        ab = __ldg(&abv[i5*HH + h]);
        const float* stb = structm + (((size_t)(i5*BB + b)*LL + m0)*LL) + n0;
        #pragma unroll
        for (int p = 0; p < 4; p++)
            #pragma unroll
            for (int j = 0; j < 4; j++)
                sv[p*4+j] = *(const float2*)(stb + (size_t)(r0 + p*8)*LL + c0 + j*8);
    };
    auto structEpi = [&]() {
        #pragma unroll
        for (int i = 0; i < 2; i++)
            #pragma unroll
            for (int hh = 0; hh < 2; hh++) {
                int p = i*2 + hh;
                #pragma unroll
                for (int j = 0; j < 4; j++) {
                    acc[i][j][hh*2+0] += (bacc[i][j][hh*2+0] + ab)*sv[p*4+j].x;
                    acc[i][j][hh*2+1] += (bacc[i][j][hh*2+1] + ab)*sv[p*4+j].y;
                }
            }
    };

    // B1 (E0=qw0), B2 (E1=qw1): barrier-free pair
    structPre(0);
    zero32(bacc); gemm32h(E0, Kb, wm, wn, lane, bacc);
    structEpi();
    structPre(1);
    zero32(bacc); gemm32h(E1, Kb, wm, wn, lane, bacc);
    structEpi();
    __syncthreads();   // sync2: Q(qw2), Ka(qw3) visible; E0 free of B1 readers

    // stage qw4 -> E0
    stsAhH<2,512>(E0, vH, tid);

    // B3 (Q=qw2), B4 (Ka=qw3): barrier-free pair
    structPre(2);
    zero32(bacc); gemm32h(Q, Kb, wm, wn, lane, bacc);
    structEpi();
    structPre(3);
    zero32(bacc); gemm32h(Ka, Kb, wm, wn, lane, bacc);
    structEpi();
    __syncthreads();   // sync3: E0(qw4) visible

    // B5 (E0=qw4)
    structPre(4);
    zero32(bacc); gemm32h(E0, Kb, wm, wn, lane, bacc);
    structEpi();

    // store scores
    float* sp = g_s + ((size_t)bh*LL + m0)*LL + n0;
    #pragma unroll
    for (int i = 0; i < 2; i++)
        #pragma unroll
        for (int j = 0; j < 4; j++) {
            int rr = r0 + i*16, cc = c0 + j*8;
            *(float2*)(sp + (size_t)rr*LL + cc)     = make_float2(acc[i][j][0], acc[i][j][1]);
            *(float2*)(sp + (size_t)(rr+8)*LL + cc) = make_float2(acc[i][j][2], acc[i][j][3]);
        }

    // ---- per-wn partial row stats: registers + quad shuffles only ----
    float rm[4], rs[4];
    #pragma unroll
    for (int ridx = 0; ridx < 4; ridx++) {
        int i = ridx >> 1, hh = ridx & 1;
        float m = acc[i][0][hh*2+0];
        #pragma unroll
        for (int j = 0; j < 4; j++) {
            m = fmaxf(m, acc[i][j][hh*2+0]);
            m = fmaxf(m, acc[i][j][hh*2+1]);
        }
        rm[ridx] = m;
    }
    #pragma unroll
    for (int o = 1; o <= 2; o <<= 1)
        #pragma unroll
        for (int r = 0; r < 4; r++)
            rm[r] = fmaxf(rm[r], __shfl_xor_sync(0xffffffffu, rm[r], o));
    #pragma unroll
    for (int ridx = 0; ridx < 4; ridx++) {
        int i = ridx >> 1, hh = ridx & 1;
        float s = 0.f;
        #pragma unroll
        for (int j = 0; j < 4; j++) {
            s += __expf(acc[i][j][hh*2+0] - rm[ridx]);
            s += __expf(acc[i][j][hh*2+1] - rm[ridx]);
        }
        rs[ridx] = s;
    }
    #pragma unroll
    for (int o = 1; o <= 2; o <<= 1)
        #pragma unroll
        for (int r = 0; r < 4; r++)
            rs[r] += __shfl_xor_sync(0xffffffffu, rs[r], o);
    if ((lane & 3) == 0) {
        #pragma unroll
        for (int r = 0; r < 4; r++) {
            int row = r0 + (r >> 1)*16 + (r & 1)*8;
            int gi = ((((bh*8 + kt)*4) + wn) << 10) + m0 + row;
            g_pm[gi] = rm[r];
            g_ps[gi] = rs[r];
        }
    }
}

// ============================================================
// K4: ctx = softmax(scores) @ v — 64-row tiles, double-buffered
// grid (16, 24), 256 thr. smem: 2x(A 8K + B 8K) + stats 512B
// ============================================================
#define PV_SMEM 33536

__global__ __launch_bounds__(256) void pv_kernel(float* __restrict__ out)
{
    extern __shared__ __align__(16) char smraw[];
    __half2* Abuf[2] = { (__half2*)smraw,           (__half2*)(smraw + 16384) };
    __half2* Bbuf[2] = { (__half2*)(smraw + 8192),  (__half2*)(smraw + 24576) };
    float* sm_m   = (float*)(smraw + 32768);
    float* sm_inv = (float*)(smraw + 33024);

    const int bh = blockIdx.y;
    const int b = bh / HH, h = bh % HH;
    const int m0 = blockIdx.x * 64;
    const int tid = threadIdx.x, lane = tid & 31, wid = tid >> 5;
    const int wm = wid & 3, wn = wid >> 2;

    if (tid < 64) {
        float m = -1e30f;
        #pragma unroll
        for (int p = 0; p < 32; p++) {
            int gi = (((bh*8 + (p >> 2))*4 + (p & 3)) << 10) + m0 + tid;
            m = fmaxf(m, g_pm[gi]);
        }
        float s = 0.f;
        #pragma unroll
        for (int p = 0; p < 32; p++) {
            int gi = (((bh*8 + (p >> 2))*4 + (p & 3)) << 10) + m0 + tid;
            s += g_ps[gi]*__expf(g_pm[gi] - m);
        }
        sm_m[tid]   = m;
        sm_inv[tid] = 1.f / s;
    }
    __syncthreads();

    const float* pb = g_s + (size_t)bh*LL*LL + (size_t)m0*LL;
    const __half* vb = g_v + (size_t)bh*LL*DHD;

    float acc[4][4];
    #pragma unroll
    for (int j = 0; j < 4; j++)
        #pragma unroll
        for (int c = 0; c < 4; c++) acc[j][c] = 0.f;

    float4 rA[4];
    uint4 rU, rW;

    auto ldExpA = [&](int kc0) {
        ldgT4<4,256>(rA, pb + kc0, LL, tid, 64);
        #pragma unroll
        for (int it = 0; it < 4; it++) {
            int m = (tid + it*256) >> 4;
            float mm = sm_m[m];
            rA[it].x = __expf(rA[it].x - mm);
            rA[it].y = __expf(rA[it].y - mm);
            rA[it].z = __expf(rA[it].z - mm);
            rA[it].w = __expf(rA[it].w - mm);
        }
    };

    // prologue: chunk 0 staged, chunk 1 in regs
    ldExpA(0);
    ldgV(rU, rW, vb, tid);
    stsAh<4,256,4>(Abuf[0], rA, tid);
    stsV(Bbuf[0], rU, rW, tid);
    ldExpA(64);
    ldgV(rU, rW, vb + (size_t)64*DHD, tid);
    __syncthreads();

    for (int c = 0; c < 16; c++) {
        int cur = c & 1;
        if (c < 15) {
            stsAh<4,256,4>(Abuf[1-cur], rA, tid);
            stsV(Bbuf[1-cur], rU, rW, tid);
        }
        if (c < 14) {
            ldExpA((c+2)*64);
            ldgV(rU, rW, vb + (size_t)(c+2)*64*DHD, tid);
        }
        gemm6464h(Abuf[cur], Bbuf[cur], wm, wn, lane, acc);
        __syncthreads();
    }

    const int r0 = wm*16 + (lane >> 2);
    const int c0 = wn*32 + (lane & 3)*2;
    const float inv0 = sm_inv[r0];
    const float inv1 = sm_inv[r0 + 8];
    #pragma unroll
    for (int j = 0; j < 4; j++) {
        int cc = c0 + j*8;
        int l0 = m0 + r0;
        *(float2*)&out[((size_t)b*LL + l0)*DD + h*DHD + cc] =
            make_float2(acc[j][0]*inv0, acc[j][1]*inv0);
        *(float2*)&out[((size_t)b*LL + l0 + 8)*DD + h*DHD + cc] =
            make_float2(acc[j][2]*inv1, acc[j][3]*inv1);
    }
}

// ============================================================
extern "C" void kernel_launch(void* const* d_in, const int* in_sizes, int n_in,
                              void* d_out, int out_size)
{
    const float* hidden  = (const float*)d_in[0];
    const float* mask    = (const float*)d_in[1];
    const float* structm = (const float*)d_in[2];
    const float* Wq      = (const float*)d_in[3];
    const float* bq      = (const float*)d_in[4];
    const float* Wk      = (const float*)d_in[5];
    const float* bk      = (const float*)d_in[6];
    const float* Wv      = (const float*)d_in[7];
    const float* bv      = (const float*)d_in[8];
    const float* dist    = (const float*)d_in[9];
    const float* ssw     = (const float*)d_in[10];
    const float* abv     = (const float*)d_in[11];
    float* out = (float*)d_out;

    cudaFuncSetAttribute(qkv_kernel,    cudaFuncAttributeMaxDynamicSharedMemorySize, 32768);
    cudaFuncSetAttribute(qw_kernel,     cudaFuncAttributeMaxDynamicSharedMemorySize, 24576);
    cudaFuncSetAttribute(pv_kernel,     cudaFuncAttributeMaxDynamicSharedMemorySize, PV_SMEM);
    cudaFuncSetAttribute(scores_kernel, cudaFuncAttributeMaxDynamicSharedMemorySize, SC_SMEM);

    qkv_kernel    <<<dim3(6,16,3),  256, 32768>>>(hidden, Wq,bq, Wk,bk, Wv,bv);
    qw_kernel     <<<dim3(8,24,5),  256, 24576>>>(ssw);
    scores_kernel <<<dim3(24,8,8),  512, SC_SMEM>>>(mask, structm, dist, abv);
    pv_kernel     <<<dim3(16,24),   256, PV_SMEM>>>(out);
}